// round 1
// baseline (speedup 1.0000x reference)
#include <cuda_runtime.h>
#include <math.h>
#include <stddef.h>

// ---------------- problem constants ----------------
#define BB   32
#define LL   512
#define DM   384
#define DI   768
#define DS   64
#define NH   16
#define HD   48
#define DIP  1680          // 2*DI + 2*DS + NH
#define CD   896           // DI + 2*DS
#define NT   (BB*LL)       // 16384 rows
#define NOUT 38667
#define N_ORDER 60
#define N_FAMILY 427
#define N_GENUS 14216
#define N_SPECIES 23964

// ---------------- scratch (static device arrays; no allocation) ----------------
__device__ float g_resid[(size_t)NT*DM];
__device__ float g_h    [(size_t)NT*DM];
__device__ float g_zx   [(size_t)NT*DIP];
__device__ float g_xBC  [(size_t)NT*CD];
__device__ float g_dt   [(size_t)NT*NH];
__device__ float g_dA   [(size_t)NT*NH];
__device__ float g_ys   [(size_t)NT*DI];
__device__ float g_yn   [(size_t)NT*DI];
__device__ float g_feat [(size_t)BB*DM];

// ---------------- embedding gather ----------------
__global__ void embed_kernel(const int* __restrict__ tokens, const float* __restrict__ emb)
{
    int i = blockIdx.x * blockDim.x + threadIdx.x;
    if (i >= NT*DM) return;
    int bt = i / DM;
    int d  = i % DM;
    g_resid[i] = emb[(size_t)tokens[bt]*DM + d];
}

// ---------------- layernorm: g_resid -> g_h (dim 384) ----------------
__global__ __launch_bounds__(128) void ln_kernel(const float* __restrict__ w, const float* __restrict__ b)
{
    __shared__ float red[128];
    int row = blockIdx.x, tid = threadIdx.x;
    const float* xr = g_resid + (size_t)row*DM;
    float v0 = xr[tid], v1 = xr[tid+128], v2 = xr[tid+256];
    red[tid] = v0+v1+v2; __syncthreads();
    for (int s=64;s>0;s>>=1){ if(tid<s) red[tid]+=red[tid+s]; __syncthreads(); }
    float mu = red[0] * (1.0f/DM);
    __syncthreads();
    float d0=v0-mu, d1=v1-mu, d2=v2-mu;
    red[tid] = d0*d0+d1*d1+d2*d2; __syncthreads();
    for (int s=64;s>0;s>>=1){ if(tid<s) red[tid]+=red[tid+s]; __syncthreads(); }
    float inv = rsqrtf(red[0]*(1.0f/DM) + 1e-5f);
    float* o = g_h + (size_t)row*DM;
    o[tid]     = d0*inv*w[tid]     + b[tid];
    o[tid+128] = d1*inv*w[tid+128] + b[tid+128];
    o[tid+256] = d2*inv*w[tid+256] + b[tid+256];
}

// ---------------- tiled fp32 GEMM ----------------
// mode 0: g_zx = g_h @ W          (M=NT, N=DIP, K=DM)
// mode 1: g_resid += g_yn @ W     (M=NT, N=DM,  K=DI)
#define BM 64
#define BN 64
#define BK 16
__global__ __launch_bounds__(256) void sgemm_kernel(const float* __restrict__ Wt, int mode,
                                                    int M, int N, int K)
{
    const float* __restrict__ A = (mode==0) ? g_h : g_yn;
    float* C = (mode==0) ? g_zx : g_resid;

    __shared__ __align__(16) float As[BK][BM];
    __shared__ __align__(16) float Bs[BK][BN];

    int tid = threadIdx.x;
    int tx = tid & 15, ty = tid >> 4;
    int m0 = blockIdx.y * BM;
    int n0 = blockIdx.x * BN;
    int arow = tid >> 2;
    int acol = (tid & 3) << 2;
    int brow = tid >> 4;
    int bcol = (tid & 15) << 2;

    float acc[4][4];
    #pragma unroll
    for (int i=0;i<4;i++)
        #pragma unroll
        for (int j=0;j<4;j++) acc[i][j]=0.f;

    for (int k0 = 0; k0 < K; k0 += BK) {
        float4 av = *(const float4*)(A + (size_t)(m0+arow)*K + k0 + acol);
        As[acol+0][arow]=av.x; As[acol+1][arow]=av.y;
        As[acol+2][arow]=av.z; As[acol+3][arow]=av.w;
        float4 bv = make_float4(0.f,0.f,0.f,0.f);
        if (n0 + bcol < N) bv = *(const float4*)(Wt + (size_t)(k0+brow)*N + n0 + bcol);
        *(float4*)&Bs[brow][bcol] = bv;
        __syncthreads();
        #pragma unroll
        for (int kk=0; kk<BK; kk++){
            float4 a  = *(const float4*)&As[kk][ty<<2];
            float4 bb = *(const float4*)&Bs[kk][tx<<2];
            acc[0][0]=fmaf(a.x,bb.x,acc[0][0]); acc[0][1]=fmaf(a.x,bb.y,acc[0][1]);
            acc[0][2]=fmaf(a.x,bb.z,acc[0][2]); acc[0][3]=fmaf(a.x,bb.w,acc[0][3]);
            acc[1][0]=fmaf(a.y,bb.x,acc[1][0]); acc[1][1]=fmaf(a.y,bb.y,acc[1][1]);
            acc[1][2]=fmaf(a.y,bb.z,acc[1][2]); acc[1][3]=fmaf(a.y,bb.w,acc[1][3]);
            acc[2][0]=fmaf(a.z,bb.x,acc[2][0]); acc[2][1]=fmaf(a.z,bb.y,acc[2][1]);
            acc[2][2]=fmaf(a.z,bb.z,acc[2][2]); acc[2][3]=fmaf(a.z,bb.w,acc[2][3]);
            acc[3][0]=fmaf(a.w,bb.x,acc[3][0]); acc[3][1]=fmaf(a.w,bb.y,acc[3][1]);
            acc[3][2]=fmaf(a.w,bb.z,acc[3][2]); acc[3][3]=fmaf(a.w,bb.w,acc[3][3]);
        }
        __syncthreads();
    }
    #pragma unroll
    for (int i=0;i<4;i++){
        int row = m0 + (ty<<2) + i;
        #pragma unroll
        for (int j=0;j<4;j++){
            int col = n0 + (tx<<2) + j;
            if (col < N){
                size_t idx = (size_t)row*N + col;
                float r = acc[i][j];
                if (mode) r += C[idx];
                C[idx] = r;
            }
        }
    }
}

// ---------------- causal depthwise conv (k=4) + silu on xBC channels ----------------
__global__ void conv_kernel(const float* __restrict__ cw, const float* __restrict__ cb)
{
    int i = blockIdx.x * blockDim.x + threadIdx.x;
    if (i >= NT*CD) return;
    int c  = i % CD;
    int bt = i / CD;
    int t  = bt % LL;
    const float* base = g_zx + (size_t)bt*DIP + DI + c;   // tap offset 0 == time t
    float acc = cb[c];
    #pragma unroll
    for (int k=0;k<4;k++){
        int off = k - 3;
        if (t + off >= 0) acc = fmaf(base[(ptrdiff_t)off*DIP], cw[c*4+k], acc);
    }
    g_xBC[i] = acc / (1.f + expf(-acc));
}

// ---------------- dt = softplus(raw+bias); dA = exp(-exp(A_log)*dt) ----------------
__global__ void dtda_kernel(const float* __restrict__ dtb, const float* __restrict__ alog)
{
    int i = blockIdx.x * blockDim.x + threadIdx.x;
    if (i >= NT*NH) return;
    int hh = i % NH;
    int bt = i / NH;
    float raw = g_zx[(size_t)bt*DIP + (DIP-NH) + hh] + dtb[hh];
    float sp = (raw > 20.f) ? raw : log1pf(expf(raw));
    g_dt[i] = sp;
    g_dA[i] = expf(-expf(alog[hh]) * sp);
}

// ---------------- selective scan: one CTA per (b,h); thread owns p, state[n] in regs ----------------
__global__ __launch_bounds__(64) void scan_kernel()
{
    int bh = blockIdx.x;
    int b  = bh >> 4;
    int h  = bh & 15;
    int tid = threadIdx.x;
    __shared__ __align__(16) float Bs[DS];
    __shared__ __align__(16) float Cs[DS];
    float s[DS];
    #pragma unroll
    for (int n=0;n<DS;n++) s[n]=0.f;

    for (int t=0;t<LL;t++){
        int bt = b*LL + t;
        const float* row = g_xBC + (size_t)bt*CD;
        Bs[tid] = row[DI + tid];
        Cs[tid] = row[DI + DS + tid];
        float dAv = g_dA[bt*NH + h];
        float dtx = g_dt[bt*NH + h] * ((tid < HD) ? row[h*HD + tid] : 0.f);
        __syncthreads();
        float y = 0.f;
        const float4* B4 = (const float4*)Bs;
        const float4* C4 = (const float4*)Cs;
        #pragma unroll
        for (int q=0;q<16;q++){
            float4 bv = B4[q], cv = C4[q];
            s[4*q+0]=fmaf(s[4*q+0],dAv,dtx*bv.x); y=fmaf(s[4*q+0],cv.x,y);
            s[4*q+1]=fmaf(s[4*q+1],dAv,dtx*bv.y); y=fmaf(s[4*q+1],cv.y,y);
            s[4*q+2]=fmaf(s[4*q+2],dAv,dtx*bv.z); y=fmaf(s[4*q+2],cv.z,y);
            s[4*q+3]=fmaf(s[4*q+3],dAv,dtx*bv.w); y=fmaf(s[4*q+3],cv.w,y);
        }
        if (tid < HD) g_ys[(size_t)bt*DI + h*HD + tid] = y;
        __syncthreads();
    }
}

// ---------------- y = (ys + D*x) * silu(z); RMS-norm with gnorm_w -> g_yn ----------------
__global__ __launch_bounds__(256) void gate_rms_kernel(const float* __restrict__ Dp,
                                                       const float* __restrict__ gnorm)
{
    __shared__ float red[256];
    int row = blockIdx.x, tid = threadIdx.x;
    float v[3]; float ss = 0.f;
    #pragma unroll
    for (int q=0;q<3;q++){
        int i = tid + q*256;
        float ys = g_ys[(size_t)row*DI + i];
        float xv = g_xBC[(size_t)row*CD + i];
        float z  = g_zx [(size_t)row*DIP + i];
        float val = (ys + Dp[i/HD]*xv) * (z / (1.f + expf(-z)));
        v[q] = val; ss += val*val;
    }
    red[tid] = ss; __syncthreads();
    for (int s=128;s>0;s>>=1){ if(tid<s) red[tid]+=red[tid+s]; __syncthreads(); }
    float scale = rsqrtf(red[0]*(1.0f/DI) + 1e-5f);
    #pragma unroll
    for (int q=0;q<3;q++){
        int i = tid + q*256;
        g_yn[(size_t)row*DI + i] = v[q]*scale*gnorm[i];
    }
}

// ---------------- mean over t + layernorm -> g_feat ----------------
__global__ __launch_bounds__(128) void pool_ln_kernel(const float* __restrict__ w,
                                                      const float* __restrict__ b)
{
    __shared__ float red[128];
    int bb = blockIdx.x, tid = threadIdx.x;
    float v[3];
    #pragma unroll
    for (int q=0;q<3;q++){
        int d = tid + q*128;
        const float* p = g_h + (size_t)bb*LL*DM + d;
        float s = 0.f;
        for (int t=0;t<LL;t++) s += p[(size_t)t*DM];
        v[q] = s * (1.0f/LL);
    }
    red[tid] = v[0]+v[1]+v[2]; __syncthreads();
    for (int s=64;s>0;s>>=1){ if(tid<s) red[tid]+=red[tid+s]; __syncthreads(); }
    float mu = red[0]*(1.0f/DM);
    __syncthreads();
    float d0=v[0]-mu, d1=v[1]-mu, d2=v[2]-mu;
    red[tid] = d0*d0+d1*d1+d2*d2; __syncthreads();
    for (int s=64;s>0;s>>=1){ if(tid<s) red[tid]+=red[tid+s]; __syncthreads(); }
    float inv = rsqrtf(red[0]*(1.0f/DM) + 1e-5f);
    g_feat[bb*DM+tid]     = d0*inv*w[tid]     + b[tid];
    g_feat[bb*DM+tid+128] = d1*inv*w[tid+128] + b[tid+128];
    g_feat[bb*DM+tid+256] = d2*inv*w[tid+256] + b[tid+256];
}

// ---------------- classification heads: out[32, 38667] ----------------
__global__ __launch_bounds__(256) void heads_kernel(
    const float* __restrict__ ow, const float* __restrict__ ob,
    const float* __restrict__ fw, const float* __restrict__ fb,
    const float* __restrict__ gw, const float* __restrict__ gb,
    const float* __restrict__ sw, const float* __restrict__ sb,
    float* __restrict__ out)
{
    __shared__ float sf[BB*DM];   // 48 KB
    int tid = threadIdx.x;
    for (int i = tid; i < BB*DM; i += blockDim.x) sf[i] = g_feat[i];
    __syncthreads();

    int j = blockIdx.x * blockDim.x + tid;
    if (j >= NOUT) return;

    const float* W; const float* Bv; int jj, Nseg;
    if (j < N_ORDER)                      { W=ow; Bv=ob; jj=j;                     Nseg=N_ORDER; }
    else if (j < N_ORDER+N_FAMILY)        { W=fw; Bv=fb; jj=j-N_ORDER;             Nseg=N_FAMILY; }
    else if (j < N_ORDER+N_FAMILY+N_GENUS){ W=gw; Bv=gb; jj=j-N_ORDER-N_FAMILY;    Nseg=N_GENUS; }
    else                                  { W=sw; Bv=sb; jj=j-N_ORDER-N_FAMILY-N_GENUS; Nseg=N_SPECIES; }

    float acc[BB];
    #pragma unroll
    for (int b=0;b<BB;b++) acc[b]=0.f;
    for (int k=0;k<DM;k++){
        float wv = W[(size_t)k*Nseg + jj];
        #pragma unroll
        for (int b=0;b<BB;b++) acc[b] = fmaf(sf[b*DM + k], wv, acc[b]);
    }
    float bias = Bv[jj];
    #pragma unroll
    for (int b=0;b<BB;b++) out[(size_t)b*NOUT + j] = acc[b] + bias;
}

// ---------------- orchestration ----------------
extern "C" void kernel_launch(void* const* d_in, const int* in_sizes, int n_in,
                              void* d_out, int out_size)
{
    const int*   tokens = (const int*)  d_in[0];
    const float* emb    = (const float*)d_in[1];
    const float* ln_w   = (const float*)d_in[2];
    const float* ln_b   = (const float*)d_in[3];
    const float* Win    = (const float*)d_in[4];
    const float* cw     = (const float*)d_in[5];
    const float* cb     = (const float*)d_in[6];
    const float* dtb    = (const float*)d_in[7];
    const float* alog   = (const float*)d_in[8];
    const float* Dd     = (const float*)d_in[9];
    const float* gnw    = (const float*)d_in[10];
    const float* Wout   = (const float*)d_in[11];
    const float* nfw    = (const float*)d_in[12];
    const float* nfb    = (const float*)d_in[13];
    const float* plw    = (const float*)d_in[14];
    const float* plb    = (const float*)d_in[15];
    const float* ow     = (const float*)d_in[16];
    const float* ob     = (const float*)d_in[17];
    const float* fw     = (const float*)d_in[18];
    const float* fb     = (const float*)d_in[19];
    const float* gw     = (const float*)d_in[20];
    const float* gb     = (const float*)d_in[21];
    const float* sw     = (const float*)d_in[22];
    const float* sb     = (const float*)d_in[23];
    float* out = (float*)d_out;

    embed_kernel<<<(NT*DM + 255)/256, 256>>>(tokens, emb);

    for (int l = 0; l < 2; l++) {
        ln_kernel<<<NT, 128>>>(ln_w + l*DM, ln_b + l*DM);
        sgemm_kernel<<<dim3((DIP+BN-1)/BN, NT/BM), 256>>>(Win + (size_t)l*DM*DIP, 0, NT, DIP, DM);
        conv_kernel<<<(NT*CD + 255)/256, 256>>>(cw + (size_t)l*CD*4, cb + l*CD);
        dtda_kernel<<<(NT*NH + 255)/256, 256>>>(dtb + l*NH, alog + l*NH);
        scan_kernel<<<BB*NH, 64>>>();
        gate_rms_kernel<<<NT, 256>>>(Dd + l*NH, gnw + l*DI);
        sgemm_kernel<<<dim3((DM+BN-1)/BN, NT/BM), 256>>>(Wout + (size_t)l*DI*DM, 1, NT, DM, DI);
    }

    ln_kernel<<<NT, 128>>>(nfw, nfb);
    pool_ln_kernel<<<BB, 128>>>(plw, plb);
    heads_kernel<<<(NOUT + 255)/256, 256>>>(ow, ob, fw, fb, gw, gb, sw, sb, out);
}

// round 2
// speedup vs baseline: 2.1788x; 2.1788x over previous
#include <cuda_runtime.h>
#include <math.h>
#include <stddef.h>
#include <stdint.h>

// ---------------- problem constants ----------------
#define BB   32
#define LL   512
#define DM   384
#define DI   768
#define DS   64
#define NH   16
#define HD   48
#define DIP  1680          // 2*DI + 2*DS + NH
#define CD   896           // DI + 2*DS
#define NT   (BB*LL)       // 16384 rows
#define NOUT 38667
#define N_ORDER 60
#define N_FAMILY 427
#define N_GENUS 14216
#define N_SPECIES 23964

// ---------------- scratch (static device arrays; no allocation) ----------------
__device__ float g_resid[(size_t)NT*DM];
__device__ float g_h    [(size_t)NT*DM];
__device__ float g_zx   [(size_t)NT*DIP];
__device__ float g_xBC  [(size_t)NT*CD];
__device__ float g_dt   [(size_t)NT*NH];
__device__ float g_dA   [(size_t)NT*NH];
__device__ float g_ys   [(size_t)NT*DI];
__device__ float g_yn   [(size_t)NT*DI];
__device__ float g_feat [(size_t)BB*DM];

// ---------------- embedding gather ----------------
__global__ void embed_kernel(const int* __restrict__ tokens, const float* __restrict__ emb)
{
    int i = blockIdx.x * blockDim.x + threadIdx.x;
    if (i >= NT*DM) return;
    int bt = i / DM;
    int d  = i % DM;
    g_resid[i] = emb[(size_t)tokens[bt]*DM + d];
}

// ---------------- layernorm: g_resid -> g_h (dim 384) ----------------
__global__ __launch_bounds__(128) void ln_kernel(const float* __restrict__ w, const float* __restrict__ b)
{
    __shared__ float red[128];
    int row = blockIdx.x, tid = threadIdx.x;
    const float* xr = g_resid + (size_t)row*DM;
    float v0 = xr[tid], v1 = xr[tid+128], v2 = xr[tid+256];
    red[tid] = v0+v1+v2; __syncthreads();
    for (int s=64;s>0;s>>=1){ if(tid<s) red[tid]+=red[tid+s]; __syncthreads(); }
    float mu = red[0] * (1.0f/DM);
    __syncthreads();
    float d0=v0-mu, d1=v1-mu, d2=v2-mu;
    red[tid] = d0*d0+d1*d1+d2*d2; __syncthreads();
    for (int s=64;s>0;s>>=1){ if(tid<s) red[tid]+=red[tid+s]; __syncthreads(); }
    float inv = rsqrtf(red[0]*(1.0f/DM) + 1e-5f);
    float* o = g_h + (size_t)row*DM;
    o[tid]     = d0*inv*w[tid]     + b[tid];
    o[tid+128] = d1*inv*w[tid+128] + b[tid+128];
    o[tid+256] = d2*inv*w[tid+256] + b[tid+256];
}

// ---------------- tf32 tensor-core GEMM ----------------
// mode 0: g_zx = g_h @ W          (M=NT, N=DIP, K=DM)
// mode 1: g_resid += g_yn @ W     (M=NT, N=DM,  K=DI)
#define GBM 128
#define GBN 128
#define GBK 16
#define GPAD 4

__device__ __forceinline__ uint32_t f2tf(float x){
    uint32_t y;
    asm volatile("cvt.rna.tf32.f32 %0, %1;" : "=r"(y) : "f"(x));
    return y;
}

__device__ __forceinline__ void mma_tf32(float* c, const uint32_t* a, const uint32_t* b){
    asm volatile(
      "mma.sync.aligned.m16n8k8.row.col.f32.tf32.tf32.f32 "
      "{%0,%1,%2,%3}, {%4,%5,%6,%7}, {%8,%9}, {%0,%1,%2,%3};\n"
      : "+f"(c[0]), "+f"(c[1]), "+f"(c[2]), "+f"(c[3])
      : "r"(a[0]), "r"(a[1]), "r"(a[2]), "r"(a[3]), "r"(b[0]), "r"(b[1]));
}

__global__ __launch_bounds__(256) void mma_gemm_kernel(const float* __restrict__ Wt, int mode,
                                                       int M, int N, int K)
{
    const float* __restrict__ A = (mode==0) ? g_h : g_yn;
    float* C = (mode==0) ? g_zx : g_resid;

    __shared__ __align__(16) float As[2][GBK][GBM+GPAD];
    __shared__ __align__(16) float Bs[2][GBK][GBN+GPAD];

    int tid  = threadIdx.x;
    int warp = tid >> 5;
    int lane = tid & 31;
    int gid  = lane >> 2;     // 0..7
    int tig  = lane & 3;      // 0..3

    int m0 = blockIdx.y * GBM;
    int n0 = blockIdx.x * GBN;
    int wm = (warp & 1) * 64; // warp m offset within tile
    int wn = (warp >> 1) * 32;// warp n offset within tile

    // global-load mapping
    int ar  = tid >> 1;           // A row within tile (0..127)
    int akc = (tid & 1) << 3;     // A k offset (0 or 8)
    int bkr = tid >> 4;           // B k row (0..15)
    int bnc = (tid & 15) << 3;    // B n offset (0..120)

    const float* Ap = A + (size_t)(m0 + ar)*K + akc;
    const float* Bp = Wt + (size_t)bkr*N + n0 + bnc;

    float acc[4][4][4];
    #pragma unroll
    for (int i=0;i<4;i++)
        #pragma unroll
        for (int j=0;j<4;j++)
            #pragma unroll
            for (int q=0;q<4;q++) acc[i][j][q]=0.f;

    float ra[8], rb[8];
    int niter = K / GBK;

    // load tile 0 -> regs
    {
        float4 a0 = *(const float4*)(Ap);
        float4 a1 = *(const float4*)(Ap + 4);
        ra[0]=a0.x;ra[1]=a0.y;ra[2]=a0.z;ra[3]=a0.w;
        ra[4]=a1.x;ra[5]=a1.y;ra[6]=a1.z;ra[7]=a1.w;
        float4 b0 = make_float4(0,0,0,0), b1 = make_float4(0,0,0,0);
        if (n0 + bnc + 3 < N) b0 = *(const float4*)(Bp);
        if (n0 + bnc + 7 < N) b1 = *(const float4*)(Bp + 4);
        rb[0]=b0.x;rb[1]=b0.y;rb[2]=b0.z;rb[3]=b0.w;
        rb[4]=b1.x;rb[5]=b1.y;rb[6]=b1.z;rb[7]=b1.w;
    }
    // sts tile 0 -> buf 0
    #pragma unroll
    for (int j=0;j<8;j++) As[0][akc+j][ar] = __uint_as_float(f2tf(ra[j]));
    #pragma unroll
    for (int j=0;j<8;j++) Bs[0][bkr][bnc+j] = __uint_as_float(f2tf(rb[j]));
    // load tile 1 -> regs
    if (niter > 1){
        const float* Ap1 = Ap + GBK;
        const float* Bp1 = Bp + (size_t)GBK*N;
        float4 a0 = *(const float4*)(Ap1);
        float4 a1 = *(const float4*)(Ap1 + 4);
        ra[0]=a0.x;ra[1]=a0.y;ra[2]=a0.z;ra[3]=a0.w;
        ra[4]=a1.x;ra[5]=a1.y;ra[6]=a1.z;ra[7]=a1.w;
        float4 b0 = make_float4(0,0,0,0), b1 = make_float4(0,0,0,0);
        if (n0 + bnc + 3 < N) b0 = *(const float4*)(Bp1);
        if (n0 + bnc + 7 < N) b1 = *(const float4*)(Bp1 + 4);
        rb[0]=b0.x;rb[1]=b0.y;rb[2]=b0.z;rb[3]=b0.w;
        rb[4]=b1.x;rb[5]=b1.y;rb[6]=b1.z;rb[7]=b1.w;
    }
    __syncthreads();

    for (int it=0; it<niter; ++it){
        // store tile it+1 (already in regs) into the other buffer
        if (it+1 < niter){
            int nb = (it+1)&1;
            #pragma unroll
            for (int j=0;j<8;j++) As[nb][akc+j][ar] = __uint_as_float(f2tf(ra[j]));
            #pragma unroll
            for (int j=0;j<8;j++) Bs[nb][bkr][bnc+j] = __uint_as_float(f2tf(rb[j]));
        }
        // prefetch tile it+2 -> regs
        if (it+2 < niter){
            const float* Ap2 = Ap + (size_t)(it+2)*GBK;
            const float* Bp2 = Bp + (size_t)(it+2)*GBK*N;
            float4 a0 = *(const float4*)(Ap2);
            float4 a1 = *(const float4*)(Ap2 + 4);
            ra[0]=a0.x;ra[1]=a0.y;ra[2]=a0.z;ra[3]=a0.w;
            ra[4]=a1.x;ra[5]=a1.y;ra[6]=a1.z;ra[7]=a1.w;
            float4 b0 = make_float4(0,0,0,0), b1 = make_float4(0,0,0,0);
            if (n0 + bnc + 3 < N) b0 = *(const float4*)(Bp2);
            if (n0 + bnc + 7 < N) b1 = *(const float4*)(Bp2 + 4);
            rb[0]=b0.x;rb[1]=b0.y;rb[2]=b0.z;rb[3]=b0.w;
            rb[4]=b1.x;rb[5]=b1.y;rb[6]=b1.z;rb[7]=b1.w;
        }
        // compute on buffer it&1
        int cb = it & 1;
        #pragma unroll
        for (int ks=0; ks<GBK; ks+=8){
            uint32_t af[4][4], bf[4][2];
            #pragma unroll
            for (int mi=0; mi<4; mi++){
                int mr = wm + 16*mi;
                af[mi][0] = __float_as_uint(As[cb][ks+tig  ][mr+gid  ]);
                af[mi][1] = __float_as_uint(As[cb][ks+tig  ][mr+gid+8]);
                af[mi][2] = __float_as_uint(As[cb][ks+tig+4][mr+gid  ]);
                af[mi][3] = __float_as_uint(As[cb][ks+tig+4][mr+gid+8]);
            }
            #pragma unroll
            for (int ni=0; ni<4; ni++){
                int nb2 = wn + 8*ni;
                bf[ni][0] = __float_as_uint(Bs[cb][ks+tig  ][nb2+gid]);
                bf[ni][1] = __float_as_uint(Bs[cb][ks+tig+4][nb2+gid]);
            }
            #pragma unroll
            for (int mi=0; mi<4; mi++)
                #pragma unroll
                for (int ni=0; ni<4; ni++)
                    mma_tf32(acc[mi][ni], af[mi], bf[ni]);
        }
        __syncthreads();
    }

    // epilogue
    #pragma unroll
    for (int mi=0; mi<4; mi++){
        int r0 = m0 + wm + 16*mi + gid;
        #pragma unroll
        for (int ni=0; ni<4; ni++){
            int c0 = n0 + wn + 8*ni + 2*tig;
            float* a = acc[mi][ni];
            if (c0 < N){
                size_t i0 = (size_t)r0*N + c0;
                size_t i2 = (size_t)(r0+8)*N + c0;
                if (mode){ C[i0] += a[0]; C[i2] += a[2]; }
                else     { C[i0]  = a[0]; C[i2]  = a[2]; }
            }
            if (c0+1 < N){
                size_t i1 = (size_t)r0*N + c0+1;
                size_t i3 = (size_t)(r0+8)*N + c0+1;
                if (mode){ C[i1] += a[1]; C[i3] += a[3]; }
                else     { C[i1]  = a[1]; C[i3]  = a[3]; }
            }
        }
    }
}

// ---------------- causal depthwise conv (k=4) + silu on xBC channels ----------------
__global__ void conv_kernel(const float* __restrict__ cw, const float* __restrict__ cb)
{
    int i = blockIdx.x * blockDim.x + threadIdx.x;
    if (i >= NT*CD) return;
    int c  = i % CD;
    int bt = i / CD;
    int t  = bt % LL;
    const float* base = g_zx + (size_t)bt*DIP + DI + c;   // tap offset 0 == time t
    float acc = cb[c];
    #pragma unroll
    for (int k=0;k<4;k++){
        int off = k - 3;
        if (t + off >= 0) acc = fmaf(base[(ptrdiff_t)off*DIP], cw[c*4+k], acc);
    }
    g_xBC[i] = acc / (1.f + __expf(-acc));
}

// ---------------- dt = softplus(raw+bias); dA = exp(-exp(A_log)*dt) ----------------
__global__ void dtda_kernel(const float* __restrict__ dtb, const float* __restrict__ alog)
{
    int i = blockIdx.x * blockDim.x + threadIdx.x;
    if (i >= NT*NH) return;
    int hh = i % NH;
    int bt = i / NH;
    float raw = g_zx[(size_t)bt*DIP + (DIP-NH) + hh] + dtb[hh];
    float sp = (raw > 20.f) ? raw : log1pf(expf(raw));
    g_dt[i] = sp;
    g_dA[i] = expf(-expf(alog[hh]) * sp);
}

// ---------------- selective scan: one CTA per (b,h); thread owns p, state[n] in regs ----------------
__global__ __launch_bounds__(64) void scan_kernel()
{
    int bh = blockIdx.x;
    int b  = bh >> 4;
    int h  = bh & 15;
    int tid = threadIdx.x;
    __shared__ __align__(16) float Bsh[2][DS];
    __shared__ __align__(16) float Csh[2][DS];
    float s[DS];
    #pragma unroll
    for (int n=0;n<DS;n++) s[n]=0.f;

    // prologue: load t=0
    {
        const float* row = g_xBC + (size_t)(b*LL)*CD;
        Bsh[0][tid] = row[DI + tid];
        Csh[0][tid] = row[DI + DS + tid];
    }
    float x_cur  = (tid < HD) ? g_xBC[(size_t)(b*LL)*CD + h*HD + tid] : 0.f;
    float dt_cur = g_dt[(b*LL)*NH + h];
    float dA_cur = g_dA[(b*LL)*NH + h];
    __syncthreads();

    for (int t=0; t<LL; t++){
        int cur = t & 1;
        float Bn=0.f, Cn=0.f, xn=0.f, dtn=0.f, dAn=0.f;
        if (t+1 < LL){
            int bt1 = b*LL + t + 1;
            const float* row1 = g_xBC + (size_t)bt1*CD;
            Bn  = row1[DI + tid];
            Cn  = row1[DI + DS + tid];
            xn  = (tid < HD) ? row1[h*HD + tid] : 0.f;
            dtn = g_dt[bt1*NH + h];
            dAn = g_dA[bt1*NH + h];
        }
        float dtx = dt_cur * x_cur;
        float dAv = dA_cur;
        float y0=0.f, y1=0.f, y2=0.f, y3=0.f;
        const float4* B4 = (const float4*)Bsh[cur];
        const float4* C4 = (const float4*)Csh[cur];
        #pragma unroll
        for (int q=0;q<16;q++){
            float4 bv = B4[q], cv = C4[q];
            s[4*q+0]=fmaf(s[4*q+0],dAv,dtx*bv.x); y0=fmaf(s[4*q+0],cv.x,y0);
            s[4*q+1]=fmaf(s[4*q+1],dAv,dtx*bv.y); y1=fmaf(s[4*q+1],cv.y,y1);
            s[4*q+2]=fmaf(s[4*q+2],dAv,dtx*bv.z); y2=fmaf(s[4*q+2],cv.z,y2);
            s[4*q+3]=fmaf(s[4*q+3],dAv,dtx*bv.w); y3=fmaf(s[4*q+3],cv.w,y3);
        }
        if (tid < HD) g_ys[(size_t)(b*LL+t)*DI + h*HD + tid] = (y0+y1)+(y2+y3);
        if (t+1 < LL){
            Bsh[cur^1][tid] = Bn;
            Csh[cur^1][tid] = Cn;
        }
        x_cur = xn; dt_cur = dtn; dA_cur = dAn;
        __syncthreads();
    }
}

// ---------------- y = (ys + D*x) * silu(z); RMS-norm with gnorm_w -> g_yn ----------------
__global__ __launch_bounds__(256) void gate_rms_kernel(const float* __restrict__ Dp,
                                                       const float* __restrict__ gnorm)
{
    __shared__ float red[256];
    int row = blockIdx.x, tid = threadIdx.x;
    float v[3]; float ss = 0.f;
    #pragma unroll
    for (int q=0;q<3;q++){
        int i = tid + q*256;
        float ys = g_ys[(size_t)row*DI + i];
        float xv = g_xBC[(size_t)row*CD + i];
        float z  = g_zx [(size_t)row*DIP + i];
        float val = (ys + Dp[i/HD]*xv) * (z / (1.f + __expf(-z)));
        v[q] = val; ss += val*val;
    }
    red[tid] = ss; __syncthreads();
    for (int s=128;s>0;s>>=1){ if(tid<s) red[tid]+=red[tid+s]; __syncthreads(); }
    float scale = rsqrtf(red[0]*(1.0f/DI) + 1e-5f);
    #pragma unroll
    for (int q=0;q<3;q++){
        int i = tid + q*256;
        g_yn[(size_t)row*DI + i] = v[q]*scale*gnorm[i];
    }
}

// ---------------- mean over t + layernorm -> g_feat ----------------
__global__ __launch_bounds__(128) void pool_ln_kernel(const float* __restrict__ w,
                                                      const float* __restrict__ b)
{
    __shared__ float red[128];
    int bb = blockIdx.x, tid = threadIdx.x;
    float v[3];
    #pragma unroll
    for (int q=0;q<3;q++){
        int d = tid + q*128;
        const float* p = g_h + (size_t)bb*LL*DM + d;
        float s = 0.f;
        for (int t=0;t<LL;t++) s += p[(size_t)t*DM];
        v[q] = s * (1.0f/LL);
    }
    red[tid] = v[0]+v[1]+v[2]; __syncthreads();
    for (int s=64;s>0;s>>=1){ if(tid<s) red[tid]+=red[tid+s]; __syncthreads(); }
    float mu = red[0]*(1.0f/DM);
    __syncthreads();
    float d0=v[0]-mu, d1=v[1]-mu, d2=v[2]-mu;
    red[tid] = d0*d0+d1*d1+d2*d2; __syncthreads();
    for (int s=64;s>0;s>>=1){ if(tid<s) red[tid]+=red[tid+s]; __syncthreads(); }
    float inv = rsqrtf(red[0]*(1.0f/DM) + 1e-5f);
    g_feat[bb*DM+tid]     = d0*inv*w[tid]     + b[tid];
    g_feat[bb*DM+tid+128] = d1*inv*w[tid+128] + b[tid+128];
    g_feat[bb*DM+tid+256] = d2*inv*w[tid+256] + b[tid+256];
}

// ---------------- classification heads: out[32, 38667] ----------------
__global__ __launch_bounds__(256) void heads_kernel(
    const float* __restrict__ ow, const float* __restrict__ ob,
    const float* __restrict__ fw, const float* __restrict__ fb,
    const float* __restrict__ gw, const float* __restrict__ gb,
    const float* __restrict__ sw, const float* __restrict__ sb,
    float* __restrict__ out)
{
    __shared__ float sf[BB*DM];   // 48 KB
    int tid = threadIdx.x;
    for (int i = tid; i < BB*DM; i += blockDim.x) sf[i] = g_feat[i];
    __syncthreads();

    int j = blockIdx.x * blockDim.x + tid;
    if (j >= NOUT) return;

    const float* W; const float* Bv; int jj, Nseg;
    if (j < N_ORDER)                      { W=ow; Bv=ob; jj=j;                     Nseg=N_ORDER; }
    else if (j < N_ORDER+N_FAMILY)        { W=fw; Bv=fb; jj=j-N_ORDER;             Nseg=N_FAMILY; }
    else if (j < N_ORDER+N_FAMILY+N_GENUS){ W=gw; Bv=gb; jj=j-N_ORDER-N_FAMILY;    Nseg=N_GENUS; }
    else                                  { W=sw; Bv=sb; jj=j-N_ORDER-N_FAMILY-N_GENUS; Nseg=N_SPECIES; }

    float acc[BB];
    #pragma unroll
    for (int b=0;b<BB;b++) acc[b]=0.f;
    for (int k=0;k<DM;k++){
        float wv = W[(size_t)k*Nseg + jj];
        #pragma unroll
        for (int b=0;b<BB;b++) acc[b] = fmaf(sf[b*DM + k], wv, acc[b]);
    }
    float bias = Bv[jj];
    #pragma unroll
    for (int b=0;b<BB;b++) out[(size_t)b*NOUT + j] = acc[b] + bias;
}

// ---------------- orchestration ----------------
extern "C" void kernel_launch(void* const* d_in, const int* in_sizes, int n_in,
                              void* d_out, int out_size)
{
    const int*   tokens = (const int*)  d_in[0];
    const float* emb    = (const float*)d_in[1];
    const float* ln_w   = (const float*)d_in[2];
    const float* ln_b   = (const float*)d_in[3];
    const float* Win    = (const float*)d_in[4];
    const float* cw     = (const float*)d_in[5];
    const float* cb     = (const float*)d_in[6];
    const float* dtb    = (const float*)d_in[7];
    const float* alog   = (const float*)d_in[8];
    const float* Dd     = (const float*)d_in[9];
    const float* gnw    = (const float*)d_in[10];
    const float* Wout   = (const float*)d_in[11];
    const float* nfw    = (const float*)d_in[12];
    const float* nfb    = (const float*)d_in[13];
    const float* plw    = (const float*)d_in[14];
    const float* plb    = (const float*)d_in[15];
    const float* ow     = (const float*)d_in[16];
    const float* ob     = (const float*)d_in[17];
    const float* fw     = (const float*)d_in[18];
    const float* fb     = (const float*)d_in[19];
    const float* gw     = (const float*)d_in[20];
    const float* gb     = (const float*)d_in[21];
    const float* sw     = (const float*)d_in[22];
    const float* sb     = (const float*)d_in[23];
    float* out = (float*)d_out;

    embed_kernel<<<(NT*DM + 255)/256, 256>>>(tokens, emb);

    for (int l = 0; l < 2; l++) {
        ln_kernel<<<NT, 128>>>(ln_w + l*DM, ln_b + l*DM);
        mma_gemm_kernel<<<dim3((DIP+GBN-1)/GBN, NT/GBM), 256>>>(Win + (size_t)l*DM*DIP, 0, NT, DIP, DM);
        conv_kernel<<<(NT*CD + 255)/256, 256>>>(cw + (size_t)l*CD*4, cb + l*CD);
        dtda_kernel<<<(NT*NH + 255)/256, 256>>>(dtb + l*NH, alog + l*NH);
        scan_kernel<<<BB*NH, 64>>>();
        gate_rms_kernel<<<NT, 256>>>(Dd + l*NH, gnw + l*DI);
        mma_gemm_kernel<<<dim3((DM+GBN-1)/GBN, NT/GBM), 256>>>(Wout + (size_t)l*DI*DM, 1, NT, DM, DI);
    }

    ln_kernel<<<NT, 128>>>(nfw, nfb);
    pool_ln_kernel<<<BB, 128>>>(plw, plb);
    heads_kernel<<<(NOUT + 255)/256, 256>>>(ow, ob, fw, fb, gw, gb, sw, sb, out);
}

// round 3
// speedup vs baseline: 2.5175x; 1.1555x over previous
#include <cuda_runtime.h>
#include <math.h>
#include <stddef.h>
#include <stdint.h>

// ---------------- problem constants ----------------
#define BB   32
#define LL   512
#define DM   384
#define DI   768
#define DS   64
#define NH   16
#define HD   48
#define DIP  1680          // 2*DI + 2*DS + NH
#define CD   896           // DI + 2*DS
#define NT   (BB*LL)       // 16384 rows
#define NOUT 38667
#define N_ORDER 60
#define N_FAMILY 427
#define N_GENUS 14216
#define N_SPECIES 23964

#define WIN1  (DM*DIP)     // 645120 per layer
#define WOUT1 (DI*DM)      // 294912 per layer

// ---------------- scratch (static device arrays; no allocation) ----------------
__device__ float g_resid[(size_t)NT*DM];
__device__ float g_h    [(size_t)NT*DM];     // tf32-rounded for layers; fp32 for final
__device__ float g_zx   [(size_t)NT*DIP];
__device__ float g_xBC  [(size_t)NT*CD];
__device__ float g_dt   [(size_t)NT*NH];
__device__ float g_dA   [(size_t)NT*NH];
__device__ float g_ys   [(size_t)NT*DI];
__device__ float g_yn   [(size_t)NT*DI];     // tf32-rounded
__device__ float g_feat [(size_t)BB*DM];
__device__ float g_wtf  [2*WIN1 + 2*WOUT1];  // tf32-rounded weights

__device__ __forceinline__ uint32_t f2tf(float x){
    uint32_t y;
    asm volatile("cvt.rna.tf32.f32 %0, %1;" : "=r"(y) : "f"(x));
    return y;
}

// ---------------- embedding gather ----------------
__global__ void embed_kernel(const int* __restrict__ tokens, const float* __restrict__ emb)
{
    int i = blockIdx.x * blockDim.x + threadIdx.x;
    if (i >= NT*DM) return;
    int bt = i / DM;
    int d  = i % DM;
    g_resid[i] = emb[(size_t)tokens[bt]*DM + d];
}

// ---------------- weight tf32 pre-convert ----------------
__global__ void wcvt_kernel(const float* __restrict__ Win, const float* __restrict__ Wout)
{
    int i = blockIdx.x * blockDim.x + threadIdx.x;
    int total = 2*WIN1 + 2*WOUT1;
    if (i >= total) return;
    float v = (i < 2*WIN1) ? Win[i] : Wout[i - 2*WIN1];
    g_wtf[i] = __uint_as_float(f2tf(v));
}

// ---------------- layernorm: g_resid -> g_h (dim 384); tf==1 rounds output to tf32 ----------------
__global__ __launch_bounds__(128) void ln_kernel(const float* __restrict__ w, const float* __restrict__ b, int tf)
{
    __shared__ float red[128];
    int row = blockIdx.x, tid = threadIdx.x;
    const float* xr = g_resid + (size_t)row*DM;
    float v0 = xr[tid], v1 = xr[tid+128], v2 = xr[tid+256];
    red[tid] = v0+v1+v2; __syncthreads();
    for (int s=64;s>0;s>>=1){ if(tid<s) red[tid]+=red[tid+s]; __syncthreads(); }
    float mu = red[0] * (1.0f/DM);
    __syncthreads();
    float d0=v0-mu, d1=v1-mu, d2=v2-mu;
    red[tid] = d0*d0+d1*d1+d2*d2; __syncthreads();
    for (int s=64;s>0;s>>=1){ if(tid<s) red[tid]+=red[tid+s]; __syncthreads(); }
    float inv = rsqrtf(red[0]*(1.0f/DM) + 1e-5f);
    float o0 = d0*inv*w[tid]     + b[tid];
    float o1 = d1*inv*w[tid+128] + b[tid+128];
    float o2 = d2*inv*w[tid+256] + b[tid+256];
    if (tf){
        o0 = __uint_as_float(f2tf(o0));
        o1 = __uint_as_float(f2tf(o1));
        o2 = __uint_as_float(f2tf(o2));
    }
    float* o = g_h + (size_t)row*DM;
    o[tid] = o0; o[tid+128] = o1; o[tid+256] = o2;
}

// ---------------- tf32 tensor-core GEMM, cp.async 4-stage pipeline ----------------
// MODE 0: g_zx = g_h @ Wtf          (M=NT, N=DIP, K=DM)
// MODE 1: g_resid += g_yn @ Wtf     (M=NT, N=DM,  K=DI)
#define GBM 128
#define GBN 128
#define GBK 16
#define NSTAGE 4
#define AS_STRIDE 20                    // BK + 4 pad (floats)
#define BS_STRIDE 132                   // BN + 4 pad (floats)
#define AS_FLOATS (GBM*AS_STRIDE)       // 2560
#define BS_FLOATS (GBK*BS_STRIDE)       // 2112
#define SMEM_FLOATS (NSTAGE*(AS_FLOATS+BS_FLOATS))   // 18688 -> 74752 B

__device__ __forceinline__ void mma_tf32(float* c, const uint32_t* a, const uint32_t* b){
    asm volatile(
      "mma.sync.aligned.m16n8k8.row.col.f32.tf32.tf32.f32 "
      "{%0,%1,%2,%3}, {%4,%5,%6,%7}, {%8,%9}, {%0,%1,%2,%3};\n"
      : "+f"(c[0]), "+f"(c[1]), "+f"(c[2]), "+f"(c[3])
      : "r"(a[0]), "r"(a[1]), "r"(a[2]), "r"(a[3]), "r"(b[0]), "r"(b[1]));
}

template<int MODE>
__global__ __launch_bounds__(256,2) void gemm_tc(int layer)
{
    const float* __restrict__ A = (MODE==0) ? g_h : g_yn;
    const float* __restrict__ W = (MODE==0) ? (g_wtf + (size_t)layer*WIN1)
                                            : (g_wtf + 2*WIN1 + (size_t)layer*WOUT1);
    float* C = (MODE==0) ? g_zx : g_resid;
    const int N = (MODE==0) ? DIP : DM;
    const int K = (MODE==0) ? DM  : DI;

    extern __shared__ float sh[];   // [NSTAGE A tiles][NSTAGE B tiles]
    float* shB = sh + NSTAGE*AS_FLOATS;

    int tid  = threadIdx.x;
    int warp = tid >> 5;
    int lane = tid & 31;
    int gid  = lane >> 2;
    int tig  = lane & 3;

    int m0 = blockIdx.y * GBM;
    int n0 = blockIdx.x * GBN;
    int wm = (warp & 1) * 64;
    int wn = (warp >> 1) * 32;

    float acc[4][4][4];
    #pragma unroll
    for (int i=0;i<4;i++)
        #pragma unroll
        for (int j=0;j<4;j++)
            #pragma unroll
            for (int q=0;q<4;q++) acc[i][j][q]=0.f;

    const int niter = K / GBK;

    // per-thread copy mapping (2 A chunks + 2 B chunks of 16B each)
    int a_row0 = (tid      ) >> 2, a_kc0 = ((tid      ) & 3) << 2;
    int a_row1 = (tid + 256) >> 2, a_kc1 = ((tid + 256) & 3) << 2;
    int b_row0 = (tid      ) >> 5, b_nc0 = ((tid      ) & 31) << 2;
    int b_row1 = (tid + 256) >> 5, b_nc1 = ((tid + 256) & 31) << 2;
    int b_ok0 = (n0 + b_nc0 < N) ? 16 : 0;
    int b_ok1 = (n0 + b_nc1 < N) ? 16 : 0;
    const float* bsrc0_base = W + (size_t)b_row0*N + ((n0 + b_nc0 < N) ? (n0 + b_nc0) : 0);
    const float* bsrc1_base = W + (size_t)b_row1*N + ((n0 + b_nc1 < N) ? (n0 + b_nc1) : 0);
    const float* asrc0_base = A + (size_t)(m0 + a_row0)*K + a_kc0;
    const float* asrc1_base = A + (size_t)(m0 + a_row1)*K + a_kc1;

    uint32_t adst0 = (uint32_t)__cvta_generic_to_shared(&sh [a_row0*AS_STRIDE + a_kc0]);
    uint32_t adst1 = (uint32_t)__cvta_generic_to_shared(&sh [a_row1*AS_STRIDE + a_kc1]);
    uint32_t bdst0 = (uint32_t)__cvta_generic_to_shared(&shB[b_row0*BS_STRIDE + b_nc0]);
    uint32_t bdst1 = (uint32_t)__cvta_generic_to_shared(&shB[b_row1*BS_STRIDE + b_nc1]);

    auto issue_copy = [&](int st, int it){
        int k0 = it * GBK;
        uint32_t ao = st*AS_FLOATS*4, bo = st*BS_FLOATS*4;
        asm volatile("cp.async.cg.shared.global [%0], [%1], 16;\n"
                     :: "r"(adst0 + ao), "l"(asrc0_base + k0));
        asm volatile("cp.async.cg.shared.global [%0], [%1], 16;\n"
                     :: "r"(adst1 + ao), "l"(asrc1_base + k0));
        asm volatile("cp.async.cg.shared.global [%0], [%1], 16, %2;\n"
                     :: "r"(bdst0 + bo), "l"(bsrc0_base + (size_t)k0*N), "r"(b_ok0));
        asm volatile("cp.async.cg.shared.global [%0], [%1], 16, %2;\n"
                     :: "r"(bdst1 + bo), "l"(bsrc1_base + (size_t)k0*N), "r"(b_ok1));
    };

    // prologue: stages 0..2
    #pragma unroll
    for (int st=0; st<NSTAGE-1; st++){
        if (st < niter) issue_copy(st, st);
        asm volatile("cp.async.commit_group;\n");
    }

    for (int it=0; it<niter; ++it){
        asm volatile("cp.async.wait_group %0;\n" :: "n"(NSTAGE-2));
        __syncthreads();

        int cb = it & (NSTAGE-1);
        const float* Asb = &sh [cb*AS_FLOATS];
        const float* Bsb = &shB[cb*BS_FLOATS];

        #pragma unroll
        for (int ks=0; ks<GBK; ks+=8){
            uint32_t af[4][4], bf[4][2];
            #pragma unroll
            for (int mi=0; mi<4; mi++){
                int mr = wm + 16*mi;
                af[mi][0] = __float_as_uint(Asb[(mr+gid  )*AS_STRIDE + ks+tig  ]);
                af[mi][1] = __float_as_uint(Asb[(mr+gid+8)*AS_STRIDE + ks+tig  ]);
                af[mi][2] = __float_as_uint(Asb[(mr+gid  )*AS_STRIDE + ks+tig+4]);
                af[mi][3] = __float_as_uint(Asb[(mr+gid+8)*AS_STRIDE + ks+tig+4]);
            }
            #pragma unroll
            for (int ni=0; ni<4; ni++){
                int nb = wn + 8*ni;
                bf[ni][0] = __float_as_uint(Bsb[(ks+tig  )*BS_STRIDE + nb+gid]);
                bf[ni][1] = __float_as_uint(Bsb[(ks+tig+4)*BS_STRIDE + nb+gid]);
            }
            #pragma unroll
            for (int mi=0; mi<4; mi++)
                #pragma unroll
                for (int ni=0; ni<4; ni++)
                    mma_tf32(acc[mi][ni], af[mi], bf[ni]);
        }

        int nx = it + NSTAGE - 1;
        if (nx < niter) issue_copy(nx & (NSTAGE-1), nx);
        asm volatile("cp.async.commit_group;\n");
    }

    // epilogue
    #pragma unroll
    for (int mi=0; mi<4; mi++){
        int r0 = m0 + wm + 16*mi + gid;
        #pragma unroll
        for (int ni=0; ni<4; ni++){
            int c0 = n0 + wn + 8*ni + 2*tig;
            float* a = acc[mi][ni];
            if (c0 < N){
                size_t i0 = (size_t)r0*N + c0;
                size_t i2 = (size_t)(r0+8)*N + c0;
                if (MODE){ C[i0] += a[0]; C[i2] += a[2]; }
                else     { C[i0]  = a[0]; C[i2]  = a[2]; }
            }
            if (c0+1 < N){
                size_t i1 = (size_t)r0*N + c0+1;
                size_t i3 = (size_t)(r0+8)*N + c0+1;
                if (MODE){ C[i1] += a[1]; C[i3] += a[3]; }
                else     { C[i1]  = a[1]; C[i3]  = a[3]; }
            }
        }
    }
}

// ---------------- causal depthwise conv (k=4) + silu on xBC channels ----------------
__global__ void conv_kernel(const float* __restrict__ cw, const float* __restrict__ cb)
{
    int i = blockIdx.x * blockDim.x + threadIdx.x;
    if (i >= NT*CD) return;
    int c  = i % CD;
    int bt = i / CD;
    int t  = bt % LL;
    const float* base = g_zx + (size_t)bt*DIP + DI + c;   // tap offset 0 == time t
    float acc = cb[c];
    #pragma unroll
    for (int k=0;k<4;k++){
        int off = k - 3;
        if (t + off >= 0) acc = fmaf(base[(ptrdiff_t)off*DIP], cw[c*4+k], acc);
    }
    g_xBC[i] = acc / (1.f + __expf(-acc));
}

// ---------------- dt = softplus(raw+bias); dA = exp(-exp(A_log)*dt) ----------------
__global__ void dtda_kernel(const float* __restrict__ dtb, const float* __restrict__ alog)
{
    int i = blockIdx.x * blockDim.x + threadIdx.x;
    if (i >= NT*NH) return;
    int hh = i % NH;
    int bt = i / NH;
    float raw = g_zx[(size_t)bt*DIP + (DIP-NH) + hh] + dtb[hh];
    float sp = (raw > 20.f) ? raw : log1pf(expf(raw));
    g_dt[i] = sp;
    g_dA[i] = expf(-expf(alog[hh]) * sp);
}

// ---------------- selective scan: one CTA per (b,h); thread owns p, state[n] in regs ----------------
__global__ __launch_bounds__(64) void scan_kernel()
{
    int bh = blockIdx.x;
    int b  = bh >> 4;
    int h  = bh & 15;
    int tid = threadIdx.x;
    __shared__ __align__(16) float Bsh[2][DS];
    __shared__ __align__(16) float Csh[2][DS];
    float s[DS];
    #pragma unroll
    for (int n=0;n<DS;n++) s[n]=0.f;

    {
        const float* row = g_xBC + (size_t)(b*LL)*CD;
        Bsh[0][tid] = row[DI + tid];
        Csh[0][tid] = row[DI + DS + tid];
    }
    float x_cur  = (tid < HD) ? g_xBC[(size_t)(b*LL)*CD + h*HD + tid] : 0.f;
    float dt_cur = g_dt[(b*LL)*NH + h];
    float dA_cur = g_dA[(b*LL)*NH + h];
    __syncthreads();

    for (int t=0; t<LL; t++){
        int cur = t & 1;
        float Bn=0.f, Cn=0.f, xn=0.f, dtn=0.f, dAn=0.f;
        if (t+1 < LL){
            int bt1 = b*LL + t + 1;
            const float* row1 = g_xBC + (size_t)bt1*CD;
            Bn  = row1[DI + tid];
            Cn  = row1[DI + DS + tid];
            xn  = (tid < HD) ? row1[h*HD + tid] : 0.f;
            dtn = g_dt[bt1*NH + h];
            dAn = g_dA[bt1*NH + h];
        }
        float dtx = dt_cur * x_cur;
        float dAv = dA_cur;
        float y0=0.f, y1=0.f, y2=0.f, y3=0.f;
        const float4* B4 = (const float4*)Bsh[cur];
        const float4* C4 = (const float4*)Csh[cur];
        #pragma unroll
        for (int q=0;q<16;q++){
            float4 bv = B4[q], cv = C4[q];
            s[4*q+0]=fmaf(s[4*q+0],dAv,dtx*bv.x); y0=fmaf(s[4*q+0],cv.x,y0);
            s[4*q+1]=fmaf(s[4*q+1],dAv,dtx*bv.y); y1=fmaf(s[4*q+1],cv.y,y1);
            s[4*q+2]=fmaf(s[4*q+2],dAv,dtx*bv.z); y2=fmaf(s[4*q+2],cv.z,y2);
            s[4*q+3]=fmaf(s[4*q+3],dAv,dtx*bv.w); y3=fmaf(s[4*q+3],cv.w,y3);
        }
        if (tid < HD) g_ys[(size_t)(b*LL+t)*DI + h*HD + tid] = (y0+y1)+(y2+y3);
        if (t+1 < LL){
            Bsh[cur^1][tid] = Bn;
            Csh[cur^1][tid] = Cn;
        }
        x_cur = xn; dt_cur = dtn; dA_cur = dAn;
        __syncthreads();
    }
}

// ---------------- y = (ys + D*x) * silu(z); RMS-norm with gnorm_w -> g_yn (tf32) ----------------
__global__ __launch_bounds__(256) void gate_rms_kernel(const float* __restrict__ Dp,
                                                       const float* __restrict__ gnorm)
{
    __shared__ float red[256];
    int row = blockIdx.x, tid = threadIdx.x;
    float v[3]; float ss = 0.f;
    #pragma unroll
    for (int q=0;q<3;q++){
        int i = tid + q*256;
        float ys = g_ys[(size_t)row*DI + i];
        float xv = g_xBC[(size_t)row*CD + i];
        float z  = g_zx [(size_t)row*DIP + i];
        float val = (ys + Dp[i/HD]*xv) * (z / (1.f + __expf(-z)));
        v[q] = val; ss += val*val;
    }
    red[tid] = ss; __syncthreads();
    for (int s=128;s>0;s>>=1){ if(tid<s) red[tid]+=red[tid+s]; __syncthreads(); }
    float scale = rsqrtf(red[0]*(1.0f/DI) + 1e-5f);
    #pragma unroll
    for (int q=0;q<3;q++){
        int i = tid + q*256;
        g_yn[(size_t)row*DI + i] = __uint_as_float(f2tf(v[q]*scale*gnorm[i]));
    }
}

// ---------------- mean over t + layernorm -> g_feat ----------------
__global__ __launch_bounds__(128) void pool_ln_kernel(const float* __restrict__ w,
                                                      const float* __restrict__ b)
{
    __shared__ float red[128];
    int bb = blockIdx.x, tid = threadIdx.x;
    float v[3];
    #pragma unroll
    for (int q=0;q<3;q++){
        int d = tid + q*128;
        const float* p = g_h + (size_t)bb*LL*DM + d;
        float s = 0.f;
        for (int t=0;t<LL;t++) s += p[(size_t)t*DM];
        v[q] = s * (1.0f/LL);
    }
    red[tid] = v[0]+v[1]+v[2]; __syncthreads();
    for (int s=64;s>0;s>>=1){ if(tid<s) red[tid]+=red[tid+s]; __syncthreads(); }
    float mu = red[0]*(1.0f/DM);
    __syncthreads();
    float d0=v[0]-mu, d1=v[1]-mu, d2=v[2]-mu;
    red[tid] = d0*d0+d1*d1+d2*d2; __syncthreads();
    for (int s=64;s>0;s>>=1){ if(tid<s) red[tid]+=red[tid+s]; __syncthreads(); }
    float inv = rsqrtf(red[0]*(1.0f/DM) + 1e-5f);
    g_feat[bb*DM+tid]     = d0*inv*w[tid]     + b[tid];
    g_feat[bb*DM+tid+128] = d1*inv*w[tid+128] + b[tid+128];
    g_feat[bb*DM+tid+256] = d2*inv*w[tid+256] + b[tid+256];
}

// ---------------- classification heads: out[32, 38667] ----------------
__global__ __launch_bounds__(256) void heads_kernel(
    const float* __restrict__ ow, const float* __restrict__ ob,
    const float* __restrict__ fw, const float* __restrict__ fb,
    const float* __restrict__ gw, const float* __restrict__ gb,
    const float* __restrict__ sw, const float* __restrict__ sb,
    float* __restrict__ out)
{
    __shared__ float sf[BB*DM];   // 48 KB
    int tid = threadIdx.x;
    for (int i = tid; i < BB*DM; i += blockDim.x) sf[i] = g_feat[i];
    __syncthreads();

    int j = blockIdx.x * blockDim.x + tid;
    if (j >= NOUT) return;

    const float* W; const float* Bv; int jj, Nseg;
    if (j < N_ORDER)                      { W=ow; Bv=ob; jj=j;                     Nseg=N_ORDER; }
    else if (j < N_ORDER+N_FAMILY)        { W=fw; Bv=fb; jj=j-N_ORDER;             Nseg=N_FAMILY; }
    else if (j < N_ORDER+N_FAMILY+N_GENUS){ W=gw; Bv=gb; jj=j-N_ORDER-N_FAMILY;    Nseg=N_GENUS; }
    else                                  { W=sw; Bv=sb; jj=j-N_ORDER-N_FAMILY-N_GENUS; Nseg=N_SPECIES; }

    float acc[BB];
    #pragma unroll
    for (int b=0;b<BB;b++) acc[b]=0.f;
    for (int k=0;k<DM;k++){
        float wv = W[(size_t)k*Nseg + jj];
        #pragma unroll
        for (int b=0;b<BB;b++) acc[b] = fmaf(sf[b*DM + k], wv, acc[b]);
    }
    float bias = Bv[jj];
    #pragma unroll
    for (int b=0;b<BB;b++) out[(size_t)b*NOUT + j] = acc[b] + bias;
}

// ---------------- orchestration ----------------
extern "C" void kernel_launch(void* const* d_in, const int* in_sizes, int n_in,
                              void* d_out, int out_size)
{
    const int*   tokens = (const int*)  d_in[0];
    const float* emb    = (const float*)d_in[1];
    const float* ln_w   = (const float*)d_in[2];
    const float* ln_b   = (const float*)d_in[3];
    const float* Win    = (const float*)d_in[4];
    const float* cw     = (const float*)d_in[5];
    const float* cb     = (const float*)d_in[6];
    const float* dtb    = (const float*)d_in[7];
    const float* alog   = (const float*)d_in[8];
    const float* Dd     = (const float*)d_in[9];
    const float* gnw    = (const float*)d_in[10];
    const float* Wout   = (const float*)d_in[11];
    const float* nfw    = (const float*)d_in[12];
    const float* nfb    = (const float*)d_in[13];
    const float* plw    = (const float*)d_in[14];
    const float* plb    = (const float*)d_in[15];
    const float* ow     = (const float*)d_in[16];
    const float* ob     = (const float*)d_in[17];
    const float* fw     = (const float*)d_in[18];
    const float* fb     = (const float*)d_in[19];
    const float* gw     = (const float*)d_in[20];
    const float* gb     = (const float*)d_in[21];
    const float* sw     = (const float*)d_in[22];
    const float* sb     = (const float*)d_in[23];
    float* out = (float*)d_out;

    const int smem_bytes = SMEM_FLOATS * 4;
    cudaFuncSetAttribute(gemm_tc<0>, cudaFuncAttributeMaxDynamicSharedMemorySize, smem_bytes);
    cudaFuncSetAttribute(gemm_tc<1>, cudaFuncAttributeMaxDynamicSharedMemorySize, smem_bytes);

    embed_kernel<<<(NT*DM + 255)/256, 256>>>(tokens, emb);
    wcvt_kernel<<<(2*WIN1 + 2*WOUT1 + 255)/256, 256>>>(Win, Wout);

    for (int l = 0; l < 2; l++) {
        ln_kernel<<<NT, 128>>>(ln_w + l*DM, ln_b + l*DM, 1);
        gemm_tc<0><<<dim3((DIP+GBN-1)/GBN, NT/GBM), 256, smem_bytes>>>(l);
        conv_kernel<<<(NT*CD + 255)/256, 256>>>(cw + (size_t)l*CD*4, cb + l*CD);
        dtda_kernel<<<(NT*NH + 255)/256, 256>>>(dtb + l*NH, alog + l*NH);
        scan_kernel<<<BB*NH, 64>>>();
        gate_rms_kernel<<<NT, 256>>>(Dd + l*NH, gnw + l*DI);
        gemm_tc<1><<<dim3((DM+GBN-1)/GBN, NT/GBM), 256, smem_bytes>>>(l);
    }

    ln_kernel<<<NT, 128>>>(nfw, nfb, 0);
    pool_ln_kernel<<<BB, 128>>>(plw, plb);
    heads_kernel<<<(NOUT + 255)/256, 256>>>(ow, ob, fw, fb, gw, gb, sw, sb, out);
}

// round 4
// speedup vs baseline: 2.7151x; 1.0785x over previous
#include <cuda_runtime.h>
#include <math.h>
#include <stddef.h>
#include <stdint.h>

typedef unsigned long long ull;

// ---------------- problem constants ----------------
#define BB   32
#define LL   512
#define DM   384
#define DI   768
#define DS   64
#define NH   16
#define HD   48
#define DIP  1680          // 2*DI + 2*DS + NH
#define CD   896           // DI + 2*DS
#define NT   (BB*LL)       // 16384 rows
#define NOUT 38667
#define N_ORDER 60
#define N_FAMILY 427
#define N_GENUS 14216
#define N_SPECIES 23964

#define WIN1  (DM*DIP)     // 645120 per layer
#define WOUT1 (DI*DM)      // 294912 per layer

// ---------------- scratch (static device arrays; no allocation) ----------------
__device__ float g_resid[(size_t)NT*DM];
__device__ float g_h    [(size_t)NT*DM];
__device__ float g_zx   [(size_t)NT*DIP];
__device__ float g_xBC  [(size_t)NT*CD];
__device__ float g_dt   [(size_t)NT*NH];
__device__ float g_dA   [(size_t)NT*NH];
__device__ float g_ys   [(size_t)NT*DI];
__device__ float g_yn   [(size_t)NT*DI];
__device__ float g_feat [(size_t)BB*DM];
__device__ float g_wtf  [2*WIN1 + 2*WOUT1];  // tf32-rounded weights

__device__ __forceinline__ uint32_t f2tf(float x){
    uint32_t y;
    asm volatile("cvt.rna.tf32.f32 %0, %1;" : "=r"(y) : "f"(x));
    return y;
}

// f32x2 packed math (sm_103a)
__device__ __forceinline__ ull pk2(float lo, float hi){
    ull r; asm("mov.b64 %0, {%1, %2};" : "=l"(r) : "f"(lo), "f"(hi)); return r;
}
__device__ __forceinline__ void upk2(float& lo, float& hi, ull v){
    asm("mov.b64 {%0, %1}, %2;" : "=f"(lo), "=f"(hi) : "l"(v));
}
#define MUL2(out,a,b)   asm("mul.rn.f32x2 %0,%1,%2;"    : "=l"(out) : "l"(a), "l"(b))
#define FMA2(out,a,b,c) asm("fma.rn.f32x2 %0,%1,%2,%3;" : "=l"(out) : "l"(a), "l"(b), "l"(c))

// ---------------- embedding gather ----------------
__global__ void embed_kernel(const int* __restrict__ tokens, const float* __restrict__ emb)
{
    int i = blockIdx.x * blockDim.x + threadIdx.x;
    if (i >= NT*DM) return;
    int bt = i / DM;
    int d  = i % DM;
    g_resid[i] = emb[(size_t)tokens[bt]*DM + d];
}

// ---------------- weight tf32 pre-convert ----------------
__global__ void wcvt_kernel(const float* __restrict__ Win, const float* __restrict__ Wout)
{
    int i = blockIdx.x * blockDim.x + threadIdx.x;
    int total = 2*WIN1 + 2*WOUT1;
    if (i >= total) return;
    float v = (i < 2*WIN1) ? Win[i] : Wout[i - 2*WIN1];
    g_wtf[i] = __uint_as_float(f2tf(v));
}

// ---------------- layernorm: g_resid -> g_h ----------------
__global__ __launch_bounds__(128) void ln_kernel(const float* __restrict__ w, const float* __restrict__ b, int tf)
{
    __shared__ float red[128];
    int row = blockIdx.x, tid = threadIdx.x;
    const float* xr = g_resid + (size_t)row*DM;
    float v0 = xr[tid], v1 = xr[tid+128], v2 = xr[tid+256];
    red[tid] = v0+v1+v2; __syncthreads();
    for (int s=64;s>0;s>>=1){ if(tid<s) red[tid]+=red[tid+s]; __syncthreads(); }
    float mu = red[0] * (1.0f/DM);
    __syncthreads();
    float d0=v0-mu, d1=v1-mu, d2=v2-mu;
    red[tid] = d0*d0+d1*d1+d2*d2; __syncthreads();
    for (int s=64;s>0;s>>=1){ if(tid<s) red[tid]+=red[tid+s]; __syncthreads(); }
    float inv = rsqrtf(red[0]*(1.0f/DM) + 1e-5f);
    float o0 = d0*inv*w[tid]     + b[tid];
    float o1 = d1*inv*w[tid+128] + b[tid+128];
    float o2 = d2*inv*w[tid+256] + b[tid+256];
    if (tf){
        o0 = __uint_as_float(f2tf(o0));
        o1 = __uint_as_float(f2tf(o1));
        o2 = __uint_as_float(f2tf(o2));
    }
    float* o = g_h + (size_t)row*DM;
    o[tid] = o0; o[tid+128] = o1; o[tid+256] = o2;
}

// ---------------- tf32 tensor-core GEMM, cp.async 4-stage pipeline ----------------
#define GBM 128
#define GBN 128
#define GBK 16
#define NSTAGE 4
#define AS_STRIDE 20
#define BS_STRIDE 132
#define AS_FLOATS (GBM*AS_STRIDE)
#define BS_FLOATS (GBK*BS_STRIDE)
#define SMEM_FLOATS (NSTAGE*(AS_FLOATS+BS_FLOATS))

__device__ __forceinline__ void mma_tf32(float* c, const uint32_t* a, const uint32_t* b){
    asm volatile(
      "mma.sync.aligned.m16n8k8.row.col.f32.tf32.tf32.f32 "
      "{%0,%1,%2,%3}, {%4,%5,%6,%7}, {%8,%9}, {%0,%1,%2,%3};\n"
      : "+f"(c[0]), "+f"(c[1]), "+f"(c[2]), "+f"(c[3])
      : "r"(a[0]), "r"(a[1]), "r"(a[2]), "r"(a[3]), "r"(b[0]), "r"(b[1]));
}

template<int MODE>
__global__ __launch_bounds__(256,2) void gemm_tc(int layer)
{
    const float* __restrict__ A = (MODE==0) ? g_h : g_yn;
    const float* __restrict__ W = (MODE==0) ? (g_wtf + (size_t)layer*WIN1)
                                            : (g_wtf + 2*WIN1 + (size_t)layer*WOUT1);
    float* C = (MODE==0) ? g_zx : g_resid;
    const int N = (MODE==0) ? DIP : DM;
    const int K = (MODE==0) ? DM  : DI;

    extern __shared__ float sh[];
    float* shB = sh + NSTAGE*AS_FLOATS;

    int tid  = threadIdx.x;
    int warp = tid >> 5;
    int lane = tid & 31;
    int gid  = lane >> 2;
    int tig  = lane & 3;

    int m0 = blockIdx.y * GBM;
    int n0 = blockIdx.x * GBN;
    int wm = (warp & 1) * 64;
    int wn = (warp >> 1) * 32;

    float acc[4][4][4];
    #pragma unroll
    for (int i=0;i<4;i++)
        #pragma unroll
        for (int j=0;j<4;j++)
            #pragma unroll
            for (int q=0;q<4;q++) acc[i][j][q]=0.f;

    const int niter = K / GBK;

    int a_row0 = (tid      ) >> 2, a_kc0 = ((tid      ) & 3) << 2;
    int a_row1 = (tid + 256) >> 2, a_kc1 = ((tid + 256) & 3) << 2;
    int b_row0 = (tid      ) >> 5, b_nc0 = ((tid      ) & 31) << 2;
    int b_row1 = (tid + 256) >> 5, b_nc1 = ((tid + 256) & 31) << 2;
    int b_ok0 = (n0 + b_nc0 < N) ? 16 : 0;
    int b_ok1 = (n0 + b_nc1 < N) ? 16 : 0;
    const float* bsrc0_base = W + (size_t)b_row0*N + ((n0 + b_nc0 < N) ? (n0 + b_nc0) : 0);
    const float* bsrc1_base = W + (size_t)b_row1*N + ((n0 + b_nc1 < N) ? (n0 + b_nc1) : 0);
    const float* asrc0_base = A + (size_t)(m0 + a_row0)*K + a_kc0;
    const float* asrc1_base = A + (size_t)(m0 + a_row1)*K + a_kc1;

    uint32_t adst0 = (uint32_t)__cvta_generic_to_shared(&sh [a_row0*AS_STRIDE + a_kc0]);
    uint32_t adst1 = (uint32_t)__cvta_generic_to_shared(&sh [a_row1*AS_STRIDE + a_kc1]);
    uint32_t bdst0 = (uint32_t)__cvta_generic_to_shared(&shB[b_row0*BS_STRIDE + b_nc0]);
    uint32_t bdst1 = (uint32_t)__cvta_generic_to_shared(&shB[b_row1*BS_STRIDE + b_nc1]);

    auto issue_copy = [&](int st, int it){
        int k0 = it * GBK;
        uint32_t ao = st*AS_FLOATS*4, bo = st*BS_FLOATS*4;
        asm volatile("cp.async.cg.shared.global [%0], [%1], 16;\n"
                     :: "r"(adst0 + ao), "l"(asrc0_base + k0));
        asm volatile("cp.async.cg.shared.global [%0], [%1], 16;\n"
                     :: "r"(adst1 + ao), "l"(asrc1_base + k0));
        asm volatile("cp.async.cg.shared.global [%0], [%1], 16, %2;\n"
                     :: "r"(bdst0 + bo), "l"(bsrc0_base + (size_t)k0*N), "r"(b_ok0));
        asm volatile("cp.async.cg.shared.global [%0], [%1], 16, %2;\n"
                     :: "r"(bdst1 + bo), "l"(bsrc1_base + (size_t)k0*N), "r"(b_ok1));
    };

    #pragma unroll
    for (int st=0; st<NSTAGE-1; st++){
        if (st < niter) issue_copy(st, st);
        asm volatile("cp.async.commit_group;\n");
    }

    for (int it=0; it<niter; ++it){
        asm volatile("cp.async.wait_group %0;\n" :: "n"(NSTAGE-2));
        __syncthreads();

        int cb = it & (NSTAGE-1);
        const float* Asb = &sh [cb*AS_FLOATS];
        const float* Bsb = &shB[cb*BS_FLOATS];

        #pragma unroll
        for (int ks=0; ks<GBK; ks+=8){
            uint32_t af[4][4], bf[4][2];
            #pragma unroll
            for (int mi=0; mi<4; mi++){
                int mr = wm + 16*mi;
                af[mi][0] = __float_as_uint(Asb[(mr+gid  )*AS_STRIDE + ks+tig  ]);
                af[mi][1] = __float_as_uint(Asb[(mr+gid+8)*AS_STRIDE + ks+tig  ]);
                af[mi][2] = __float_as_uint(Asb[(mr+gid  )*AS_STRIDE + ks+tig+4]);
                af[mi][3] = __float_as_uint(Asb[(mr+gid+8)*AS_STRIDE + ks+tig+4]);
            }
            #pragma unroll
            for (int ni=0; ni<4; ni++){
                int nb = wn + 8*ni;
                bf[ni][0] = __float_as_uint(Bsb[(ks+tig  )*BS_STRIDE + nb+gid]);
                bf[ni][1] = __float_as_uint(Bsb[(ks+tig+4)*BS_STRIDE + nb+gid]);
            }
            #pragma unroll
            for (int mi=0; mi<4; mi++)
                #pragma unroll
                for (int ni=0; ni<4; ni++)
                    mma_tf32(acc[mi][ni], af[mi], bf[ni]);
        }

        int nx = it + NSTAGE - 1;
        if (nx < niter) issue_copy(nx & (NSTAGE-1), nx);
        asm volatile("cp.async.commit_group;\n");
    }

    #pragma unroll
    for (int mi=0; mi<4; mi++){
        int r0 = m0 + wm + 16*mi + gid;
        #pragma unroll
        for (int ni=0; ni<4; ni++){
            int c0 = n0 + wn + 8*ni + 2*tig;
            float* a = acc[mi][ni];
            if (c0 < N){
                size_t i0 = (size_t)r0*N + c0;
                size_t i2 = (size_t)(r0+8)*N + c0;
                if (MODE){ C[i0] += a[0]; C[i2] += a[2]; }
                else     { C[i0]  = a[0]; C[i2]  = a[2]; }
            }
            if (c0+1 < N){
                size_t i1 = (size_t)r0*N + c0+1;
                size_t i3 = (size_t)(r0+8)*N + c0+1;
                if (MODE){ C[i1] += a[1]; C[i3] += a[3]; }
                else     { C[i1]  = a[1]; C[i3]  = a[3]; }
            }
        }
    }
}

// ---------------- causal depthwise conv (k=4) + silu, float4 vectorized ----------------
__global__ void conv_kernel(const float* __restrict__ cw, const float* __restrict__ cb)
{
    int i = blockIdx.x * blockDim.x + threadIdx.x;
    if (i >= NT*(CD/4)) return;
    int cg = i % (CD/4);
    int bt = i / (CD/4);
    int t  = bt % LL;
    int c  = cg << 2;
    const float* base = g_zx + (size_t)bt*DIP + DI + c;

    float4 w0 = *(const float4*)&cw[(c+0)*4];
    float4 w1 = *(const float4*)&cw[(c+1)*4];
    float4 w2 = *(const float4*)&cw[(c+2)*4];
    float4 w3 = *(const float4*)&cw[(c+3)*4];
    float4 acc = *(const float4*)&cb[c];

    #pragma unroll
    for (int k=0;k<4;k++){
        int off = k - 3;
        if (t + off >= 0){
            float4 v = *(const float4*)(base + (ptrdiff_t)off*DIP);
            float wk0 = (k==0)?w0.x:(k==1)?w0.y:(k==2)?w0.z:w0.w;
            float wk1 = (k==0)?w1.x:(k==1)?w1.y:(k==2)?w1.z:w1.w;
            float wk2 = (k==0)?w2.x:(k==1)?w2.y:(k==2)?w2.z:w2.w;
            float wk3 = (k==0)?w3.x:(k==1)?w3.y:(k==2)?w3.z:w3.w;
            acc.x = fmaf(v.x, wk0, acc.x);
            acc.y = fmaf(v.y, wk1, acc.y);
            acc.z = fmaf(v.z, wk2, acc.z);
            acc.w = fmaf(v.w, wk3, acc.w);
        }
    }
    float4 r;
    r.x = acc.x / (1.f + __expf(-acc.x));
    r.y = acc.y / (1.f + __expf(-acc.y));
    r.z = acc.z / (1.f + __expf(-acc.z));
    r.w = acc.w / (1.f + __expf(-acc.w));
    *(float4*)&g_xBC[(size_t)bt*CD + c] = r;
}

// ---------------- dt = softplus(raw+bias); dA = exp(-exp(A_log)*dt) ----------------
__global__ void dtda_kernel(const float* __restrict__ dtb, const float* __restrict__ alog)
{
    int i = blockIdx.x * blockDim.x + threadIdx.x;
    if (i >= NT*NH) return;
    int hh = i % NH;
    int bt = i / NH;
    float raw = g_zx[(size_t)bt*DIP + (DIP-NH) + hh] + dtb[hh];
    float sp = (raw > 20.f) ? raw : log1pf(expf(raw));
    g_dt[i] = sp;
    g_dA[i] = expf(-expf(alog[hh]) * sp);
}

// ---------------- selective scan: CTA per (b, head-pair); 96 threads; f32x2 packed ----------------
__global__ __launch_bounds__(96) void scan_kernel()
{
    int b   = blockIdx.x >> 3;
    int hp  = blockIdx.x & 7;
    int tid = threadIdx.x;
    int hl  = tid / HD;          // 0 or 1
    int p   = tid - hl*HD;       // 0..47
    int h   = hp*2 + hl;

    __shared__ __align__(16) ull B2[2][DS/2];
    __shared__ __align__(16) ull C2[2][DS/2];

    ull s[DS/2];
    #pragma unroll
    for (int q=0;q<DS/2;q++) s[q]=0ull;

    // prologue t=0
    {
        const float* row = g_xBC + (size_t)(b*LL)*CD;
        if (tid < 32)      B2[0][tid]    = *(const ull*)(row + DI + 2*tid);
        else if (tid < 64) C2[0][tid-32] = *(const ull*)(row + DI + DS + 2*(tid-32));
    }
    float x_cur  = g_xBC[(size_t)(b*LL)*CD + h*HD + p];
    float dt_cur = g_dt[(b*LL)*NH + h];
    float dA_cur = g_dA[(b*LL)*NH + h];
    __syncthreads();

    for (int t=0; t<LL; t++){
        int cur = t & 1;
        ull Bn=0ull, Cn=0ull; float xn=0.f, dtn=0.f, dAn=0.f;
        if (t+1 < LL){
            int bt1 = b*LL + t + 1;
            const float* row1 = g_xBC + (size_t)bt1*CD;
            if (tid < 32)      Bn = *(const ull*)(row1 + DI + 2*tid);
            else if (tid < 64) Cn = *(const ull*)(row1 + DI + DS + 2*(tid-32));
            xn  = row1[h*HD + p];
            dtn = g_dt[bt1*NH + h];
            dAn = g_dA[bt1*NH + h];
        }

        float dtx = dt_cur * x_cur;
        ull dA2  = pk2(dA_cur, dA_cur);
        ull dtx2 = pk2(dtx, dtx);
        ull ya=0ull, yb=0ull, yc=0ull, yd=0ull;

        #pragma unroll
        for (int q=0;q<DS/2;q+=4){
            ull t0,t1,t2,t3;
            MUL2(t0, dtx2, B2[cur][q+0]); FMA2(s[q+0], s[q+0], dA2, t0); FMA2(ya, s[q+0], C2[cur][q+0], ya);
            MUL2(t1, dtx2, B2[cur][q+1]); FMA2(s[q+1], s[q+1], dA2, t1); FMA2(yb, s[q+1], C2[cur][q+1], yb);
            MUL2(t2, dtx2, B2[cur][q+2]); FMA2(s[q+2], s[q+2], dA2, t2); FMA2(yc, s[q+2], C2[cur][q+2], yc);
            MUL2(t3, dtx2, B2[cur][q+3]); FMA2(s[q+3], s[q+3], dA2, t3); FMA2(yd, s[q+3], C2[cur][q+3], yd);
        }
        float a0,a1,b0,b1,c0,c1,d0,d1;
        upk2(a0,a1,ya); upk2(b0,b1,yb); upk2(c0,c1,yc); upk2(d0,d1,yd);
        g_ys[(size_t)(b*LL+t)*DI + h*HD + p] = ((a0+a1)+(b0+b1)) + ((c0+c1)+(d0+d1));

        if (t+1 < LL){
            if (tid < 32)      B2[cur^1][tid]    = Bn;
            else if (tid < 64) C2[cur^1][tid-32] = Cn;
        }
        x_cur = xn; dt_cur = dtn; dA_cur = dAn;
        __syncthreads();
    }
}

// ---------------- y = (ys + D*x) * silu(z); RMS-norm with gnorm_w -> g_yn (tf32) ----------------
__global__ __launch_bounds__(256) void gate_rms_kernel(const float* __restrict__ Dp,
                                                       const float* __restrict__ gnorm)
{
    __shared__ float red[256];
    int row = blockIdx.x, tid = threadIdx.x;
    float v[3]; float ss = 0.f;
    #pragma unroll
    for (int q=0;q<3;q++){
        int i = tid + q*256;
        float ys = g_ys[(size_t)row*DI + i];
        float xv = g_xBC[(size_t)row*CD + i];
        float z  = g_zx [(size_t)row*DIP + i];
        float val = (ys + Dp[i/HD]*xv) * (z / (1.f + __expf(-z)));
        v[q] = val; ss += val*val;
    }
    red[tid] = ss; __syncthreads();
    for (int s=128;s>0;s>>=1){ if(tid<s) red[tid]+=red[tid+s]; __syncthreads(); }
    float scale = rsqrtf(red[0]*(1.0f/DI) + 1e-5f);
    #pragma unroll
    for (int q=0;q<3;q++){
        int i = tid + q*256;
        g_yn[(size_t)row*DI + i] = __uint_as_float(f2tf(v[q]*scale*gnorm[i]));
    }
}

// ---------------- mean over t + layernorm -> g_feat ----------------
__global__ __launch_bounds__(128) void pool_ln_kernel(const float* __restrict__ w,
                                                      const float* __restrict__ b)
{
    __shared__ float red[128];
    int bb = blockIdx.x, tid = threadIdx.x;
    float v[3];
    #pragma unroll
    for (int q=0;q<3;q++){
        int d = tid + q*128;
        const float* p = g_h + (size_t)bb*LL*DM + d;
        float s = 0.f;
        for (int t=0;t<LL;t++) s += p[(size_t)t*DM];
        v[q] = s * (1.0f/LL);
    }
    red[tid] = v[0]+v[1]+v[2]; __syncthreads();
    for (int s=64;s>0;s>>=1){ if(tid<s) red[tid]+=red[tid+s]; __syncthreads(); }
    float mu = red[0]*(1.0f/DM);
    __syncthreads();
    float d0=v[0]-mu, d1=v[1]-mu, d2=v[2]-mu;
    red[tid] = d0*d0+d1*d1+d2*d2; __syncthreads();
    for (int s=64;s>0;s>>=1){ if(tid<s) red[tid]+=red[tid+s]; __syncthreads(); }
    float inv = rsqrtf(red[0]*(1.0f/DM) + 1e-5f);
    g_feat[bb*DM+tid]     = d0*inv*w[tid]     + b[tid];
    g_feat[bb*DM+tid+128] = d1*inv*w[tid+128] + b[tid+128];
    g_feat[bb*DM+tid+256] = d2*inv*w[tid+256] + b[tid+256];
}

// ---------------- classification heads: out[32, 38667] ----------------
__global__ __launch_bounds__(256) void heads_kernel(
    const float* __restrict__ ow, const float* __restrict__ ob,
    const float* __restrict__ fw, const float* __restrict__ fb,
    const float* __restrict__ gw, const float* __restrict__ gb,
    const float* __restrict__ sw, const float* __restrict__ sb,
    float* __restrict__ out)
{
    __shared__ float sf[BB*DM];
    int tid = threadIdx.x;
    for (int i = tid; i < BB*DM; i += blockDim.x) sf[i] = g_feat[i];
    __syncthreads();

    int j = blockIdx.x * blockDim.x + tid;
    if (j >= NOUT) return;

    const float* W; const float* Bv; int jj, Nseg;
    if (j < N_ORDER)                      { W=ow; Bv=ob; jj=j;                     Nseg=N_ORDER; }
    else if (j < N_ORDER+N_FAMILY)        { W=fw; Bv=fb; jj=j-N_ORDER;             Nseg=N_FAMILY; }
    else if (j < N_ORDER+N_FAMILY+N_GENUS){ W=gw; Bv=gb; jj=j-N_ORDER-N_FAMILY;    Nseg=N_GENUS; }
    else                                  { W=sw; Bv=sb; jj=j-N_ORDER-N_FAMILY-N_GENUS; Nseg=N_SPECIES; }

    float acc[BB];
    #pragma unroll
    for (int b=0;b<BB;b++) acc[b]=0.f;
    for (int k=0;k<DM;k++){
        float wv = W[(size_t)k*Nseg + jj];
        #pragma unroll
        for (int b=0;b<BB;b++) acc[b] = fmaf(sf[b*DM + k], wv, acc[b]);
    }
    float bias = Bv[jj];
    #pragma unroll
    for (int b=0;b<BB;b++) out[(size_t)b*NOUT + j] = acc[b] + bias;
}

// ---------------- orchestration ----------------
extern "C" void kernel_launch(void* const* d_in, const int* in_sizes, int n_in,
                              void* d_out, int out_size)
{
    const int*   tokens = (const int*)  d_in[0];
    const float* emb    = (const float*)d_in[1];
    const float* ln_w   = (const float*)d_in[2];
    const float* ln_b   = (const float*)d_in[3];
    const float* Win    = (const float*)d_in[4];
    const float* cw     = (const float*)d_in[5];
    const float* cb     = (const float*)d_in[6];
    const float* dtb    = (const float*)d_in[7];
    const float* alog   = (const float*)d_in[8];
    const float* Dd     = (const float*)d_in[9];
    const float* gnw    = (const float*)d_in[10];
    const float* Wout   = (const float*)d_in[11];
    const float* nfw    = (const float*)d_in[12];
    const float* nfb    = (const float*)d_in[13];
    const float* plw    = (const float*)d_in[14];
    const float* plb    = (const float*)d_in[15];
    const float* ow     = (const float*)d_in[16];
    const float* ob     = (const float*)d_in[17];
    const float* fw     = (const float*)d_in[18];
    const float* fb     = (const float*)d_in[19];
    const float* gw     = (const float*)d_in[20];
    const float* gb     = (const float*)d_in[21];
    const float* sw     = (const float*)d_in[22];
    const float* sb     = (const float*)d_in[23];
    float* out = (float*)d_out;

    const int smem_bytes = SMEM_FLOATS * 4;
    cudaFuncSetAttribute(gemm_tc<0>, cudaFuncAttributeMaxDynamicSharedMemorySize, smem_bytes);
    cudaFuncSetAttribute(gemm_tc<1>, cudaFuncAttributeMaxDynamicSharedMemorySize, smem_bytes);

    embed_kernel<<<(NT*DM + 255)/256, 256>>>(tokens, emb);
    wcvt_kernel<<<(2*WIN1 + 2*WOUT1 + 255)/256, 256>>>(Win, Wout);

    for (int l = 0; l < 2; l++) {
        ln_kernel<<<NT, 128>>>(ln_w + l*DM, ln_b + l*DM, 1);
        gemm_tc<0><<<dim3((DIP+GBN-1)/GBN, NT/GBM), 256, smem_bytes>>>(l);
        conv_kernel<<<(NT*(CD/4) + 255)/256, 256>>>(cw + (size_t)l*CD*4, cb + l*CD);
        dtda_kernel<<<(NT*NH + 255)/256, 256>>>(dtb + l*NH, alog + l*NH);
        scan_kernel<<<BB*8, 96>>>();
        gate_rms_kernel<<<NT, 256>>>(Dd + l*NH, gnw + l*DI);
        gemm_tc<1><<<dim3((DM+GBN-1)/GBN, NT/GBM), 256, smem_bytes>>>(l);
    }

    ln_kernel<<<NT, 128>>>(nfw, nfb, 0);
    pool_ln_kernel<<<BB, 128>>>(plw, plb);
    heads_kernel<<<(NOUT + 255)/256, 256>>>(ow, ob, fw, fb, gw, gb, sw, sb, out);
}

// round 5
// speedup vs baseline: 3.3440x; 1.2316x over previous
#include <cuda_runtime.h>
#include <math.h>
#include <stddef.h>
#include <stdint.h>

typedef unsigned long long ull;

// ---------------- problem constants ----------------
#define BB   32
#define LL   512
#define DM   384
#define DI   768
#define DS   64
#define NH   16
#define HD   48
#define DIP  1680
#define CD   896
#define NT   (BB*LL)
#define NOUT 38667
#define N_ORDER 60
#define N_FAMILY 427
#define N_GENUS 14216
#define N_SPECIES 23964

#define WIN1  (DM*DIP)
#define WOUT1 (DI*DM)

// ---------------- scratch ----------------
__device__ float g_resid[(size_t)NT*DM];
__device__ float g_h    [(size_t)NT*DM];
__device__ float g_zx   [(size_t)NT*DIP];
__device__ float g_xBC  [(size_t)NT*CD];
__device__ float g_dt   [(size_t)NT*NH];
__device__ float g_dA   [(size_t)NT*NH];
__device__ float g_ys   [(size_t)NT*DI];
__device__ float g_yn   [(size_t)NT*DI];
__device__ float g_feat [(size_t)BB*DM];
__device__ float g_wtf  [2*WIN1 + 2*WOUT1];

__device__ __forceinline__ uint32_t f2tf(float x){
    uint32_t y;
    asm volatile("cvt.rna.tf32.f32 %0, %1;" : "=r"(y) : "f"(x));
    return y;
}
__device__ __forceinline__ ull pk2(float lo, float hi){
    ull r; asm("mov.b64 %0, {%1, %2};" : "=l"(r) : "f"(lo), "f"(hi)); return r;
}
__device__ __forceinline__ void upk2(float& lo, float& hi, ull v){
    asm("mov.b64 {%0, %1}, %2;" : "=f"(lo), "=f"(hi) : "l"(v));
}
#define MUL2(out,a,b)   asm("mul.rn.f32x2 %0,%1,%2;"    : "=l"(out) : "l"(a), "l"(b))
#define FMA2(out,a,b,c) asm("fma.rn.f32x2 %0,%1,%2,%3;" : "=l"(out) : "l"(a), "l"(b), "l"(c))

// ---------------- weight tf32 pre-convert ----------------
__global__ void wcvt_kernel(const float* __restrict__ Win, const float* __restrict__ Wout)
{
    int i = blockIdx.x * blockDim.x + threadIdx.x;
    int total = 2*WIN1 + 2*WOUT1;
    if (i >= total) return;
    float v = (i < 2*WIN1) ? Win[i] : Wout[i - 2*WIN1];
    g_wtf[i] = __uint_as_float(f2tf(v));
}

// ---------------- fused embedding gather + layer-0 layernorm ----------------
__global__ __launch_bounds__(128) void embed_ln_kernel(const int* __restrict__ tokens,
                                                       const float* __restrict__ emb,
                                                       const float* __restrict__ w,
                                                       const float* __restrict__ b)
{
    __shared__ float red[128];
    int row = blockIdx.x, tid = threadIdx.x;
    const float* er = emb + (size_t)tokens[row]*DM;
    float v0 = er[tid], v1 = er[tid+128], v2 = er[tid+256];
    float* rr = g_resid + (size_t)row*DM;
    rr[tid] = v0; rr[tid+128] = v1; rr[tid+256] = v2;

    red[tid] = v0+v1+v2; __syncthreads();
    for (int s=64;s>0;s>>=1){ if(tid<s) red[tid]+=red[tid+s]; __syncthreads(); }
    float mu = red[0] * (1.0f/DM);
    __syncthreads();
    float d0=v0-mu, d1=v1-mu, d2=v2-mu;
    red[tid] = d0*d0+d1*d1+d2*d2; __syncthreads();
    for (int s=64;s>0;s>>=1){ if(tid<s) red[tid]+=red[tid+s]; __syncthreads(); }
    float inv = rsqrtf(red[0]*(1.0f/DM) + 1e-5f);
    float* o = g_h + (size_t)row*DM;
    o[tid]     = __uint_as_float(f2tf(d0*inv*w[tid]     + b[tid]));
    o[tid+128] = __uint_as_float(f2tf(d1*inv*w[tid+128] + b[tid+128]));
    o[tid+256] = __uint_as_float(f2tf(d2*inv*w[tid+256] + b[tid+256]));
}

// ---------------- layernorm: g_resid -> g_h ----------------
__global__ __launch_bounds__(128) void ln_kernel(const float* __restrict__ w, const float* __restrict__ b, int tf)
{
    __shared__ float red[128];
    int row = blockIdx.x, tid = threadIdx.x;
    const float* xr = g_resid + (size_t)row*DM;
    float v0 = xr[tid], v1 = xr[tid+128], v2 = xr[tid+256];
    red[tid] = v0+v1+v2; __syncthreads();
    for (int s=64;s>0;s>>=1){ if(tid<s) red[tid]+=red[tid+s]; __syncthreads(); }
    float mu = red[0] * (1.0f/DM);
    __syncthreads();
    float d0=v0-mu, d1=v1-mu, d2=v2-mu;
    red[tid] = d0*d0+d1*d1+d2*d2; __syncthreads();
    for (int s=64;s>0;s>>=1){ if(tid<s) red[tid]+=red[tid+s]; __syncthreads(); }
    float inv = rsqrtf(red[0]*(1.0f/DM) + 1e-5f);
    float o0 = d0*inv*w[tid]     + b[tid];
    float o1 = d1*inv*w[tid+128] + b[tid+128];
    float o2 = d2*inv*w[tid+256] + b[tid+256];
    if (tf){
        o0 = __uint_as_float(f2tf(o0));
        o1 = __uint_as_float(f2tf(o1));
        o2 = __uint_as_float(f2tf(o2));
    }
    float* o = g_h + (size_t)row*DM;
    o[tid] = o0; o[tid+128] = o1; o[tid+256] = o2;
}

// ---------------- tf32 tensor-core GEMM, cp.async 4-stage pipeline, optional split-K ----------------
#define GBM 128
#define GBN 128
#define GBK 16
#define NSTAGE 4
#define AS_STRIDE 20
#define BS_STRIDE 132
#define AS_FLOATS (GBM*AS_STRIDE)
#define BS_FLOATS (GBK*BS_STRIDE)
#define SMEM_FLOATS (NSTAGE*(AS_FLOATS+BS_FLOATS))

__device__ __forceinline__ void mma_tf32(float* c, const uint32_t* a, const uint32_t* b){
    asm volatile(
      "mma.sync.aligned.m16n8k8.row.col.f32.tf32.tf32.f32 "
      "{%0,%1,%2,%3}, {%4,%5,%6,%7}, {%8,%9}, {%0,%1,%2,%3};\n"
      : "+f"(c[0]), "+f"(c[1]), "+f"(c[2]), "+f"(c[3])
      : "r"(a[0]), "r"(a[1]), "r"(a[2]), "r"(a[3]), "r"(b[0]), "r"(b[1]));
}

// MODE 0: g_zx = g_h @ Wtf  (store).  MODE 1: g_resid += g_yn @ Wtf (atomicAdd, split-K).
template<int MODE, int SPLITK>
__global__ __launch_bounds__(256,2) void gemm_tc(int layer)
{
    const float* __restrict__ A = (MODE==0) ? g_h : g_yn;
    const float* __restrict__ W = (MODE==0) ? (g_wtf + (size_t)layer*WIN1)
                                            : (g_wtf + 2*WIN1 + (size_t)layer*WOUT1);
    float* C = (MODE==0) ? g_zx : g_resid;
    const int N = (MODE==0) ? DIP : DM;
    const int K = (MODE==0) ? DM  : DI;
    const int Ks = K / SPLITK;
    const int k_origin = blockIdx.z * Ks;

    extern __shared__ float sh[];
    float* shB = sh + NSTAGE*AS_FLOATS;

    int tid  = threadIdx.x;
    int warp = tid >> 5;
    int lane = tid & 31;
    int gid  = lane >> 2;
    int tig  = lane & 3;

    int m0 = blockIdx.y * GBM;
    int n0 = blockIdx.x * GBN;
    int wm = (warp & 1) * 64;
    int wn = (warp >> 1) * 32;

    float acc[4][4][4];
    #pragma unroll
    for (int i=0;i<4;i++)
        #pragma unroll
        for (int j=0;j<4;j++)
            #pragma unroll
            for (int q=0;q<4;q++) acc[i][j][q]=0.f;

    const int niter = Ks / GBK;

    int a_row0 = (tid      ) >> 2, a_kc0 = ((tid      ) & 3) << 2;
    int a_row1 = (tid + 256) >> 2, a_kc1 = ((tid + 256) & 3) << 2;
    int b_row0 = (tid      ) >> 5, b_nc0 = ((tid      ) & 31) << 2;
    int b_row1 = (tid + 256) >> 5, b_nc1 = ((tid + 256) & 31) << 2;
    int b_ok0 = (n0 + b_nc0 < N) ? 16 : 0;
    int b_ok1 = (n0 + b_nc1 < N) ? 16 : 0;
    const float* bsrc0_base = W + (size_t)(b_row0 + k_origin)*N + ((n0 + b_nc0 < N) ? (n0 + b_nc0) : 0);
    const float* bsrc1_base = W + (size_t)(b_row1 + k_origin)*N + ((n0 + b_nc1 < N) ? (n0 + b_nc1) : 0);
    const float* asrc0_base = A + (size_t)(m0 + a_row0)*K + k_origin + a_kc0;
    const float* asrc1_base = A + (size_t)(m0 + a_row1)*K + k_origin + a_kc1;

    uint32_t adst0 = (uint32_t)__cvta_generic_to_shared(&sh [a_row0*AS_STRIDE + a_kc0]);
    uint32_t adst1 = (uint32_t)__cvta_generic_to_shared(&sh [a_row1*AS_STRIDE + a_kc1]);
    uint32_t bdst0 = (uint32_t)__cvta_generic_to_shared(&shB[b_row0*BS_STRIDE + b_nc0]);
    uint32_t bdst1 = (uint32_t)__cvta_generic_to_shared(&shB[b_row1*BS_STRIDE + b_nc1]);

    auto issue_copy = [&](int st, int it){
        int k0 = it * GBK;
        uint32_t ao = st*AS_FLOATS*4, bo = st*BS_FLOATS*4;
        asm volatile("cp.async.cg.shared.global [%0], [%1], 16;\n"
                     :: "r"(adst0 + ao), "l"(asrc0_base + k0));
        asm volatile("cp.async.cg.shared.global [%0], [%1], 16;\n"
                     :: "r"(adst1 + ao), "l"(asrc1_base + k0));
        asm volatile("cp.async.cg.shared.global [%0], [%1], 16, %2;\n"
                     :: "r"(bdst0 + bo), "l"(bsrc0_base + (size_t)k0*N), "r"(b_ok0));
        asm volatile("cp.async.cg.shared.global [%0], [%1], 16, %2;\n"
                     :: "r"(bdst1 + bo), "l"(bsrc1_base + (size_t)k0*N), "r"(b_ok1));
    };

    #pragma unroll
    for (int st=0; st<NSTAGE-1; st++){
        if (st < niter) issue_copy(st, st);
        asm volatile("cp.async.commit_group;\n");
    }

    for (int it=0; it<niter; ++it){
        asm volatile("cp.async.wait_group %0;\n" :: "n"(NSTAGE-2));
        __syncthreads();

        int cb = it & (NSTAGE-1);
        const float* Asb = &sh [cb*AS_FLOATS];
        const float* Bsb = &shB[cb*BS_FLOATS];

        #pragma unroll
        for (int ks=0; ks<GBK; ks+=8){
            uint32_t af[4][4], bf[4][2];
            #pragma unroll
            for (int mi=0; mi<4; mi++){
                int mr = wm + 16*mi;
                af[mi][0] = __float_as_uint(Asb[(mr+gid  )*AS_STRIDE + ks+tig  ]);
                af[mi][1] = __float_as_uint(Asb[(mr+gid+8)*AS_STRIDE + ks+tig  ]);
                af[mi][2] = __float_as_uint(Asb[(mr+gid  )*AS_STRIDE + ks+tig+4]);
                af[mi][3] = __float_as_uint(Asb[(mr+gid+8)*AS_STRIDE + ks+tig+4]);
            }
            #pragma unroll
            for (int ni=0; ni<4; ni++){
                int nb = wn + 8*ni;
                bf[ni][0] = __float_as_uint(Bsb[(ks+tig  )*BS_STRIDE + nb+gid]);
                bf[ni][1] = __float_as_uint(Bsb[(ks+tig+4)*BS_STRIDE + nb+gid]);
            }
            #pragma unroll
            for (int mi=0; mi<4; mi++)
                #pragma unroll
                for (int ni=0; ni<4; ni++)
                    mma_tf32(acc[mi][ni], af[mi], bf[ni]);
        }

        int nx = it + NSTAGE - 1;
        if (nx < niter) issue_copy(nx & (NSTAGE-1), nx);
        asm volatile("cp.async.commit_group;\n");
    }

    #pragma unroll
    for (int mi=0; mi<4; mi++){
        int r0 = m0 + wm + 16*mi + gid;
        #pragma unroll
        for (int ni=0; ni<4; ni++){
            int c0 = n0 + wn + 8*ni + 2*tig;
            float* a = acc[mi][ni];
            #pragma unroll
            for (int half=0; half<2; half++){
                int cc = c0 + half;
                if (cc < N){
                    size_t i0 = (size_t)r0*N + cc;
                    size_t i2 = (size_t)(r0+8)*N + cc;
                    if (MODE){ atomicAdd(&C[i0], a[half]); atomicAdd(&C[i2], a[2+half]); }
                    else     { C[i0] = a[half]; C[i2] = a[2+half]; }
                }
            }
        }
    }
}

// ---------------- fused: causal conv (k=4)+silu AND dt/dA ----------------
#define CONV_N (NT*(CD/4))
#define DTDA_N (NT*(NH/4))
__global__ void conv_dtda_kernel(const float* __restrict__ cw, const float* __restrict__ cb,
                                 const float* __restrict__ dtb, const float* __restrict__ alog)
{
    int i = blockIdx.x * blockDim.x + threadIdx.x;
    if (i < CONV_N){
        int cg = i % (CD/4);
        int bt = i / (CD/4);
        int t  = bt % LL;
        int c  = cg << 2;
        const float* base = g_zx + (size_t)bt*DIP + DI + c;

        float4 w0 = *(const float4*)&cw[(c+0)*4];
        float4 w1 = *(const float4*)&cw[(c+1)*4];
        float4 w2 = *(const float4*)&cw[(c+2)*4];
        float4 w3 = *(const float4*)&cw[(c+3)*4];
        float4 acc = *(const float4*)&cb[c];

        #pragma unroll
        for (int k=0;k<4;k++){
            int off = k - 3;
            if (t + off >= 0){
                float4 v = *(const float4*)(base + (ptrdiff_t)off*DIP);
                float wk0 = (k==0)?w0.x:(k==1)?w0.y:(k==2)?w0.z:w0.w;
                float wk1 = (k==0)?w1.x:(k==1)?w1.y:(k==2)?w1.z:w1.w;
                float wk2 = (k==0)?w2.x:(k==1)?w2.y:(k==2)?w2.z:w2.w;
                float wk3 = (k==0)?w3.x:(k==1)?w3.y:(k==2)?w3.z:w3.w;
                acc.x = fmaf(v.x, wk0, acc.x);
                acc.y = fmaf(v.y, wk1, acc.y);
                acc.z = fmaf(v.z, wk2, acc.z);
                acc.w = fmaf(v.w, wk3, acc.w);
            }
        }
        float4 r;
        r.x = acc.x / (1.f + __expf(-acc.x));
        r.y = acc.y / (1.f + __expf(-acc.y));
        r.z = acc.z / (1.f + __expf(-acc.z));
        r.w = acc.w / (1.f + __expf(-acc.w));
        *(float4*)&g_xBC[(size_t)bt*CD + c] = r;
    } else {
        int j = i - CONV_N;
        if (j >= DTDA_N) return;
        int hq = (j % (NH/4)) << 2;
        int bt = j / (NH/4);
        #pragma unroll
        for (int q=0;q<4;q++){
            int hh = hq + q;
            float raw = g_zx[(size_t)bt*DIP + (DIP-NH) + hh] + dtb[hh];
            float sp = (raw > 20.f) ? raw : log1pf(expf(raw));
            g_dt[bt*NH + hh] = sp;
            g_dA[bt*NH + hh] = expf(-expf(alog[hh]) * sp);
        }
    }
}

// ---------------- selective scan: CTA per (b, head-pair); 2 steps per barrier; f32x2 ----------------
__global__ __launch_bounds__(96) void scan_kernel()
{
    int b   = blockIdx.x >> 3;
    int hp  = blockIdx.x & 7;
    int tid = threadIdx.x;
    int hl  = tid / HD;
    int p   = tid - hl*HD;
    int h   = hp*2 + hl;

    __shared__ __align__(16) ull B2[2][2][DS/2];   // [set][parity][pair]
    __shared__ __align__(16) ull C2[2][2][DS/2];

    ull s[DS/2];
    #pragma unroll
    for (int q=0;q<DS/2;q++) s[q]=0ull;

    const size_t bh_dt = (size_t)(b*LL)*NH + h;
    const size_t bh_x  = (size_t)(b*LL)*CD + h*HD + p;

    // preload t=0,1 into set 0
    {
        const float* r0 = g_xBC + (size_t)(b*LL)*CD;
        const float* r1 = r0 + CD;
        if (tid < 32){
            B2[0][0][tid] = *(const ull*)(r0 + DI + 2*tid);
            B2[0][1][tid] = *(const ull*)(r1 + DI + 2*tid);
        } else if (tid < 64){
            int q = tid-32;
            C2[0][0][q] = *(const ull*)(r0 + DI + DS + 2*q);
            C2[0][1][q] = *(const ull*)(r1 + DI + DS + 2*q);
        }
    }
    float x0  = g_xBC[bh_x],        x1  = g_xBC[bh_x + CD];
    float dt0 = g_dt[bh_dt],        dt1 = g_dt[bh_dt + NH];
    float dA0 = g_dA[bh_dt],        dA1 = g_dA[bh_dt + NH];
    __syncthreads();

    for (int i=0; i<LL/2; i++){
        int t0 = 2*i;
        int set = i & 1;

        // prefetch t+2, t+3
        ull Bn0=0,Bn1=0,Cn0=0,Cn1=0;
        float xn0=0,xn1=0,dtn0=0,dtn1=0,dAn0=0,dAn1=0;
        if (t0+2 < LL){
            const float* r2 = g_xBC + (size_t)(b*LL + t0+2)*CD;
            const float* r3 = r2 + CD;
            if (tid < 32){
                Bn0 = *(const ull*)(r2 + DI + 2*tid);
                Bn1 = *(const ull*)(r3 + DI + 2*tid);
            } else if (tid < 64){
                int q = tid-32;
                Cn0 = *(const ull*)(r2 + DI + DS + 2*q);
                Cn1 = *(const ull*)(r3 + DI + DS + 2*q);
            }
            xn0  = g_xBC[bh_x  + (size_t)(t0+2)*CD];
            xn1  = g_xBC[bh_x  + (size_t)(t0+3)*CD];
            dtn0 = g_dt[bh_dt + (size_t)(t0+2)*NH];
            dtn1 = g_dt[bh_dt + (size_t)(t0+3)*NH];
            dAn0 = g_dA[bh_dt + (size_t)(t0+2)*NH];
            dAn1 = g_dA[bh_dt + (size_t)(t0+3)*NH];
        }

        // ---- step t0 ----
        {
            float dtx = dt0 * x0;
            ull dA2  = pk2(dA0, dA0);
            ull dtx2 = pk2(dtx, dtx);
            ull ya=0ull, yb=0ull, yc=0ull, yd=0ull;
            const ull* Bp = B2[set][0];
            const ull* Cp = C2[set][0];
            #pragma unroll
            for (int q=0;q<DS/2;q+=4){
                ull u0,u1,u2,u3;
                MUL2(u0, dtx2, Bp[q+0]); FMA2(s[q+0], s[q+0], dA2, u0); FMA2(ya, s[q+0], Cp[q+0], ya);
                MUL2(u1, dtx2, Bp[q+1]); FMA2(s[q+1], s[q+1], dA2, u1); FMA2(yb, s[q+1], Cp[q+1], yb);
                MUL2(u2, dtx2, Bp[q+2]); FMA2(s[q+2], s[q+2], dA2, u2); FMA2(yc, s[q+2], Cp[q+2], yc);
                MUL2(u3, dtx2, Bp[q+3]); FMA2(s[q+3], s[q+3], dA2, u3); FMA2(yd, s[q+3], Cp[q+3], yd);
            }
            float a0,a1,b0,b1,c0,c1,d0,d1;
            upk2(a0,a1,ya); upk2(b0,b1,yb); upk2(c0,c1,yc); upk2(d0,d1,yd);
            g_ys[(size_t)(b*LL+t0)*DI + h*HD + p] = ((a0+a1)+(b0+b1)) + ((c0+c1)+(d0+d1));
        }
        // ---- step t0+1 ----
        {
            float dtx = dt1 * x1;
            ull dA2  = pk2(dA1, dA1);
            ull dtx2 = pk2(dtx, dtx);
            ull ya=0ull, yb=0ull, yc=0ull, yd=0ull;
            const ull* Bp = B2[set][1];
            const ull* Cp = C2[set][1];
            #pragma unroll
            for (int q=0;q<DS/2;q+=4){
                ull u0,u1,u2,u3;
                MUL2(u0, dtx2, Bp[q+0]); FMA2(s[q+0], s[q+0], dA2, u0); FMA2(ya, s[q+0], Cp[q+0], ya);
                MUL2(u1, dtx2, Bp[q+1]); FMA2(s[q+1], s[q+1], dA2, u1); FMA2(yb, s[q+1], Cp[q+1], yb);
                MUL2(u2, dtx2, Bp[q+2]); FMA2(s[q+2], s[q+2], dA2, u2); FMA2(yc, s[q+2], Cp[q+2], yc);
                MUL2(u3, dtx2, Bp[q+3]); FMA2(s[q+3], s[q+3], dA2, u3); FMA2(yd, s[q+3], Cp[q+3], yd);
            }
            float a0,a1,b0,b1,c0,c1,d0,d1;
            upk2(a0,a1,ya); upk2(b0,b1,yb); upk2(c0,c1,yc); upk2(d0,d1,yd);
            g_ys[(size_t)(b*LL+t0+1)*DI + h*HD + p] = ((a0+a1)+(b0+b1)) + ((c0+c1)+(d0+d1));
        }

        if (t0+2 < LL){
            if (tid < 32){
                B2[set^1][0][tid] = Bn0;
                B2[set^1][1][tid] = Bn1;
            } else if (tid < 64){
                int q = tid-32;
                C2[set^1][0][q] = Cn0;
                C2[set^1][1][q] = Cn1;
            }
        }
        x0=xn0; x1=xn1; dt0=dtn0; dt1=dtn1; dA0=dAn0; dA1=dAn1;
        __syncthreads();
    }
}

// ---------------- y = (ys + D*x) * silu(z); RMS-norm -> g_yn (tf32) ----------------
__global__ __launch_bounds__(256) void gate_rms_kernel(const float* __restrict__ Dp,
                                                       const float* __restrict__ gnorm)
{
    __shared__ float red[256];
    int row = blockIdx.x, tid = threadIdx.x;
    float v[3]; float ss = 0.f;
    #pragma unroll
    for (int q=0;q<3;q++){
        int i = tid + q*256;
        float ys = g_ys[(size_t)row*DI + i];
        float xv = g_xBC[(size_t)row*CD + i];
        float z  = g_zx [(size_t)row*DIP + i];
        float val = (ys + Dp[i/HD]*xv) * (z / (1.f + __expf(-z)));
        v[q] = val; ss += val*val;
    }
    red[tid] = ss; __syncthreads();
    for (int s=128;s>0;s>>=1){ if(tid<s) red[tid]+=red[tid+s]; __syncthreads(); }
    float scale = rsqrtf(red[0]*(1.0f/DI) + 1e-5f);
    #pragma unroll
    for (int q=0;q<3;q++){
        int i = tid + q*256;
        g_yn[(size_t)row*DI + i] = __uint_as_float(f2tf(v[q]*scale*gnorm[i]));
    }
}

// ---------------- mean over t + layernorm -> g_feat ----------------
__global__ __launch_bounds__(128) void pool_ln_kernel(const float* __restrict__ w,
                                                      const float* __restrict__ b)
{
    __shared__ float red[128];
    int bb = blockIdx.x, tid = threadIdx.x;
    float v[3];
    #pragma unroll
    for (int q=0;q<3;q++){
        int d = tid + q*128;
        const float* p = g_h + (size_t)bb*LL*DM + d;
        float s = 0.f;
        for (int t=0;t<LL;t++) s += p[(size_t)t*DM];
        v[q] = s * (1.0f/LL);
    }
    red[tid] = v[0]+v[1]+v[2]; __syncthreads();
    for (int s=64;s>0;s>>=1){ if(tid<s) red[tid]+=red[tid+s]; __syncthreads(); }
    float mu = red[0]*(1.0f/DM);
    __syncthreads();
    float d0=v[0]-mu, d1=v[1]-mu, d2=v[2]-mu;
    red[tid] = d0*d0+d1*d1+d2*d2; __syncthreads();
    for (int s=64;s>0;s>>=1){ if(tid<s) red[tid]+=red[tid+s]; __syncthreads(); }
    float inv = rsqrtf(red[0]*(1.0f/DM) + 1e-5f);
    g_feat[bb*DM+tid]     = d0*inv*w[tid]     + b[tid];
    g_feat[bb*DM+tid+128] = d1*inv*w[tid+128] + b[tid+128];
    g_feat[bb*DM+tid+256] = d2*inv*w[tid+256] + b[tid+256];
}

// ---------------- classification heads ----------------
__global__ __launch_bounds__(256) void heads_kernel(
    const float* __restrict__ ow, const float* __restrict__ ob,
    const float* __restrict__ fw, const float* __restrict__ fb,
    const float* __restrict__ gw, const float* __restrict__ gb,
    const float* __restrict__ sw, const float* __restrict__ sb,
    float* __restrict__ out)
{
    __shared__ float sf[BB*DM];
    int tid = threadIdx.x;
    for (int i = tid; i < BB*DM; i += blockDim.x) sf[i] = g_feat[i];
    __syncthreads();

    int j = blockIdx.x * blockDim.x + tid;
    if (j >= NOUT) return;

    const float* W; const float* Bv; int jj, Nseg;
    if (j < N_ORDER)                      { W=ow; Bv=ob; jj=j;                     Nseg=N_ORDER; }
    else if (j < N_ORDER+N_FAMILY)        { W=fw; Bv=fb; jj=j-N_ORDER;             Nseg=N_FAMILY; }
    else if (j < N_ORDER+N_FAMILY+N_GENUS){ W=gw; Bv=gb; jj=j-N_ORDER-N_FAMILY;    Nseg=N_GENUS; }
    else                                  { W=sw; Bv=sb; jj=j-N_ORDER-N_FAMILY-N_GENUS; Nseg=N_SPECIES; }

    float acc[BB];
    #pragma unroll
    for (int b=0;b<BB;b++) acc[b]=0.f;
    for (int k=0;k<DM;k++){
        float wv = W[(size_t)k*Nseg + jj];
        #pragma unroll
        for (int b=0;b<BB;b++) acc[b] = fmaf(sf[b*DM + k], wv, acc[b]);
    }
    float bias = Bv[jj];
    #pragma unroll
    for (int b=0;b<BB;b++) out[(size_t)b*NOUT + j] = acc[b] + bias;
}

// ---------------- orchestration ----------------
extern "C" void kernel_launch(void* const* d_in, const int* in_sizes, int n_in,
                              void* d_out, int out_size)
{
    const int*   tokens = (const int*)  d_in[0];
    const float* emb    = (const float*)d_in[1];
    const float* ln_w   = (const float*)d_in[2];
    const float* ln_b   = (const float*)d_in[3];
    const float* Win    = (const float*)d_in[4];
    const float* cw     = (const float*)d_in[5];
    const float* cb     = (const float*)d_in[6];
    const float* dtb    = (const float*)d_in[7];
    const float* alog   = (const float*)d_in[8];
    const float* Dd     = (const float*)d_in[9];
    const float* gnw    = (const float*)d_in[10];
    const float* Wout   = (const float*)d_in[11];
    const float* nfw    = (const float*)d_in[12];
    const float* nfb    = (const float*)d_in[13];
    const float* plw    = (const float*)d_in[14];
    const float* plb    = (const float*)d_in[15];
    const float* ow     = (const float*)d_in[16];
    const float* ob     = (const float*)d_in[17];
    const float* fw     = (const float*)d_in[18];
    const float* fb     = (const float*)d_in[19];
    const float* gw     = (const float*)d_in[20];
    const float* gb     = (const float*)d_in[21];
    const float* sw     = (const float*)d_in[22];
    const float* sb     = (const float*)d_in[23];
    float* out = (float*)d_out;

    const int smem_bytes = SMEM_FLOATS * 4;
    cudaFuncSetAttribute((const void*)gemm_tc<0,1>, cudaFuncAttributeMaxDynamicSharedMemorySize, smem_bytes);
    cudaFuncSetAttribute((const void*)gemm_tc<1,2>, cudaFuncAttributeMaxDynamicSharedMemorySize, smem_bytes);

    wcvt_kernel<<<(2*WIN1 + 2*WOUT1 + 255)/256, 256>>>(Win, Wout);
    embed_ln_kernel<<<NT, 128>>>(tokens, emb, ln_w, ln_b);

    for (int l = 0; l < 2; l++) {
        if (l > 0) ln_kernel<<<NT, 128>>>(ln_w + l*DM, ln_b + l*DM, 1);
        gemm_tc<0,1><<<dim3((DIP+GBN-1)/GBN, NT/GBM, 1), 256, smem_bytes>>>(l);
        conv_dtda_kernel<<<(CONV_N + DTDA_N + 255)/256, 256>>>(cw + (size_t)l*CD*4, cb + l*CD,
                                                               dtb + l*NH, alog + l*NH);
        scan_kernel<<<BB*8, 96>>>();
        gate_rms_kernel<<<NT, 256>>>(Dd + l*NH, gnw + l*DI);
        gemm_tc<1,2><<<dim3((DM+GBN-1)/GBN, NT/GBM, 2), 256, smem_bytes>>>(l);
    }

    ln_kernel<<<NT, 128>>>(nfw, nfb, 0);
    pool_ln_kernel<<<BB, 128>>>(plw, plb);
    heads_kernel<<<(NOUT + 255)/256, 256>>>(ow, ob, fw, fb, gw, gb, sw, sb, out);
}

// round 6
// speedup vs baseline: 3.4707x; 1.0379x over previous
#include <cuda_runtime.h>
#include <math.h>
#include <stddef.h>
#include <stdint.h>

typedef unsigned long long ull;

// ---------------- problem constants ----------------
#define BB   32
#define LL   512
#define DM   384
#define DI   768
#define DS   64
#define NH   16
#define HD   48
#define DIP  1680
#define CD   896
#define NT   (BB*LL)
#define NOUT 38667
#define N_ORDER 60
#define N_FAMILY 427
#define N_GENUS 14216
#define N_SPECIES 23964

#define WIN1  (DM*DIP)
#define WOUT1 (DI*DM)

// k-permutation within each 8-group: pos = k<4 ? 2k : 2(k-4)+1
__device__ __forceinline__ int kperm(int k){
    int j = k & 7;
    return (k & ~7) | ((j<4) ? (j<<1) : (((j-4)<<1)|1));
}

// ---------------- scratch ----------------
__device__ float g_resid[(size_t)NT*DM];
__device__ float g_h    [(size_t)NT*DM];     // k-permuted when feeding gemm; plain for final LN
__device__ float g_zx   [(size_t)NT*DIP];
__device__ float g_xBC  [(size_t)NT*CD];
__device__ float g_dt   [(size_t)NT*NH];
__device__ float g_dA   [(size_t)NT*NH];
__device__ float g_ys   [(size_t)NT*DI];
__device__ float g_yn   [(size_t)NT*DI];     // k-permuted
__device__ float g_feat [(size_t)BB*DM];
__device__ float g_wtB  [2*WIN1 + 2*WOUT1];  // weights: transposed [N][K], k-permuted, tf32-rounded

__device__ __forceinline__ uint32_t f2tf(float x){
    uint32_t y;
    asm volatile("cvt.rna.tf32.f32 %0, %1;" : "=r"(y) : "f"(x));
    return y;
}
__device__ __forceinline__ ull pk2(float lo, float hi){
    ull r; asm("mov.b64 %0, {%1, %2};" : "=l"(r) : "f"(lo), "f"(hi)); return r;
}
__device__ __forceinline__ void upk2(float& lo, float& hi, ull v){
    asm("mov.b64 {%0, %1}, %2;" : "=f"(lo), "=f"(hi) : "l"(v));
}
__device__ __forceinline__ void upk2u(uint32_t& lo, uint32_t& hi, ull v){
    asm("mov.b64 {%0, %1}, %2;" : "=r"(lo), "=r"(hi) : "l"(v));
}
#define MUL2(out,a,b)   asm("mul.rn.f32x2 %0,%1,%2;"    : "=l"(out) : "l"(a), "l"(b))
#define FMA2(out,a,b,c) asm("fma.rn.f32x2 %0,%1,%2,%3;" : "=l"(out) : "l"(a), "l"(b), "l"(c))

// ---------------- weight transpose + permute + tf32 convert (tiled, coalesced) ----------------
__global__ __launch_bounds__(256) void wcvt_t_kernel(const float* __restrict__ Win,
                                                     const float* __restrict__ Wout)
{
    int r = blockIdx.z;
    const float* src; float* dst; int K_, N_;
    if (r < 2){ src = Win  + (size_t)r*WIN1;      dst = g_wtB + (size_t)r*WIN1;              K_ = DM; N_ = DIP; }
    else      { src = Wout + (size_t)(r-2)*WOUT1; dst = g_wtB + 2*WIN1 + (size_t)(r-2)*WOUT1; K_ = DI; N_ = DM; }
    int k0 = blockIdx.y*32, n0 = blockIdx.x*32;
    if (k0 >= K_ || n0 >= N_) return;
    __shared__ float sm[32][33];
    int tx = threadIdx.x & 31, ty = threadIdx.x >> 5;   // 32 x 8
    #pragma unroll
    for (int q=0;q<4;q++){
        int k = k0 + ty + q*8;
        if (k < K_ && n0+tx < N_) sm[ty+q*8][tx] = src[(size_t)k*N_ + n0+tx];
    }
    __syncthreads();
    #pragma unroll
    for (int q=0;q<4;q++){
        int n = n0 + ty + q*8;
        int k = k0 + tx;
        if (n < N_ && k < K_)
            dst[(size_t)n*K_ + kperm(k)] = __uint_as_float(f2tf(sm[tx][ty+q*8]));
    }
}

// ---------------- fused embedding gather + layer-0 layernorm (k-permuted output) ----------------
__global__ __launch_bounds__(128) void embed_ln_kernel(const int* __restrict__ tokens,
                                                       const float* __restrict__ emb,
                                                       const float* __restrict__ w,
                                                       const float* __restrict__ b)
{
    __shared__ float red[128];
    int row = blockIdx.x, tid = threadIdx.x;
    const float* er = emb + (size_t)tokens[row]*DM;
    float v0 = er[tid], v1 = er[tid+128], v2 = er[tid+256];
    float* rr = g_resid + (size_t)row*DM;
    rr[tid] = v0; rr[tid+128] = v1; rr[tid+256] = v2;

    red[tid] = v0+v1+v2; __syncthreads();
    for (int s=64;s>0;s>>=1){ if(tid<s) red[tid]+=red[tid+s]; __syncthreads(); }
    float mu = red[0] * (1.0f/DM);
    __syncthreads();
    float d0=v0-mu, d1=v1-mu, d2=v2-mu;
    red[tid] = d0*d0+d1*d1+d2*d2; __syncthreads();
    for (int s=64;s>0;s>>=1){ if(tid<s) red[tid]+=red[tid+s]; __syncthreads(); }
    float inv = rsqrtf(red[0]*(1.0f/DM) + 1e-5f);
    float* o = g_h + (size_t)row*DM;
    o[kperm(tid)]     = __uint_as_float(f2tf(d0*inv*w[tid]     + b[tid]));
    o[kperm(tid+128)] = __uint_as_float(f2tf(d1*inv*w[tid+128] + b[tid+128]));
    o[kperm(tid+256)] = __uint_as_float(f2tf(d2*inv*w[tid+256] + b[tid+256]));
}

// ---------------- layernorm: g_resid -> g_h; tf=1: tf32-round + k-permute ----------------
__global__ __launch_bounds__(128) void ln_kernel(const float* __restrict__ w, const float* __restrict__ b, int tf)
{
    __shared__ float red[128];
    int row = blockIdx.x, tid = threadIdx.x;
    const float* xr = g_resid + (size_t)row*DM;
    float v0 = xr[tid], v1 = xr[tid+128], v2 = xr[tid+256];
    red[tid] = v0+v1+v2; __syncthreads();
    for (int s=64;s>0;s>>=1){ if(tid<s) red[tid]+=red[tid+s]; __syncthreads(); }
    float mu = red[0] * (1.0f/DM);
    __syncthreads();
    float d0=v0-mu, d1=v1-mu, d2=v2-mu;
    red[tid] = d0*d0+d1*d1+d2*d2; __syncthreads();
    for (int s=64;s>0;s>>=1){ if(tid<s) red[tid]+=red[tid+s]; __syncthreads(); }
    float inv = rsqrtf(red[0]*(1.0f/DM) + 1e-5f);
    float o0 = d0*inv*w[tid]     + b[tid];
    float o1 = d1*inv*w[tid+128] + b[tid+128];
    float o2 = d2*inv*w[tid+256] + b[tid+256];
    float* o = g_h + (size_t)row*DM;
    if (tf){
        o[kperm(tid)]     = __uint_as_float(f2tf(o0));
        o[kperm(tid+128)] = __uint_as_float(f2tf(o1));
        o[kperm(tid+256)] = __uint_as_float(f2tf(o2));
    } else {
        o[tid] = o0; o[tid+128] = o1; o[tid+256] = o2;
    }
}

// ---------------- tf32 tensor-core GEMM; paired-k LDS.64 operand feed ----------------
#define GBM 128
#define GBN 128
#define GBK 16
#define NSTAGE 4
#define TSTR 24                         // 16 + 8 pad: conflict-free LDS.64 pattern
#define AS_FLOATS (GBM*TSTR)            // 3072
#define BS_FLOATS (GBN*TSTR)            // 3072
#define SMEM_FLOATS (NSTAGE*(AS_FLOATS+BS_FLOATS))   // 24576 floats = 96 KB

__device__ __forceinline__ void mma_tf32(float* c, const uint32_t* a, const uint32_t* b){
    asm volatile(
      "mma.sync.aligned.m16n8k8.row.col.f32.tf32.tf32.f32 "
      "{%0,%1,%2,%3}, {%4,%5,%6,%7}, {%8,%9}, {%0,%1,%2,%3};\n"
      : "+f"(c[0]), "+f"(c[1]), "+f"(c[2]), "+f"(c[3])
      : "r"(a[0]), "r"(a[1]), "r"(a[2]), "r"(a[3]), "r"(b[0]), "r"(b[1]));
}

// MODE 0: g_zx = g_h @ W  (store).  MODE 1: g_resid += g_yn @ W (atomicAdd, split-K).
template<int MODE, int SPLITK>
__global__ __launch_bounds__(256,2) void gemm_tc(int layer)
{
    const float* __restrict__ A = (MODE==0) ? g_h : g_yn;
    const float* __restrict__ W = (MODE==0) ? (g_wtB + (size_t)layer*WIN1)
                                            : (g_wtB + 2*WIN1 + (size_t)layer*WOUT1);
    float* C = (MODE==0) ? g_zx : g_resid;
    const int N = (MODE==0) ? DIP : DM;
    const int K = (MODE==0) ? DM  : DI;
    const int Ks = K / SPLITK;
    const int k_origin = blockIdx.z * Ks;

    extern __shared__ float sh[];
    float* shB = sh + NSTAGE*AS_FLOATS;

    int tid  = threadIdx.x;
    int warp = tid >> 5;
    int lane = tid & 31;
    int gid  = lane >> 2;
    int tig  = lane & 3;

    int m0 = blockIdx.y * GBM;
    int n0 = blockIdx.x * GBN;
    int wm = (warp & 1) * 64;
    int wn = (warp >> 1) * 32;

    float acc[4][4][4];
    #pragma unroll
    for (int i=0;i<4;i++)
        #pragma unroll
        for (int j=0;j<4;j++)
            #pragma unroll
            for (int q=0;q<4;q++) acc[i][j][q]=0.f;

    const int niter = Ks / GBK;

    // copy mapping: A and B both [row][16 k-floats], 128 rows x 4 chunks = 512 chunks, 2/thread
    int row0 = tid >> 2,        kc0 = (tid & 3) << 2;
    int row1 = (tid+256) >> 2,  kc1 = (tid & 3) << 2;   // row1 = row0 + 64
    int b_ok0 = (n0 + row0 < N) ? 16 : 0;
    int b_ok1 = (n0 + row1 < N) ? 16 : 0;
    const float* asrc0 = A + (size_t)(m0 + row0)*K + k_origin + kc0;
    const float* asrc1 = A + (size_t)(m0 + row1)*K + k_origin + kc1;
    const float* bsrc0 = W + (size_t)((n0 + row0 < N) ? (n0 + row0) : 0)*K + k_origin + kc0;
    const float* bsrc1 = W + (size_t)((n0 + row1 < N) ? (n0 + row1) : 0)*K + k_origin + kc1;

    uint32_t adst0 = (uint32_t)__cvta_generic_to_shared(&sh [row0*TSTR + kc0]);
    uint32_t adst1 = (uint32_t)__cvta_generic_to_shared(&sh [row1*TSTR + kc1]);
    uint32_t bdst0 = (uint32_t)__cvta_generic_to_shared(&shB[row0*TSTR + kc0]);
    uint32_t bdst1 = (uint32_t)__cvta_generic_to_shared(&shB[row1*TSTR + kc1]);

    auto issue_copy = [&](int st, int it){
        int k0 = it * GBK;
        uint32_t ao = st*AS_FLOATS*4, bo = st*BS_FLOATS*4;
        asm volatile("cp.async.cg.shared.global [%0], [%1], 16;\n"
                     :: "r"(adst0 + ao), "l"(asrc0 + k0));
        asm volatile("cp.async.cg.shared.global [%0], [%1], 16;\n"
                     :: "r"(adst1 + ao), "l"(asrc1 + k0));
        asm volatile("cp.async.cg.shared.global [%0], [%1], 16, %2;\n"
                     :: "r"(bdst0 + bo), "l"(bsrc0 + k0), "r"(b_ok0));
        asm volatile("cp.async.cg.shared.global [%0], [%1], 16, %2;\n"
                     :: "r"(bdst1 + bo), "l"(bsrc1 + k0), "r"(b_ok1));
    };

    #pragma unroll
    for (int st=0; st<NSTAGE-1; st++){
        if (st < niter) issue_copy(st, st);
        asm volatile("cp.async.commit_group;\n");
    }

    for (int it=0; it<niter; ++it){
        asm volatile("cp.async.wait_group %0;\n" :: "n"(NSTAGE-2));
        __syncthreads();

        int cb = it & (NSTAGE-1);
        const float* Asb = &sh [cb*AS_FLOATS];
        const float* Bsb = &shB[cb*BS_FLOATS];

        #pragma unroll
        for (int ks=0; ks<GBK; ks+=8){
            uint32_t af[4][4], bf[4][2];
            #pragma unroll
            for (int mi=0; mi<4; mi++){
                int mr = wm + 16*mi;
                ull lo8 = *(const ull*)&Asb[(mr+gid  )*TSTR + ks + 2*tig];
                ull hi8 = *(const ull*)&Asb[(mr+gid+8)*TSTR + ks + 2*tig];
                upk2u(af[mi][0], af[mi][2], lo8);   // (k=tig, k=tig+4) for row gid
                upk2u(af[mi][1], af[mi][3], hi8);   // same for row gid+8
            }
            #pragma unroll
            for (int ni=0; ni<4; ni++){
                int nb = wn + 8*ni;
                ull bb = *(const ull*)&Bsb[(nb+gid)*TSTR + ks + 2*tig];
                upk2u(bf[ni][0], bf[ni][1], bb);
            }
            #pragma unroll
            for (int mi=0; mi<4; mi++)
                #pragma unroll
                for (int ni=0; ni<4; ni++)
                    mma_tf32(acc[mi][ni], af[mi], bf[ni]);
        }

        int nx = it + NSTAGE - 1;
        if (nx < niter) issue_copy(nx & (NSTAGE-1), nx);
        asm volatile("cp.async.commit_group;\n");
    }

    #pragma unroll
    for (int mi=0; mi<4; mi++){
        int r0 = m0 + wm + 16*mi + gid;
        #pragma unroll
        for (int ni=0; ni<4; ni++){
            int c0 = n0 + wn + 8*ni + 2*tig;
            float* a = acc[mi][ni];
            #pragma unroll
            for (int half=0; half<2; half++){
                int cc = c0 + half;
                if (cc < N){
                    size_t i0 = (size_t)r0*N + cc;
                    size_t i2 = (size_t)(r0+8)*N + cc;
                    if (MODE){ atomicAdd(&C[i0], a[half]); atomicAdd(&C[i2], a[2+half]); }
                    else     { C[i0] = a[half]; C[i2] = a[2+half]; }
                }
            }
        }
    }
}

// ---------------- fused: sliding-window causal conv (k=4)+silu AND dt/dA ----------------
// blocks [0,256): conv — block = (b, t-chunk of 64), thread = 4-channel group (224 threads)
// blocks [256, 256+293): dt/dA
#define CONV_BLKS (BB*8)
#define DTDA_TOT  (NT*(NH/4))
#define DTDA_BLKS ((DTDA_TOT + 223)/224)
__global__ __launch_bounds__(224) void conv_dtda_kernel(const float* __restrict__ cw, const float* __restrict__ cb,
                                                        const float* __restrict__ dtb, const float* __restrict__ alog)
{
    int blk = blockIdx.x;
    int tid = threadIdx.x;
    if (blk < CONV_BLKS){
        int b  = blk >> 3;
        int tc = blk & 7;
        int t0 = tc * 64;
        int c  = tid << 2;

        // tap-major weights for 4 channels
        float4 tw[4];
        #pragma unroll
        for (int k=0;k<4;k++){
            tw[k].x = cw[(c+0)*4+k];
            tw[k].y = cw[(c+1)*4+k];
            tw[k].z = cw[(c+2)*4+k];
            tw[k].w = cw[(c+3)*4+k];
        }
        float4 bias = *(const float4*)&cb[c];

        const float* base = g_zx + (size_t)(b*LL + t0)*DIP + DI + c;
        float* obase = g_xBC + (size_t)(b*LL + t0)*CD + c;

        float4 p1, p2, p3;
        if (t0 > 0){
            p1 = *(const float4*)(base - 3*DIP);
            p2 = *(const float4*)(base - 2*DIP);
            p3 = *(const float4*)(base - 1*DIP);
        } else {
            p1 = p2 = p3 = make_float4(0.f,0.f,0.f,0.f);
        }

        #pragma unroll 4
        for (int i=0;i<64;i++){
            float4 v = *(const float4*)(base + (size_t)i*DIP);
            float4 a;
            a.x = bias.x + p1.x*tw[0].x + p2.x*tw[1].x + p3.x*tw[2].x + v.x*tw[3].x;
            a.y = bias.y + p1.y*tw[0].y + p2.y*tw[1].y + p3.y*tw[2].y + v.y*tw[3].y;
            a.z = bias.z + p1.z*tw[0].z + p2.z*tw[1].z + p3.z*tw[2].z + v.z*tw[3].z;
            a.w = bias.w + p1.w*tw[0].w + p2.w*tw[1].w + p3.w*tw[2].w + v.w*tw[3].w;
            float4 r;
            r.x = a.x / (1.f + __expf(-a.x));
            r.y = a.y / (1.f + __expf(-a.y));
            r.z = a.z / (1.f + __expf(-a.z));
            r.w = a.w / (1.f + __expf(-a.w));
            *(float4*)(obase + (size_t)i*CD) = r;
            p1 = p2; p2 = p3; p3 = v;
        }
    } else {
        int j = (blk - CONV_BLKS)*224 + tid;
        if (j >= DTDA_TOT) return;
        int hq = (j & 3) << 2;
        int bt = j >> 2;
        #pragma unroll
        for (int q=0;q<4;q++){
            int hh = hq + q;
            float raw = g_zx[(size_t)bt*DIP + (DIP-NH) + hh] + dtb[hh];
            float sp = (raw > 20.f) ? raw : log1pf(expf(raw));
            g_dt[bt*NH + hh] = sp;
            g_dA[bt*NH + hh] = expf(-expf(alog[hh]) * sp);
        }
    }
}

// ---------------- selective scan: CTA per (b, head-pair); 2 steps per barrier; f32x2 ----------------
__global__ __launch_bounds__(96) void scan_kernel()
{
    int b   = blockIdx.x >> 3;
    int hp  = blockIdx.x & 7;
    int tid = threadIdx.x;
    int hl  = tid / HD;
    int p   = tid - hl*HD;
    int h   = hp*2 + hl;

    __shared__ __align__(16) ull B2[2][2][DS/2];
    __shared__ __align__(16) ull C2[2][2][DS/2];

    ull s[DS/2];
    #pragma unroll
    for (int q=0;q<DS/2;q++) s[q]=0ull;

    const size_t bh_dt = (size_t)(b*LL)*NH + h;
    const size_t bh_x  = (size_t)(b*LL)*CD + h*HD + p;

    {
        const float* r0 = g_xBC + (size_t)(b*LL)*CD;
        const float* r1 = r0 + CD;
        if (tid < 32){
            B2[0][0][tid] = *(const ull*)(r0 + DI + 2*tid);
            B2[0][1][tid] = *(const ull*)(r1 + DI + 2*tid);
        } else if (tid < 64){
            int q = tid-32;
            C2[0][0][q] = *(const ull*)(r0 + DI + DS + 2*q);
            C2[0][1][q] = *(const ull*)(r1 + DI + DS + 2*q);
        }
    }
    float x0  = g_xBC[bh_x],        x1  = g_xBC[bh_x + CD];
    float dt0 = g_dt[bh_dt],        dt1 = g_dt[bh_dt + NH];
    float dA0 = g_dA[bh_dt],        dA1 = g_dA[bh_dt + NH];
    __syncthreads();

    for (int i=0; i<LL/2; i++){
        int t0 = 2*i;
        int set = i & 1;

        ull Bn0=0,Bn1=0,Cn0=0,Cn1=0;
        float xn0=0,xn1=0,dtn0=0,dtn1=0,dAn0=0,dAn1=0;
        if (t0+2 < LL){
            const float* r2 = g_xBC + (size_t)(b*LL + t0+2)*CD;
            const float* r3 = r2 + CD;
            if (tid < 32){
                Bn0 = *(const ull*)(r2 + DI + 2*tid);
                Bn1 = *(const ull*)(r3 + DI + 2*tid);
            } else if (tid < 64){
                int q = tid-32;
                Cn0 = *(const ull*)(r2 + DI + DS + 2*q);
                Cn1 = *(const ull*)(r3 + DI + DS + 2*q);
            }
            xn0  = g_xBC[bh_x  + (size_t)(t0+2)*CD];
            xn1  = g_xBC[bh_x  + (size_t)(t0+3)*CD];
            dtn0 = g_dt[bh_dt + (size_t)(t0+2)*NH];
            dtn1 = g_dt[bh_dt + (size_t)(t0+3)*NH];
            dAn0 = g_dA[bh_dt + (size_t)(t0+2)*NH];
            dAn1 = g_dA[bh_dt + (size_t)(t0+3)*NH];
        }

        {
            float dtx = dt0 * x0;
            ull dA2  = pk2(dA0, dA0);
            ull dtx2 = pk2(dtx, dtx);
            ull ya=0ull, yb=0ull, yc=0ull, yd=0ull;
            const ull* Bp = B2[set][0];
            const ull* Cp = C2[set][0];
            #pragma unroll
            for (int q=0;q<DS/2;q+=4){
                ull u0,u1,u2,u3;
                MUL2(u0, dtx2, Bp[q+0]); FMA2(s[q+0], s[q+0], dA2, u0); FMA2(ya, s[q+0], Cp[q+0], ya);
                MUL2(u1, dtx2, Bp[q+1]); FMA2(s[q+1], s[q+1], dA2, u1); FMA2(yb, s[q+1], Cp[q+1], yb);
                MUL2(u2, dtx2, Bp[q+2]); FMA2(s[q+2], s[q+2], dA2, u2); FMA2(yc, s[q+2], Cp[q+2], yc);
                MUL2(u3, dtx2, Bp[q+3]); FMA2(s[q+3], s[q+3], dA2, u3); FMA2(yd, s[q+3], Cp[q+3], yd);
            }
            float a0,a1,b0,b1,c0,c1,d0,d1;
            upk2(a0,a1,ya); upk2(b0,b1,yb); upk2(c0,c1,yc); upk2(d0,d1,yd);
            g_ys[(size_t)(b*LL+t0)*DI + h*HD + p] = ((a0+a1)+(b0+b1)) + ((c0+c1)+(d0+d1));
        }
        {
            float dtx = dt1 * x1;
            ull dA2  = pk2(dA1, dA1);
            ull dtx2 = pk2(dtx, dtx);
            ull ya=0ull, yb=0ull, yc=0ull, yd=0ull;
            const ull* Bp = B2[set][1];
            const ull* Cp = C2[set][1];
            #pragma unroll
            for (int q=0;q<DS/2;q+=4){
                ull u0,u1,u2,u3;
                MUL2(u0, dtx2, Bp[q+0]); FMA2(s[q+0], s[q+0], dA2, u0); FMA2(ya, s[q+0], Cp[q+0], ya);
                MUL2(u1, dtx2, Bp[q+1]); FMA2(s[q+1], s[q+1], dA2, u1); FMA2(yb, s[q+1], Cp[q+1], yb);
                MUL2(u2, dtx2, Bp[q+2]); FMA2(s[q+2], s[q+2], dA2, u2); FMA2(yc, s[q+2], Cp[q+2], yc);
                MUL2(u3, dtx2, Bp[q+3]); FMA2(s[q+3], s[q+3], dA2, u3); FMA2(yd, s[q+3], Cp[q+3], yd);
            }
            float a0,a1,b0,b1,c0,c1,d0,d1;
            upk2(a0,a1,ya); upk2(b0,b1,yb); upk2(c0,c1,yc); upk2(d0,d1,yd);
            g_ys[(size_t)(b*LL+t0+1)*DI + h*HD + p] = ((a0+a1)+(b0+b1)) + ((c0+c1)+(d0+d1));
        }

        if (t0+2 < LL){
            if (tid < 32){
                B2[set^1][0][tid] = Bn0;
                B2[set^1][1][tid] = Bn1;
            } else if (tid < 64){
                int q = tid-32;
                C2[set^1][0][q] = Cn0;
                C2[set^1][1][q] = Cn1;
            }
        }
        x0=xn0; x1=xn1; dt0=dtn0; dt1=dtn1; dA0=dAn0; dA1=dAn1;
        __syncthreads();
    }
}

// ---------------- y = (ys + D*x) * silu(z); RMS-norm -> g_yn (tf32, k-permuted) ----------------
__global__ __launch_bounds__(256) void gate_rms_kernel(const float* __restrict__ Dp,
                                                       const float* __restrict__ gnorm)
{
    __shared__ float red[256];
    int row = blockIdx.x, tid = threadIdx.x;
    float v[3]; float ss = 0.f;
    #pragma unroll
    for (int q=0;q<3;q++){
        int i = tid + q*256;
        float ys = g_ys[(size_t)row*DI + i];
        float xv = g_xBC[(size_t)row*CD + i];
        float z  = g_zx [(size_t)row*DIP + i];
        float val = (ys + Dp[i/HD]*xv) * (z / (1.f + __expf(-z)));
        v[q] = val; ss += val*val;
    }
    red[tid] = ss; __syncthreads();
    for (int s=128;s>0;s>>=1){ if(tid<s) red[tid]+=red[tid+s]; __syncthreads(); }
    float scale = rsqrtf(red[0]*(1.0f/DI) + 1e-5f);
    #pragma unroll
    for (int q=0;q<3;q++){
        int i = tid + q*256;
        g_yn[(size_t)row*DI + kperm(i)] = __uint_as_float(f2tf(v[q]*scale*gnorm[i]));
    }
}

// ---------------- mean over t + layernorm -> g_feat ----------------
__global__ __launch_bounds__(128) void pool_ln_kernel(const float* __restrict__ w,
                                                      const float* __restrict__ b)
{
    __shared__ float red[128];
    int bb = blockIdx.x, tid = threadIdx.x;
    float v[3];
    #pragma unroll
    for (int q=0;q<3;q++){
        int d = tid + q*128;
        const float* p = g_h + (size_t)bb*LL*DM + d;
        float s = 0.f;
        for (int t=0;t<LL;t++) s += p[(size_t)t*DM];
        v[q] = s * (1.0f/LL);
    }
    red[tid] = v[0]+v[1]+v[2]; __syncthreads();
    for (int s=64;s>0;s>>=1){ if(tid<s) red[tid]+=red[tid+s]; __syncthreads(); }
    float mu = red[0]*(1.0f/DM);
    __syncthreads();
    float d0=v[0]-mu, d1=v[1]-mu, d2=v[2]-mu;
    red[tid] = d0*d0+d1*d1+d2*d2; __syncthreads();
    for (int s=64;s>0;s>>=1){ if(tid<s) red[tid]+=red[tid+s]; __syncthreads(); }
    float inv = rsqrtf(red[0]*(1.0f/DM) + 1e-5f);
    g_feat[bb*DM+tid]     = d0*inv*w[tid]     + b[tid];
    g_feat[bb*DM+tid+128] = d1*inv*w[tid+128] + b[tid+128];
    g_feat[bb*DM+tid+256] = d2*inv*w[tid+256] + b[tid+256];
}

// ---------------- classification heads ----------------
__global__ __launch_bounds__(256) void heads_kernel(
    const float* __restrict__ ow, const float* __restrict__ ob,
    const float* __restrict__ fw, const float* __restrict__ fb,
    const float* __restrict__ gw, const float* __restrict__ gb,
    const float* __restrict__ sw, const float* __restrict__ sb,
    float* __restrict__ out)
{
    __shared__ float sf[BB*DM];
    int tid = threadIdx.x;
    for (int i = tid; i < BB*DM; i += blockDim.x) sf[i] = g_feat[i];
    __syncthreads();

    int j = blockIdx.x * blockDim.x + tid;
    if (j >= NOUT) return;

    const float* W; const float* Bv; int jj, Nseg;
    if (j < N_ORDER)                      { W=ow; Bv=ob; jj=j;                     Nseg=N_ORDER; }
    else if (j < N_ORDER+N_FAMILY)        { W=fw; Bv=fb; jj=j-N_ORDER;             Nseg=N_FAMILY; }
    else if (j < N_ORDER+N_FAMILY+N_GENUS){ W=gw; Bv=gb; jj=j-N_ORDER-N_FAMILY;    Nseg=N_GENUS; }
    else                                  { W=sw; Bv=sb; jj=j-N_ORDER-N_FAMILY-N_GENUS; Nseg=N_SPECIES; }

    float acc[BB];
    #pragma unroll
    for (int b=0;b<BB;b++) acc[b]=0.f;
    for (int k=0;k<DM;k++){
        float wv = W[(size_t)k*Nseg + jj];
        #pragma unroll
        for (int b=0;b<BB;b++) acc[b] = fmaf(sf[b*DM + k], wv, acc[b]);
    }
    float bias = Bv[jj];
    #pragma unroll
    for (int b=0;b<BB;b++) out[(size_t)b*NOUT + j] = acc[b] + bias;
}

// ---------------- orchestration ----------------
extern "C" void kernel_launch(void* const* d_in, const int* in_sizes, int n_in,
                              void* d_out, int out_size)
{
    const int*   tokens = (const int*)  d_in[0];
    const float* emb    = (const float*)d_in[1];
    const float* ln_w   = (const float*)d_in[2];
    const float* ln_b   = (const float*)d_in[3];
    const float* Win    = (const float*)d_in[4];
    const float* cw     = (const float*)d_in[5];
    const float* cb     = (const float*)d_in[6];
    const float* dtb    = (const float*)d_in[7];
    const float* alog   = (const float*)d_in[8];
    const float* Dd     = (const float*)d_in[9];
    const float* gnw    = (const float*)d_in[10];
    const float* Wout   = (const float*)d_in[11];
    const float* nfw    = (const float*)d_in[12];
    const float* nfb    = (const float*)d_in[13];
    const float* plw    = (const float*)d_in[14];
    const float* plb    = (const float*)d_in[15];
    const float* ow     = (const float*)d_in[16];
    const float* ob     = (const float*)d_in[17];
    const float* fw     = (const float*)d_in[18];
    const float* fb     = (const float*)d_in[19];
    const float* gw     = (const float*)d_in[20];
    const float* gb     = (const float*)d_in[21];
    const float* sw     = (const float*)d_in[22];
    const float* sb     = (const float*)d_in[23];
    float* out = (float*)d_out;

    const int smem_bytes = SMEM_FLOATS * 4;
    cudaFuncSetAttribute((const void*)gemm_tc<0,1>, cudaFuncAttributeMaxDynamicSharedMemorySize, smem_bytes);
    cudaFuncSetAttribute((const void*)gemm_tc<1,2>, cudaFuncAttributeMaxDynamicSharedMemorySize, smem_bytes);

    wcvt_t_kernel<<<dim3((DIP+31)/32, (DI+31)/32, 4), 256>>>(Win, Wout);
    embed_ln_kernel<<<NT, 128>>>(tokens, emb, ln_w, ln_b);

    for (int l = 0; l < 2; l++) {
        if (l > 0) ln_kernel<<<NT, 128>>>(ln_w + l*DM, ln_b + l*DM, 1);
        gemm_tc<0,1><<<dim3((DIP+GBN-1)/GBN, NT/GBM, 1), 256, smem_bytes>>>(l);
        conv_dtda_kernel<<<CONV_BLKS + DTDA_BLKS, 224>>>(cw + (size_t)l*CD*4, cb + l*CD,
                                                         dtb + l*NH, alog + l*NH);
        scan_kernel<<<BB*8, 96>>>();
        gate_rms_kernel<<<NT, 256>>>(Dd + l*NH, gnw + l*DI);
        gemm_tc<1,2><<<dim3((DM+GBN-1)/GBN, NT/GBM, 2), 256, smem_bytes>>>(l);
    }

    ln_kernel<<<NT, 128>>>(nfw, nfb, 0);
    pool_ln_kernel<<<BB, 128>>>(plw, plb);
    heads_kernel<<<(NOUT + 255)/256, 256>>>(ow, ob, fw, fb, gw, gb, sw, sb, out);
}

// round 7
// speedup vs baseline: 3.6164x; 1.0420x over previous
#include <cuda_runtime.h>
#include <math.h>
#include <stddef.h>
#include <stdint.h>

typedef unsigned long long ull;

// ---------------- problem constants ----------------
#define BB   32
#define LL   512
#define DM   384
#define DI   768
#define DS   64
#define NH   16
#define HD   48
#define DIP  1680
#define CD   896
#define NT   (BB*LL)
#define NOUT 38667
#define N_ORDER 60
#define N_FAMILY 427
#define N_GENUS 14216
#define N_SPECIES 23964

#define WIN1  (DM*DIP)
#define WOUT1 (DI*DM)

#define NCHUNK 8
#define CLEN   64            // LL / NCHUNK
#define STATE_PAIRS 1536     // HD*DS/2 per (b,h,chunk)

// k-permutation within each 8-group: pos = k<4 ? 2k : 2(k-4)+1
__device__ __forceinline__ int kperm(int k){
    int j = k & 7;
    return (k & ~7) | ((j<4) ? (j<<1) : (((j-4)<<1)|1));
}

// ---------------- scratch ----------------
__device__ float g_resid[(size_t)NT*DM];
__device__ float g_h    [(size_t)NT*DM];
__device__ float g_zx   [(size_t)NT*DIP];
__device__ float g_xBC  [(size_t)NT*CD];
__device__ float g_dt   [(size_t)NT*NH];
__device__ float g_dA   [(size_t)NT*NH];
__device__ float g_ys   [(size_t)NT*DI];
__device__ float g_yn   [(size_t)NT*DI];
__device__ float g_wtB  [2*WIN1 + 2*WOUT1];
__device__ ull   g_state_u[(size_t)BB*NH*NCHUNK*STATE_PAIRS];
__device__ ull   g_sin_u  [(size_t)BB*NH*NCHUNK*STATE_PAIRS];
__device__ float g_cda  [(size_t)NT*NH];
__device__ float g_pool [BB*16*DM];
__device__ float g_featT[DM*BB];

__device__ __forceinline__ uint32_t f2tf(float x){
    uint32_t y;
    asm volatile("cvt.rna.tf32.f32 %0, %1;" : "=r"(y) : "f"(x));
    return y;
}
__device__ __forceinline__ ull pk2(float lo, float hi){
    ull r; asm("mov.b64 %0, {%1, %2};" : "=l"(r) : "f"(lo), "f"(hi)); return r;
}
__device__ __forceinline__ void upk2(float& lo, float& hi, ull v){
    asm("mov.b64 {%0, %1}, %2;" : "=f"(lo), "=f"(hi) : "l"(v));
}
__device__ __forceinline__ void upk2u(uint32_t& lo, uint32_t& hi, ull v){
    asm("mov.b64 {%0, %1}, %2;" : "=r"(lo), "=r"(hi) : "l"(v));
}
#define MUL2(out,a,b)   asm("mul.rn.f32x2 %0,%1,%2;"    : "=l"(out) : "l"(a), "l"(b))
#define FMA2(out,a,b,c) asm("fma.rn.f32x2 %0,%1,%2,%3;" : "=l"(out) : "l"(a), "l"(b), "l"(c))

// ---------------- weight transpose + permute + tf32 convert ----------------
__global__ __launch_bounds__(256) void wcvt_t_kernel(const float* __restrict__ Win,
                                                     const float* __restrict__ Wout)
{
    int r = blockIdx.z;
    const float* src; float* dst; int K_, N_;
    if (r < 2){ src = Win  + (size_t)r*WIN1;      dst = g_wtB + (size_t)r*WIN1;              K_ = DM; N_ = DIP; }
    else      { src = Wout + (size_t)(r-2)*WOUT1; dst = g_wtB + 2*WIN1 + (size_t)(r-2)*WOUT1; K_ = DI; N_ = DM; }
    int k0 = blockIdx.y*32, n0 = blockIdx.x*32;
    if (k0 >= K_ || n0 >= N_) return;
    __shared__ float sm[32][33];
    int tx = threadIdx.x & 31, ty = threadIdx.x >> 5;
    #pragma unroll
    for (int q=0;q<4;q++){
        int k = k0 + ty + q*8;
        if (k < K_ && n0+tx < N_) sm[ty+q*8][tx] = src[(size_t)k*N_ + n0+tx];
    }
    __syncthreads();
    #pragma unroll
    for (int q=0;q<4;q++){
        int n = n0 + ty + q*8;
        int k = k0 + tx;
        if (n < N_ && k < K_)
            dst[(size_t)n*K_ + kperm(k)] = __uint_as_float(f2tf(sm[tx][ty+q*8]));
    }
}

// ---------------- fused embedding + layer-0 layernorm (k-permuted) ----------------
__global__ __launch_bounds__(128) void embed_ln_kernel(const int* __restrict__ tokens,
                                                       const float* __restrict__ emb,
                                                       const float* __restrict__ w,
                                                       const float* __restrict__ b)
{
    __shared__ float red[128];
    int row = blockIdx.x, tid = threadIdx.x;
    const float* er = emb + (size_t)tokens[row]*DM;
    float v0 = er[tid], v1 = er[tid+128], v2 = er[tid+256];
    float* rr = g_resid + (size_t)row*DM;
    rr[tid] = v0; rr[tid+128] = v1; rr[tid+256] = v2;

    red[tid] = v0+v1+v2; __syncthreads();
    for (int s=64;s>0;s>>=1){ if(tid<s) red[tid]+=red[tid+s]; __syncthreads(); }
    float mu = red[0] * (1.0f/DM);
    __syncthreads();
    float d0=v0-mu, d1=v1-mu, d2=v2-mu;
    red[tid] = d0*d0+d1*d1+d2*d2; __syncthreads();
    for (int s=64;s>0;s>>=1){ if(tid<s) red[tid]+=red[tid+s]; __syncthreads(); }
    float inv = rsqrtf(red[0]*(1.0f/DM) + 1e-5f);
    float* o = g_h + (size_t)row*DM;
    o[kperm(tid)]     = __uint_as_float(f2tf(d0*inv*w[tid]     + b[tid]));
    o[kperm(tid+128)] = __uint_as_float(f2tf(d1*inv*w[tid+128] + b[tid+128]));
    o[kperm(tid+256)] = __uint_as_float(f2tf(d2*inv*w[tid+256] + b[tid+256]));
}

// ---------------- layernorm: g_resid -> g_h ----------------
__global__ __launch_bounds__(128) void ln_kernel(const float* __restrict__ w, const float* __restrict__ b, int tf)
{
    __shared__ float red[128];
    int row = blockIdx.x, tid = threadIdx.x;
    const float* xr = g_resid + (size_t)row*DM;
    float v0 = xr[tid], v1 = xr[tid+128], v2 = xr[tid+256];
    red[tid] = v0+v1+v2; __syncthreads();
    for (int s=64;s>0;s>>=1){ if(tid<s) red[tid]+=red[tid+s]; __syncthreads(); }
    float mu = red[0] * (1.0f/DM);
    __syncthreads();
    float d0=v0-mu, d1=v1-mu, d2=v2-mu;
    red[tid] = d0*d0+d1*d1+d2*d2; __syncthreads();
    for (int s=64;s>0;s>>=1){ if(tid<s) red[tid]+=red[tid+s]; __syncthreads(); }
    float inv = rsqrtf(red[0]*(1.0f/DM) + 1e-5f);
    float o0 = d0*inv*w[tid]     + b[tid];
    float o1 = d1*inv*w[tid+128] + b[tid+128];
    float o2 = d2*inv*w[tid+256] + b[tid+256];
    float* o = g_h + (size_t)row*DM;
    if (tf){
        o[kperm(tid)]     = __uint_as_float(f2tf(o0));
        o[kperm(tid+128)] = __uint_as_float(f2tf(o1));
        o[kperm(tid+256)] = __uint_as_float(f2tf(o2));
    } else {
        o[tid] = o0; o[tid+128] = o1; o[tid+256] = o2;
    }
}

// ---------------- tf32 tensor-core GEMM (unchanged from R6) ----------------
#define GBM 128
#define GBN 128
#define GBK 16
#define NSTAGE 4
#define TSTR 24
#define AS_FLOATS (GBM*TSTR)
#define BS_FLOATS (GBN*TSTR)
#define SMEM_FLOATS (NSTAGE*(AS_FLOATS+BS_FLOATS))

__device__ __forceinline__ void mma_tf32(float* c, const uint32_t* a, const uint32_t* b){
    asm volatile(
      "mma.sync.aligned.m16n8k8.row.col.f32.tf32.tf32.f32 "
      "{%0,%1,%2,%3}, {%4,%5,%6,%7}, {%8,%9}, {%0,%1,%2,%3};\n"
      : "+f"(c[0]), "+f"(c[1]), "+f"(c[2]), "+f"(c[3])
      : "r"(a[0]), "r"(a[1]), "r"(a[2]), "r"(a[3]), "r"(b[0]), "r"(b[1]));
}

template<int MODE, int SPLITK>
__global__ __launch_bounds__(256,2) void gemm_tc(int layer)
{
    const float* __restrict__ A = (MODE==0) ? g_h : g_yn;
    const float* __restrict__ W = (MODE==0) ? (g_wtB + (size_t)layer*WIN1)
                                            : (g_wtB + 2*WIN1 + (size_t)layer*WOUT1);
    float* C = (MODE==0) ? g_zx : g_resid;
    const int N = (MODE==0) ? DIP : DM;
    const int K = (MODE==0) ? DM  : DI;
    const int Ks = K / SPLITK;
    const int k_origin = blockIdx.z * Ks;

    extern __shared__ float sh[];
    float* shB = sh + NSTAGE*AS_FLOATS;

    int tid  = threadIdx.x;
    int warp = tid >> 5;
    int lane = tid & 31;
    int gid  = lane >> 2;
    int tig  = lane & 3;

    int m0 = blockIdx.y * GBM;
    int n0 = blockIdx.x * GBN;
    int wm = (warp & 1) * 64;
    int wn = (warp >> 1) * 32;

    float acc[4][4][4];
    #pragma unroll
    for (int i=0;i<4;i++)
        #pragma unroll
        for (int j=0;j<4;j++)
            #pragma unroll
            for (int q=0;q<4;q++) acc[i][j][q]=0.f;

    const int niter = Ks / GBK;

    int row0 = tid >> 2,        kc0 = (tid & 3) << 2;
    int row1 = (tid+256) >> 2,  kc1 = (tid & 3) << 2;
    int b_ok0 = (n0 + row0 < N) ? 16 : 0;
    int b_ok1 = (n0 + row1 < N) ? 16 : 0;
    const float* asrc0 = A + (size_t)(m0 + row0)*K + k_origin + kc0;
    const float* asrc1 = A + (size_t)(m0 + row1)*K + k_origin + kc1;
    const float* bsrc0 = W + (size_t)((n0 + row0 < N) ? (n0 + row0) : 0)*K + k_origin + kc0;
    const float* bsrc1 = W + (size_t)((n0 + row1 < N) ? (n0 + row1) : 0)*K + k_origin + kc1;

    uint32_t adst0 = (uint32_t)__cvta_generic_to_shared(&sh [row0*TSTR + kc0]);
    uint32_t adst1 = (uint32_t)__cvta_generic_to_shared(&sh [row1*TSTR + kc1]);
    uint32_t bdst0 = (uint32_t)__cvta_generic_to_shared(&shB[row0*TSTR + kc0]);
    uint32_t bdst1 = (uint32_t)__cvta_generic_to_shared(&shB[row1*TSTR + kc1]);

    auto issue_copy = [&](int st, int it){
        int k0 = it * GBK;
        uint32_t ao = st*AS_FLOATS*4, bo = st*BS_FLOATS*4;
        asm volatile("cp.async.cg.shared.global [%0], [%1], 16;\n"
                     :: "r"(adst0 + ao), "l"(asrc0 + k0));
        asm volatile("cp.async.cg.shared.global [%0], [%1], 16;\n"
                     :: "r"(adst1 + ao), "l"(asrc1 + k0));
        asm volatile("cp.async.cg.shared.global [%0], [%1], 16, %2;\n"
                     :: "r"(bdst0 + bo), "l"(bsrc0 + k0), "r"(b_ok0));
        asm volatile("cp.async.cg.shared.global [%0], [%1], 16, %2;\n"
                     :: "r"(bdst1 + bo), "l"(bsrc1 + k0), "r"(b_ok1));
    };

    #pragma unroll
    for (int st=0; st<NSTAGE-1; st++){
        if (st < niter) issue_copy(st, st);
        asm volatile("cp.async.commit_group;\n");
    }

    for (int it=0; it<niter; ++it){
        asm volatile("cp.async.wait_group %0;\n" :: "n"(NSTAGE-2));
        __syncthreads();

        int cb = it & (NSTAGE-1);
        const float* Asb = &sh [cb*AS_FLOATS];
        const float* Bsb = &shB[cb*BS_FLOATS];

        #pragma unroll
        for (int ks=0; ks<GBK; ks+=8){
            uint32_t af[4][4], bf[4][2];
            #pragma unroll
            for (int mi=0; mi<4; mi++){
                int mr = wm + 16*mi;
                ull lo8 = *(const ull*)&Asb[(mr+gid  )*TSTR + ks + 2*tig];
                ull hi8 = *(const ull*)&Asb[(mr+gid+8)*TSTR + ks + 2*tig];
                upk2u(af[mi][0], af[mi][2], lo8);
                upk2u(af[mi][1], af[mi][3], hi8);
            }
            #pragma unroll
            for (int ni=0; ni<4; ni++){
                int nb = wn + 8*ni;
                ull bb = *(const ull*)&Bsb[(nb+gid)*TSTR + ks + 2*tig];
                upk2u(bf[ni][0], bf[ni][1], bb);
            }
            #pragma unroll
            for (int mi=0; mi<4; mi++)
                #pragma unroll
                for (int ni=0; ni<4; ni++)
                    mma_tf32(acc[mi][ni], af[mi], bf[ni]);
        }

        int nx = it + NSTAGE - 1;
        if (nx < niter) issue_copy(nx & (NSTAGE-1), nx);
        asm volatile("cp.async.commit_group;\n");
    }

    #pragma unroll
    for (int mi=0; mi<4; mi++){
        int r0 = m0 + wm + 16*mi + gid;
        #pragma unroll
        for (int ni=0; ni<4; ni++){
            int c0 = n0 + wn + 8*ni + 2*tig;
            float* a = acc[mi][ni];
            #pragma unroll
            for (int half=0; half<2; half++){
                int cc = c0 + half;
                if (cc < N){
                    size_t i0 = (size_t)r0*N + cc;
                    size_t i2 = (size_t)(r0+8)*N + cc;
                    if (MODE){ atomicAdd(&C[i0], a[half]); atomicAdd(&C[i2], a[2+half]); }
                    else     { C[i0] = a[half]; C[i2] = a[2+half]; }
                }
            }
        }
    }
}

// ---------------- fused conv (16-step chunks) + dt/dA ----------------
#define CONV_BLKS (BB*32)
#define DTDA_TOT  (NT*(NH/4))
#define DTDA_BLKS ((DTDA_TOT + 223)/224)
__global__ __launch_bounds__(224) void conv_dtda_kernel(const float* __restrict__ cw, const float* __restrict__ cb,
                                                        const float* __restrict__ dtb, const float* __restrict__ alog)
{
    int blk = blockIdx.x;
    int tid = threadIdx.x;
    if (blk < CONV_BLKS){
        int b  = blk >> 5;
        int tc = blk & 31;
        int t0 = tc * 16;
        int c  = tid << 2;

        float4 tw[4];
        #pragma unroll
        for (int k=0;k<4;k++){
            tw[k].x = cw[(c+0)*4+k];
            tw[k].y = cw[(c+1)*4+k];
            tw[k].z = cw[(c+2)*4+k];
            tw[k].w = cw[(c+3)*4+k];
        }
        float4 bias = *(const float4*)&cb[c];

        const float* base = g_zx + (size_t)(b*LL + t0)*DIP + DI + c;
        float* obase = g_xBC + (size_t)(b*LL + t0)*CD + c;

        float4 p1, p2, p3;
        if (t0 > 0){
            p1 = *(const float4*)(base - 3*DIP);
            p2 = *(const float4*)(base - 2*DIP);
            p3 = *(const float4*)(base - 1*DIP);
        } else {
            p1 = p2 = p3 = make_float4(0.f,0.f,0.f,0.f);
        }

        #pragma unroll
        for (int i=0;i<16;i++){
            float4 v = *(const float4*)(base + (size_t)i*DIP);
            float4 a;
            a.x = bias.x + p1.x*tw[0].x + p2.x*tw[1].x + p3.x*tw[2].x + v.x*tw[3].x;
            a.y = bias.y + p1.y*tw[0].y + p2.y*tw[1].y + p3.y*tw[2].y + v.y*tw[3].y;
            a.z = bias.z + p1.z*tw[0].z + p2.z*tw[1].z + p3.z*tw[2].z + v.z*tw[3].z;
            a.w = bias.w + p1.w*tw[0].w + p2.w*tw[1].w + p3.w*tw[2].w + v.w*tw[3].w;
            float4 r;
            r.x = a.x / (1.f + __expf(-a.x));
            r.y = a.y / (1.f + __expf(-a.y));
            r.z = a.z / (1.f + __expf(-a.z));
            r.w = a.w / (1.f + __expf(-a.w));
            *(float4*)(obase + (size_t)i*CD) = r;
            p1 = p2; p2 = p3; p3 = v;
        }
    } else {
        int j = (blk - CONV_BLKS)*224 + tid;
        if (j >= DTDA_TOT) return;
        int hq = (j & 3) << 2;
        int bt = j >> 2;
        #pragma unroll
        for (int q=0;q<4;q++){
            int hh = hq + q;
            float raw = g_zx[(size_t)bt*DIP + (DIP-NH) + hh] + dtb[hh];
            float sp = (raw > 20.f) ? raw : log1pf(expf(raw));
            g_dt[bt*NH + hh] = sp;
            g_dA[bt*NH + hh] = expf(-expf(alog[hh]) * sp);
        }
    }
}

// ---------------- chunked scan pass A: local scan per (b, head-pair, chunk) ----------------
__global__ __launch_bounds__(96) void scan_local_kernel()
{
    int blk = blockIdx.x;              // 256*NCHUNK
    int c   = blk & (NCHUNK-1);
    int bp  = blk >> 3;
    int b   = bp >> 3;
    int hp  = bp & 7;
    int tid = threadIdx.x;
    int hl  = tid / HD;
    int p   = tid - hl*HD;
    int h   = hp*2 + hl;
    int tbase = c*CLEN;

    __shared__ __align__(16) ull B2[2][2][DS/2];
    __shared__ __align__(16) ull C2[2][2][DS/2];

    ull s[DS/2];
    #pragma unroll
    for (int q=0;q<DS/2;q++) s[q]=0ull;
    float cum = 1.f;

    const size_t bh_dt = (size_t)(b*LL + tbase)*NH + h;
    const size_t bh_x  = (size_t)(b*LL + tbase)*CD + h*HD + p;

    {
        const float* r0 = g_xBC + (size_t)(b*LL + tbase)*CD;
        const float* r1 = r0 + CD;
        if (tid < 32){
            B2[0][0][tid] = *(const ull*)(r0 + DI + 2*tid);
            B2[0][1][tid] = *(const ull*)(r1 + DI + 2*tid);
        } else if (tid < 64){
            int q = tid-32;
            C2[0][0][q] = *(const ull*)(r0 + DI + DS + 2*q);
            C2[0][1][q] = *(const ull*)(r1 + DI + DS + 2*q);
        }
    }
    float x0  = g_xBC[bh_x],  x1  = g_xBC[bh_x + CD];
    float dt0 = g_dt[bh_dt],  dt1 = g_dt[bh_dt + NH];
    float dA0 = g_dA[bh_dt],  dA1 = g_dA[bh_dt + NH];
    __syncthreads();

    for (int i=0; i<CLEN/2; i++){
        int tr = 2*i;
        int t0 = tbase + tr;
        int set = i & 1;

        ull Bn0=0,Bn1=0,Cn0=0,Cn1=0;
        float xn0=0,xn1=0,dtn0=0,dtn1=0,dAn0=0,dAn1=0;
        if (tr+2 < CLEN){
            const float* r2 = g_xBC + (size_t)(b*LL + t0+2)*CD;
            const float* r3 = r2 + CD;
            if (tid < 32){
                Bn0 = *(const ull*)(r2 + DI + 2*tid);
                Bn1 = *(const ull*)(r3 + DI + 2*tid);
            } else if (tid < 64){
                int q = tid-32;
                Cn0 = *(const ull*)(r2 + DI + DS + 2*q);
                Cn1 = *(const ull*)(r3 + DI + DS + 2*q);
            }
            xn0  = g_xBC[bh_x  + (size_t)(tr+2)*CD];
            xn1  = g_xBC[bh_x  + (size_t)(tr+3)*CD];
            dtn0 = g_dt[bh_dt + (size_t)(tr+2)*NH];
            dtn1 = g_dt[bh_dt + (size_t)(tr+3)*NH];
            dAn0 = g_dA[bh_dt + (size_t)(tr+2)*NH];
            dAn1 = g_dA[bh_dt + (size_t)(tr+3)*NH];
        }

        {
            float dtx = dt0 * x0;
            ull dA2  = pk2(dA0, dA0);
            ull dtx2 = pk2(dtx, dtx);
            ull ya=0ull, yb=0ull, yc=0ull, yd=0ull;
            const ull* Bp = B2[set][0];
            const ull* Cp = C2[set][0];
            #pragma unroll
            for (int q=0;q<DS/2;q+=4){
                ull u0,u1,u2,u3;
                MUL2(u0, dtx2, Bp[q+0]); FMA2(s[q+0], s[q+0], dA2, u0); FMA2(ya, s[q+0], Cp[q+0], ya);
                MUL2(u1, dtx2, Bp[q+1]); FMA2(s[q+1], s[q+1], dA2, u1); FMA2(yb, s[q+1], Cp[q+1], yb);
                MUL2(u2, dtx2, Bp[q+2]); FMA2(s[q+2], s[q+2], dA2, u2); FMA2(yc, s[q+2], Cp[q+2], yc);
                MUL2(u3, dtx2, Bp[q+3]); FMA2(s[q+3], s[q+3], dA2, u3); FMA2(yd, s[q+3], Cp[q+3], yd);
            }
            float a0,a1,b0,b1,c0,c1,d0,d1;
            upk2(a0,a1,ya); upk2(b0,b1,yb); upk2(c0,c1,yc); upk2(d0,d1,yd);
            g_ys[(size_t)(b*LL+t0)*DI + h*HD + p] = ((a0+a1)+(b0+b1)) + ((c0+c1)+(d0+d1));
            cum *= dA0;
            if (p == 0) g_cda[(size_t)(b*LL+t0)*NH + h] = cum;
        }
        {
            float dtx = dt1 * x1;
            ull dA2  = pk2(dA1, dA1);
            ull dtx2 = pk2(dtx, dtx);
            ull ya=0ull, yb=0ull, yc=0ull, yd=0ull;
            const ull* Bp = B2[set][1];
            const ull* Cp = C2[set][1];
            #pragma unroll
            for (int q=0;q<DS/2;q+=4){
                ull u0,u1,u2,u3;
                MUL2(u0, dtx2, Bp[q+0]); FMA2(s[q+0], s[q+0], dA2, u0); FMA2(ya, s[q+0], Cp[q+0], ya);
                MUL2(u1, dtx2, Bp[q+1]); FMA2(s[q+1], s[q+1], dA2, u1); FMA2(yb, s[q+1], Cp[q+1], yb);
                MUL2(u2, dtx2, Bp[q+2]); FMA2(s[q+2], s[q+2], dA2, u2); FMA2(yc, s[q+2], Cp[q+2], yc);
                MUL2(u3, dtx2, Bp[q+3]); FMA2(s[q+3], s[q+3], dA2, u3); FMA2(yd, s[q+3], Cp[q+3], yd);
            }
            float a0,a1,b0,b1,c0,c1,d0,d1;
            upk2(a0,a1,ya); upk2(b0,b1,yb); upk2(c0,c1,yc); upk2(d0,d1,yd);
            g_ys[(size_t)(b*LL+t0+1)*DI + h*HD + p] = ((a0+a1)+(b0+b1)) + ((c0+c1)+(d0+d1));
            cum *= dA1;
            if (p == 0) g_cda[(size_t)(b*LL+t0+1)*NH + h] = cum;
        }

        if (tr+2 < CLEN){
            if (tid < 32){
                B2[set^1][0][tid] = Bn0;
                B2[set^1][1][tid] = Bn1;
            } else if (tid < 64){
                int q = tid-32;
                C2[set^1][0][q] = Cn0;
                C2[set^1][1][q] = Cn1;
            }
        }
        x0=xn0; x1=xn1; dt0=dtn0; dt1=dtn1; dA0=dAn0; dA1=dAn1;
        __syncthreads();
    }

    size_t sbase = ((size_t)(b*NH+h)*NCHUNK + c)*STATE_PAIRS;
    #pragma unroll
    for (int q=0;q<DS/2;q++) g_state_u[sbase + q*HD + p] = s[q];
}

// ---------------- chunked scan pass B: sequential chunk-state combine ----------------
__global__ __launch_bounds__(128) void scan_combine_kernel()
{
    int bh  = blockIdx.x;       // BB*NH
    int b   = bh >> 4;
    int h   = bh & 15;
    int tid = threadIdx.x;
    size_t base = (size_t)bh*NCHUNK*STATE_PAIRS;

    ull sin[STATE_PAIRS/128];
    #pragma unroll
    for (int j=0;j<STATE_PAIRS/128;j++) sin[j]=0ull;

    for (int c=0;c<NCHUNK-1;c++){
        float P = g_cda[(size_t)(b*LL + c*CLEN + CLEN-1)*NH + h];
        ull P2 = pk2(P,P);
        #pragma unroll
        for (int j=0;j<STATE_PAIRS/128;j++){
            ull S = g_state_u[base + (size_t)c*STATE_PAIRS + tid*(STATE_PAIRS/128)+j];
            FMA2(sin[j], sin[j], P2, S);
        }
        #pragma unroll
        for (int j=0;j<STATE_PAIRS/128;j++)
            g_sin_u[base + (size_t)(c+1)*STATE_PAIRS + tid*(STATE_PAIRS/128)+j] = sin[j];
    }
}

// ---------------- chunked scan pass C: fixup y += cumdA * (C . s_in) ----------------
__global__ __launch_bounds__(96) void scan_fixup_kernel()
{
    int blk = blockIdx.x;               // 256*(NCHUNK-1)
    int bp  = blk / (NCHUNK-1);
    int c   = blk - bp*(NCHUNK-1) + 1;
    int b   = bp >> 3;
    int hp  = bp & 7;
    int tid = threadIdx.x;
    int hl  = tid / HD;
    int p   = tid - hl*HD;
    int h   = hp*2 + hl;
    int tbase = c*CLEN;

    __shared__ __align__(16) ull Csh[2][2][DS/2];

    ull sin[DS/2];
    size_t sbase = ((size_t)(b*NH+h)*NCHUNK + c)*STATE_PAIRS;
    #pragma unroll
    for (int q=0;q<DS/2;q++) sin[q] = g_sin_u[sbase + q*HD + p];

    const size_t bh_dt = (size_t)(b*LL + tbase)*NH + h;
    {
        const float* r0 = g_xBC + (size_t)(b*LL + tbase)*CD;
        const float* r1 = r0 + CD;
        if (tid < 32){
            Csh[0][0][tid] = *(const ull*)(r0 + DI + DS + 2*tid);
            Csh[0][1][tid] = *(const ull*)(r1 + DI + DS + 2*tid);
        }
    }
    float cd0 = g_cda[bh_dt];
    float cd1 = g_cda[bh_dt + NH];
    __syncthreads();

    for (int i=0; i<CLEN/2; i++){
        int tr = 2*i;
        int t0 = tbase + tr;
        int set = i & 1;

        ull Cn0=0, Cn1=0; float cdn0=0, cdn1=0;
        if (tr+2 < CLEN){
            const float* r2 = g_xBC + (size_t)(b*LL + t0+2)*CD;
            const float* r3 = r2 + CD;
            if (tid < 32){
                Cn0 = *(const ull*)(r2 + DI + DS + 2*tid);
                Cn1 = *(const ull*)(r3 + DI + DS + 2*tid);
            }
            cdn0 = g_cda[bh_dt + (size_t)(tr+2)*NH];
            cdn1 = g_cda[bh_dt + (size_t)(tr+3)*NH];
        }

        {
            ull ya=0ull, yb=0ull, yc=0ull, yd=0ull;
            const ull* Cp = Csh[set][0];
            #pragma unroll
            for (int q=0;q<DS/2;q+=4){
                FMA2(ya, sin[q+0], Cp[q+0], ya);
                FMA2(yb, sin[q+1], Cp[q+1], yb);
                FMA2(yc, sin[q+2], Cp[q+2], yc);
                FMA2(yd, sin[q+3], Cp[q+3], yd);
            }
            float a0,a1,b0,b1,c0,c1,d0,d1;
            upk2(a0,a1,ya); upk2(b0,b1,yb); upk2(c0,c1,yc); upk2(d0,d1,yd);
            float dot = ((a0+a1)+(b0+b1)) + ((c0+c1)+(d0+d1));
            g_ys[(size_t)(b*LL+t0)*DI + h*HD + p] += cd0 * dot;
        }
        {
            ull ya=0ull, yb=0ull, yc=0ull, yd=0ull;
            const ull* Cp = Csh[set][1];
            #pragma unroll
            for (int q=0;q<DS/2;q+=4){
                FMA2(ya, sin[q+0], Cp[q+0], ya);
                FMA2(yb, sin[q+1], Cp[q+1], yb);
                FMA2(yc, sin[q+2], Cp[q+2], yc);
                FMA2(yd, sin[q+3], Cp[q+3], yd);
            }
            float a0,a1,b0,b1,c0,c1,d0,d1;
            upk2(a0,a1,ya); upk2(b0,b1,yb); upk2(c0,c1,yc); upk2(d0,d1,yd);
            float dot = ((a0+a1)+(b0+b1)) + ((c0+c1)+(d0+d1));
            g_ys[(size_t)(b*LL+t0+1)*DI + h*HD + p] += cd1 * dot;
        }

        if (tr+2 < CLEN){
            if (tid < 32){
                Csh[set^1][0][tid] = Cn0;
                Csh[set^1][1][tid] = Cn1;
            }
        }
        cd0=cdn0; cd1=cdn1;
        __syncthreads();
    }
}

// ---------------- y = (ys + D*x) * silu(z); RMS-norm -> g_yn (tf32, k-permuted) ----------------
__global__ __launch_bounds__(256) void gate_rms_kernel(const float* __restrict__ Dp,
                                                       const float* __restrict__ gnorm)
{
    __shared__ float red[256];
    int row = blockIdx.x, tid = threadIdx.x;
    float v[3]; float ss = 0.f;
    #pragma unroll
    for (int q=0;q<3;q++){
        int i = tid + q*256;
        float ys = g_ys[(size_t)row*DI + i];
        float xv = g_xBC[(size_t)row*CD + i];
        float z  = g_zx [(size_t)row*DIP + i];
        float val = (ys + Dp[i/HD]*xv) * (z / (1.f + __expf(-z)));
        v[q] = val; ss += val*val;
    }
    red[tid] = ss; __syncthreads();
    for (int s=128;s>0;s>>=1){ if(tid<s) red[tid]+=red[tid+s]; __syncthreads(); }
    float scale = rsqrtf(red[0]*(1.0f/DI) + 1e-5f);
    #pragma unroll
    for (int q=0;q<3;q++){
        int i = tid + q*256;
        g_yn[(size_t)row*DI + kperm(i)] = __uint_as_float(f2tf(v[q]*scale*gnorm[i]));
    }
}

// ---------------- pool stage 1: partial sums over 32-t slices ----------------
__global__ __launch_bounds__(128) void pool1_kernel()
{
    int blk = blockIdx.x;         // BB*16
    int b   = blk >> 4;
    int tc  = blk & 15;
    int tid = threadIdx.x;
    #pragma unroll
    for (int q=0;q<3;q++){
        int d = tid + q*128;
        const float* p = g_h + (size_t)(b*LL + tc*32)*DM + d;
        float s = 0.f;
        #pragma unroll 8
        for (int t=0;t<32;t++) s += p[(size_t)t*DM];
        g_pool[blk*DM + d] = s;
    }
}

// ---------------- pool stage 2: final mean + LN -> g_featT (transposed) ----------------
__global__ __launch_bounds__(128) void pool2_kernel(const float* __restrict__ w,
                                                    const float* __restrict__ b2)
{
    __shared__ float red[128];
    int b = blockIdx.x, tid = threadIdx.x;
    float v[3];
    #pragma unroll
    for (int q=0;q<3;q++){
        int d = tid + q*128;
        float s = 0.f;
        #pragma unroll
        for (int tc=0;tc<16;tc++) s += g_pool[(b*16+tc)*DM + d];
        v[q] = s * (1.0f/LL);
    }
    red[tid] = v[0]+v[1]+v[2]; __syncthreads();
    for (int s=64;s>0;s>>=1){ if(tid<s) red[tid]+=red[tid+s]; __syncthreads(); }
    float mu = red[0]*(1.0f/DM);
    __syncthreads();
    float d0=v[0]-mu, d1=v[1]-mu, d2=v[2]-mu;
    red[tid] = d0*d0+d1*d1+d2*d2; __syncthreads();
    for (int s=64;s>0;s>>=1){ if(tid<s) red[tid]+=red[tid+s]; __syncthreads(); }
    float inv = rsqrtf(red[0]*(1.0f/DM) + 1e-5f);
    g_featT[(tid    )*BB + b] = d0*inv*w[tid]     + b2[tid];
    g_featT[(tid+128)*BB + b] = d1*inv*w[tid+128] + b2[tid+128];
    g_featT[(tid+256)*BB + b] = d2*inv*w[tid+256] + b2[tid+256];
}

// ---------------- classification heads (transposed feat, float4 smem reads) ----------------
__global__ __launch_bounds__(256) void heads_kernel(
    const float* __restrict__ ow, const float* __restrict__ ob,
    const float* __restrict__ fw, const float* __restrict__ fb,
    const float* __restrict__ gw, const float* __restrict__ gb,
    const float* __restrict__ sw, const float* __restrict__ sb,
    float* __restrict__ out)
{
    __shared__ __align__(16) float sf[DM*BB];
    int tid = threadIdx.x;
    for (int i = tid; i < DM*BB; i += blockDim.x) sf[i] = g_featT[i];
    __syncthreads();

    int j = blockIdx.x * blockDim.x + tid;
    if (j >= NOUT) return;

    const float* W; const float* Bv; int jj, Nseg;
    if (j < N_ORDER)                      { W=ow; Bv=ob; jj=j;                     Nseg=N_ORDER; }
    else if (j < N_ORDER+N_FAMILY)        { W=fw; Bv=fb; jj=j-N_ORDER;             Nseg=N_FAMILY; }
    else if (j < N_ORDER+N_FAMILY+N_GENUS){ W=gw; Bv=gb; jj=j-N_ORDER-N_FAMILY;    Nseg=N_GENUS; }
    else                                  { W=sw; Bv=sb; jj=j-N_ORDER-N_FAMILY-N_GENUS; Nseg=N_SPECIES; }

    float acc[BB];
    #pragma unroll
    for (int b=0;b<BB;b++) acc[b]=0.f;
    for (int k=0;k<DM;k++){
        float wv = W[(size_t)k*Nseg + jj];
        const float4* row = (const float4*)&sf[k*BB];
        #pragma unroll
        for (int bq=0;bq<8;bq++){
            float4 f = row[bq];
            acc[4*bq+0] = fmaf(f.x, wv, acc[4*bq+0]);
            acc[4*bq+1] = fmaf(f.y, wv, acc[4*bq+1]);
            acc[4*bq+2] = fmaf(f.z, wv, acc[4*bq+2]);
            acc[4*bq+3] = fmaf(f.w, wv, acc[4*bq+3]);
        }
    }
    float bias = Bv[jj];
    #pragma unroll
    for (int b=0;b<BB;b++) out[(size_t)b*NOUT + j] = acc[b] + bias;
}

// ---------------- orchestration ----------------
extern "C" void kernel_launch(void* const* d_in, const int* in_sizes, int n_in,
                              void* d_out, int out_size)
{
    const int*   tokens = (const int*)  d_in[0];
    const float* emb    = (const float*)d_in[1];
    const float* ln_w   = (const float*)d_in[2];
    const float* ln_b   = (const float*)d_in[3];
    const float* Win    = (const float*)d_in[4];
    const float* cw     = (const float*)d_in[5];
    const float* cb     = (const float*)d_in[6];
    const float* dtb    = (const float*)d_in[7];
    const float* alog   = (const float*)d_in[8];
    const float* Dd     = (const float*)d_in[9];
    const float* gnw    = (const float*)d_in[10];
    const float* Wout   = (const float*)d_in[11];
    const float* nfw    = (const float*)d_in[12];
    const float* nfb    = (const float*)d_in[13];
    const float* plw    = (const float*)d_in[14];
    const float* plb    = (const float*)d_in[15];
    const float* ow     = (const float*)d_in[16];
    const float* ob     = (const float*)d_in[17];
    const float* fw     = (const float*)d_in[18];
    const float* fb     = (const float*)d_in[19];
    const float* gw     = (const float*)d_in[20];
    const float* gb     = (const float*)d_in[21];
    const float* sw     = (const float*)d_in[22];
    const float* sb     = (const float*)d_in[23];
    float* out = (float*)d_out;

    const int smem_bytes = SMEM_FLOATS * 4;
    cudaFuncSetAttribute((const void*)gemm_tc<0,1>, cudaFuncAttributeMaxDynamicSharedMemorySize, smem_bytes);
    cudaFuncSetAttribute((const void*)gemm_tc<1,2>, cudaFuncAttributeMaxDynamicSharedMemorySize, smem_bytes);

    wcvt_t_kernel<<<dim3((DIP+31)/32, (DI+31)/32, 4), 256>>>(Win, Wout);
    embed_ln_kernel<<<NT, 128>>>(tokens, emb, ln_w, ln_b);

    for (int l = 0; l < 2; l++) {
        if (l > 0) ln_kernel<<<NT, 128>>>(ln_w + l*DM, ln_b + l*DM, 1);
        gemm_tc<0,1><<<dim3((DIP+GBN-1)/GBN, NT/GBM, 1), 256, smem_bytes>>>(l);
        conv_dtda_kernel<<<CONV_BLKS + DTDA_BLKS, 224>>>(cw + (size_t)l*CD*4, cb + l*CD,
                                                         dtb + l*NH, alog + l*NH);
        scan_local_kernel  <<<BB*8*NCHUNK, 96>>>();
        scan_combine_kernel<<<BB*NH, 128>>>();
        scan_fixup_kernel  <<<BB*8*(NCHUNK-1), 96>>>();
        gate_rms_kernel<<<NT, 256>>>(Dd + l*NH, gnw + l*DI);
        gemm_tc<1,2><<<dim3((DM+GBN-1)/GBN, NT/GBM, 2), 256, smem_bytes>>>(l);
    }

    ln_kernel<<<NT, 128>>>(nfw, nfb, 0);
    pool1_kernel<<<BB*16, 128>>>();
    pool2_kernel<<<BB, 128>>>(plw, plb);
    heads_kernel<<<(NOUT + 255)/256, 256>>>(ow, ob, fw, fb, gw, gb, sw, sb, out);
}

// round 8
// speedup vs baseline: 3.7216x; 1.0291x over previous
#include <cuda_runtime.h>
#include <math.h>
#include <stddef.h>
#include <stdint.h>

typedef unsigned long long ull;

// ---------------- problem constants ----------------
#define BB   32
#define LL   512
#define DM   384
#define DI   768
#define DS   64
#define NH   16
#define HD   48
#define DIP  1680
#define CD   896
#define NT   (BB*LL)
#define NOUT 38667
#define N_ORDER 60
#define N_FAMILY 427
#define N_GENUS 14216
#define N_SPECIES 23964

#define WIN1  (DM*DIP)
#define WOUT1 (DI*DM)

#define NCHUNK 8
#define CLEN   64
#define SFL    3072          // DS*HD floats per (b,h,chunk) state

// k-permutation within each 8-group: pos = k<4 ? 2k : 2(k-4)+1
__device__ __forceinline__ int kperm(int k){
    int j = k & 7;
    return (k & ~7) | ((j<4) ? (j<<1) : (((j-4)<<1)|1));
}

// ---------------- scratch ----------------
__device__ float g_resid[(size_t)NT*DM];
__device__ float g_h    [(size_t)NT*DM];
__device__ float g_zx   [(size_t)NT*DIP];
__device__ float g_xBC  [(size_t)NT*CD];
__device__ float g_dt   [(size_t)NT*NH];
__device__ float g_dA   [(size_t)NT*NH];    // stores log(dA) = -exp(A_log)*dt
__device__ float g_lc   [(size_t)NT*NH];    // chunk-local cumsum of log dA
__device__ float g_ys   [(size_t)NT*DI];
__device__ float g_yn   [(size_t)NT*DI];
__device__ float g_wtB  [2*WIN1 + 2*WOUT1];
__device__ float g_state[(size_t)BB*NH*NCHUNK*SFL];
__device__ float g_sin  [(size_t)BB*NH*NCHUNK*SFL];
__device__ float g_pool [BB*16*DM];
__device__ float g_featT[DM*BB];

__device__ __forceinline__ uint32_t f2tf(float x){
    uint32_t y;
    asm volatile("cvt.rna.tf32.f32 %0, %1;" : "=r"(y) : "f"(x));
    return y;
}
__device__ __forceinline__ void upk2u(uint32_t& lo, uint32_t& hi, ull v){
    asm("mov.b64 {%0, %1}, %2;" : "=r"(lo), "=r"(hi) : "l"(v));
}

// ---------------- weight transpose + permute + tf32 convert ----------------
__global__ __launch_bounds__(256) void wcvt_t_kernel(const float* __restrict__ Win,
                                                     const float* __restrict__ Wout)
{
    int r = blockIdx.z;
    const float* src; float* dst; int K_, N_;
    if (r < 2){ src = Win  + (size_t)r*WIN1;      dst = g_wtB + (size_t)r*WIN1;              K_ = DM; N_ = DIP; }
    else      { src = Wout + (size_t)(r-2)*WOUT1; dst = g_wtB + 2*WIN1 + (size_t)(r-2)*WOUT1; K_ = DI; N_ = DM; }
    int k0 = blockIdx.y*32, n0 = blockIdx.x*32;
    if (k0 >= K_ || n0 >= N_) return;
    __shared__ float sm[32][33];
    int tx = threadIdx.x & 31, ty = threadIdx.x >> 5;
    #pragma unroll
    for (int q=0;q<4;q++){
        int k = k0 + ty + q*8;
        if (k < K_ && n0+tx < N_) sm[ty+q*8][tx] = src[(size_t)k*N_ + n0+tx];
    }
    __syncthreads();
    #pragma unroll
    for (int q=0;q<4;q++){
        int n = n0 + ty + q*8;
        int k = k0 + tx;
        if (n < N_ && k < K_)
            dst[(size_t)n*K_ + kperm(k)] = __uint_as_float(f2tf(sm[tx][ty+q*8]));
    }
}

// ---------------- fused embedding + layer-0 layernorm (k-permuted) ----------------
__global__ __launch_bounds__(128) void embed_ln_kernel(const int* __restrict__ tokens,
                                                       const float* __restrict__ emb,
                                                       const float* __restrict__ w,
                                                       const float* __restrict__ b)
{
    __shared__ float red[128];
    int row = blockIdx.x, tid = threadIdx.x;
    const float* er = emb + (size_t)tokens[row]*DM;
    float v0 = er[tid], v1 = er[tid+128], v2 = er[tid+256];
    float* rr = g_resid + (size_t)row*DM;
    rr[tid] = v0; rr[tid+128] = v1; rr[tid+256] = v2;

    red[tid] = v0+v1+v2; __syncthreads();
    for (int s=64;s>0;s>>=1){ if(tid<s) red[tid]+=red[tid+s]; __syncthreads(); }
    float mu = red[0] * (1.0f/DM);
    __syncthreads();
    float d0=v0-mu, d1=v1-mu, d2=v2-mu;
    red[tid] = d0*d0+d1*d1+d2*d2; __syncthreads();
    for (int s=64;s>0;s>>=1){ if(tid<s) red[tid]+=red[tid+s]; __syncthreads(); }
    float inv = rsqrtf(red[0]*(1.0f/DM) + 1e-5f);
    float* o = g_h + (size_t)row*DM;
    o[kperm(tid)]     = __uint_as_float(f2tf(d0*inv*w[tid]     + b[tid]));
    o[kperm(tid+128)] = __uint_as_float(f2tf(d1*inv*w[tid+128] + b[tid+128]));
    o[kperm(tid+256)] = __uint_as_float(f2tf(d2*inv*w[tid+256] + b[tid+256]));
}

// ---------------- layernorm: g_resid -> g_h ----------------
__global__ __launch_bounds__(128) void ln_kernel(const float* __restrict__ w, const float* __restrict__ b, int tf)
{
    __shared__ float red[128];
    int row = blockIdx.x, tid = threadIdx.x;
    const float* xr = g_resid + (size_t)row*DM;
    float v0 = xr[tid], v1 = xr[tid+128], v2 = xr[tid+256];
    red[tid] = v0+v1+v2; __syncthreads();
    for (int s=64;s>0;s>>=1){ if(tid<s) red[tid]+=red[tid+s]; __syncthreads(); }
    float mu = red[0] * (1.0f/DM);
    __syncthreads();
    float d0=v0-mu, d1=v1-mu, d2=v2-mu;
    red[tid] = d0*d0+d1*d1+d2*d2; __syncthreads();
    for (int s=64;s>0;s>>=1){ if(tid<s) red[tid]+=red[tid+s]; __syncthreads(); }
    float inv = rsqrtf(red[0]*(1.0f/DM) + 1e-5f);
    float o0 = d0*inv*w[tid]     + b[tid];
    float o1 = d1*inv*w[tid+128] + b[tid+128];
    float o2 = d2*inv*w[tid+256] + b[tid+256];
    float* o = g_h + (size_t)row*DM;
    if (tf){
        o[kperm(tid)]     = __uint_as_float(f2tf(o0));
        o[kperm(tid+128)] = __uint_as_float(f2tf(o1));
        o[kperm(tid+256)] = __uint_as_float(f2tf(o2));
    } else {
        o[tid] = o0; o[tid+128] = o1; o[tid+256] = o2;
    }
}

// ---------------- tf32 mma helper ----------------
__device__ __forceinline__ void mma_tf32(float* c, const uint32_t* a, const uint32_t* b){
    asm volatile(
      "mma.sync.aligned.m16n8k8.row.col.f32.tf32.tf32.f32 "
      "{%0,%1,%2,%3}, {%4,%5,%6,%7}, {%8,%9}, {%0,%1,%2,%3};\n"
      : "+f"(c[0]), "+f"(c[1]), "+f"(c[2]), "+f"(c[3])
      : "r"(a[0]), "r"(a[1]), "r"(a[2]), "r"(a[3]), "r"(b[0]), "r"(b[1]));
}

// ---------------- tf32 tensor-core GEMM (unchanged) ----------------
#define GBM 128
#define GBN 128
#define GBK 16
#define NSTAGE 4
#define TSTR 24
#define AS_FLOATS (GBM*TSTR)
#define BS_FLOATS (GBN*TSTR)
#define SMEM_FLOATS (NSTAGE*(AS_FLOATS+BS_FLOATS))

template<int MODE, int SPLITK>
__global__ __launch_bounds__(256,2) void gemm_tc(int layer)
{
    const float* __restrict__ A = (MODE==0) ? g_h : g_yn;
    const float* __restrict__ W = (MODE==0) ? (g_wtB + (size_t)layer*WIN1)
                                            : (g_wtB + 2*WIN1 + (size_t)layer*WOUT1);
    float* C = (MODE==0) ? g_zx : g_resid;
    const int N = (MODE==0) ? DIP : DM;
    const int K = (MODE==0) ? DM  : DI;
    const int Ks = K / SPLITK;
    const int k_origin = blockIdx.z * Ks;

    extern __shared__ float sh[];
    float* shB = sh + NSTAGE*AS_FLOATS;

    int tid  = threadIdx.x;
    int warp = tid >> 5;
    int lane = tid & 31;
    int gid  = lane >> 2;
    int tig  = lane & 3;

    int m0 = blockIdx.y * GBM;
    int n0 = blockIdx.x * GBN;
    int wm = (warp & 1) * 64;
    int wn = (warp >> 1) * 32;

    float acc[4][4][4];
    #pragma unroll
    for (int i=0;i<4;i++)
        #pragma unroll
        for (int j=0;j<4;j++)
            #pragma unroll
            for (int q=0;q<4;q++) acc[i][j][q]=0.f;

    const int niter = Ks / GBK;

    int row0 = tid >> 2,        kc0 = (tid & 3) << 2;
    int row1 = (tid+256) >> 2,  kc1 = (tid & 3) << 2;
    int b_ok0 = (n0 + row0 < N) ? 16 : 0;
    int b_ok1 = (n0 + row1 < N) ? 16 : 0;
    const float* asrc0 = A + (size_t)(m0 + row0)*K + k_origin + kc0;
    const float* asrc1 = A + (size_t)(m0 + row1)*K + k_origin + kc1;
    const float* bsrc0 = W + (size_t)((n0 + row0 < N) ? (n0 + row0) : 0)*K + k_origin + kc0;
    const float* bsrc1 = W + (size_t)((n0 + row1 < N) ? (n0 + row1) : 0)*K + k_origin + kc1;

    uint32_t adst0 = (uint32_t)__cvta_generic_to_shared(&sh [row0*TSTR + kc0]);
    uint32_t adst1 = (uint32_t)__cvta_generic_to_shared(&sh [row1*TSTR + kc1]);
    uint32_t bdst0 = (uint32_t)__cvta_generic_to_shared(&shB[row0*TSTR + kc0]);
    uint32_t bdst1 = (uint32_t)__cvta_generic_to_shared(&shB[row1*TSTR + kc1]);

    auto issue_copy = [&](int st, int it){
        int k0 = it * GBK;
        uint32_t ao = st*AS_FLOATS*4, bo = st*BS_FLOATS*4;
        asm volatile("cp.async.cg.shared.global [%0], [%1], 16;\n"
                     :: "r"(adst0 + ao), "l"(asrc0 + k0));
        asm volatile("cp.async.cg.shared.global [%0], [%1], 16;\n"
                     :: "r"(adst1 + ao), "l"(asrc1 + k0));
        asm volatile("cp.async.cg.shared.global [%0], [%1], 16, %2;\n"
                     :: "r"(bdst0 + bo), "l"(bsrc0 + k0), "r"(b_ok0));
        asm volatile("cp.async.cg.shared.global [%0], [%1], 16, %2;\n"
                     :: "r"(bdst1 + bo), "l"(bsrc1 + k0), "r"(b_ok1));
    };

    #pragma unroll
    for (int st=0; st<NSTAGE-1; st++){
        if (st < niter) issue_copy(st, st);
        asm volatile("cp.async.commit_group;\n");
    }

    for (int it=0; it<niter; ++it){
        asm volatile("cp.async.wait_group %0;\n" :: "n"(NSTAGE-2));
        __syncthreads();

        int cb = it & (NSTAGE-1);
        const float* Asb = &sh [cb*AS_FLOATS];
        const float* Bsb = &shB[cb*BS_FLOATS];

        #pragma unroll
        for (int ks=0; ks<GBK; ks+=8){
            uint32_t af[4][4], bf[4][2];
            #pragma unroll
            for (int mi=0; mi<4; mi++){
                int mr = wm + 16*mi;
                ull lo8 = *(const ull*)&Asb[(mr+gid  )*TSTR + ks + 2*tig];
                ull hi8 = *(const ull*)&Asb[(mr+gid+8)*TSTR + ks + 2*tig];
                upk2u(af[mi][0], af[mi][2], lo8);
                upk2u(af[mi][1], af[mi][3], hi8);
            }
            #pragma unroll
            for (int ni=0; ni<4; ni++){
                int nb = wn + 8*ni;
                ull bb = *(const ull*)&Bsb[(nb+gid)*TSTR + ks + 2*tig];
                upk2u(bf[ni][0], bf[ni][1], bb);
            }
            #pragma unroll
            for (int mi=0; mi<4; mi++)
                #pragma unroll
                for (int ni=0; ni<4; ni++)
                    mma_tf32(acc[mi][ni], af[mi], bf[ni]);
        }

        int nx = it + NSTAGE - 1;
        if (nx < niter) issue_copy(nx & (NSTAGE-1), nx);
        asm volatile("cp.async.commit_group;\n");
    }

    #pragma unroll
    for (int mi=0; mi<4; mi++){
        int r0 = m0 + wm + 16*mi + gid;
        #pragma unroll
        for (int ni=0; ni<4; ni++){
            int c0 = n0 + wn + 8*ni + 2*tig;
            float* a = acc[mi][ni];
            #pragma unroll
            for (int half=0; half<2; half++){
                int cc = c0 + half;
                if (cc < N){
                    size_t i0 = (size_t)r0*N + cc;
                    size_t i2 = (size_t)(r0+8)*N + cc;
                    if (MODE){ atomicAdd(&C[i0], a[half]); atomicAdd(&C[i2], a[2+half]); }
                    else     { C[i0] = a[half]; C[i2] = a[2+half]; }
                }
            }
        }
    }
}

// ---------------- fused conv (16-step chunks) + dt/logdA ----------------
#define CONV_BLKS (BB*32)
#define DTDA_TOT  (NT*(NH/4))
#define DTDA_BLKS ((DTDA_TOT + 223)/224)
__global__ __launch_bounds__(224) void conv_dtda_kernel(const float* __restrict__ cw, const float* __restrict__ cb,
                                                        const float* __restrict__ dtb, const float* __restrict__ alog)
{
    int blk = blockIdx.x;
    int tid = threadIdx.x;
    if (blk < CONV_BLKS){
        int b  = blk >> 5;
        int tc = blk & 31;
        int t0 = tc * 16;
        int c  = tid << 2;

        float4 tw[4];
        #pragma unroll
        for (int k=0;k<4;k++){
            tw[k].x = cw[(c+0)*4+k];
            tw[k].y = cw[(c+1)*4+k];
            tw[k].z = cw[(c+2)*4+k];
            tw[k].w = cw[(c+3)*4+k];
        }
        float4 bias = *(const float4*)&cb[c];

        const float* base = g_zx + (size_t)(b*LL + t0)*DIP + DI + c;
        float* obase = g_xBC + (size_t)(b*LL + t0)*CD + c;

        float4 p1, p2, p3;
        if (t0 > 0){
            p1 = *(const float4*)(base - 3*DIP);
            p2 = *(const float4*)(base - 2*DIP);
            p3 = *(const float4*)(base - 1*DIP);
        } else {
            p1 = p2 = p3 = make_float4(0.f,0.f,0.f,0.f);
        }

        #pragma unroll
        for (int i=0;i<16;i++){
            float4 v = *(const float4*)(base + (size_t)i*DIP);
            float4 a;
            a.x = bias.x + p1.x*tw[0].x + p2.x*tw[1].x + p3.x*tw[2].x + v.x*tw[3].x;
            a.y = bias.y + p1.y*tw[0].y + p2.y*tw[1].y + p3.y*tw[2].y + v.y*tw[3].y;
            a.z = bias.z + p1.z*tw[0].z + p2.z*tw[1].z + p3.z*tw[2].z + v.z*tw[3].z;
            a.w = bias.w + p1.w*tw[0].w + p2.w*tw[1].w + p3.w*tw[2].w + v.w*tw[3].w;
            float4 r;
            r.x = a.x / (1.f + __expf(-a.x));
            r.y = a.y / (1.f + __expf(-a.y));
            r.z = a.z / (1.f + __expf(-a.z));
            r.w = a.w / (1.f + __expf(-a.w));
            *(float4*)(obase + (size_t)i*CD) = r;
            p1 = p2; p2 = p3; p3 = v;
        }
    } else {
        int j = (blk - CONV_BLKS)*224 + tid;
        if (j >= DTDA_TOT) return;
        int hq = (j & 3) << 2;
        int bt = j >> 2;
        #pragma unroll
        for (int q=0;q<4;q++){
            int hh = hq + q;
            float raw = g_zx[(size_t)bt*DIP + (DIP-NH) + hh] + dtb[hh];
            float sp = (raw > 20.f) ? raw : log1pf(expf(raw));
            g_dt[bt*NH + hh] = sp;
            g_dA[bt*NH + hh] = -expf(alog[hh]) * sp;    // log(dA)
        }
    }
}

// ---------------- SSD scan pass A: per (b,h,chunk) tensor-core local scan ----------------
#define SA_STR 68
#define SSD_A_SMEM ((3*64*SA_STR + 2*48*SA_STR + 192)*4)

__global__ __launch_bounds__(128) void ssd_local_kernel()
{
    int blk = blockIdx.x;           // BB*NH*NCHUNK
    int c  = blk & (NCHUNK-1);
    int bh = blk >> 3;
    int b  = bh >> 4;
    int h  = bh & 15;
    int tid = threadIdx.x;
    int warp = tid >> 5, lane = tid & 31, gid = lane >> 2, tig = lane & 3;
    int bt0 = b*LL + c*CLEN;

    extern __shared__ float sa[];
    float* sC   = sa;                       // [64][SA_STR]  C rows by t
    float* sBW  = sC  + 64*SA_STR;          // [64][SA_STR]  B rows by s; later W[t][s]
    float* sBT  = sBW + 64*SA_STR;          // [64][SA_STR]  B^T: [n][s]
    float* sXT  = sBT + 64*SA_STR;          // [48][SA_STR]  X^T: [p][s]
    float* sXwT = sXT + 48*SA_STR;          // [48][SA_STR]  w2-scaled X^T
    float* lc_sh = sXwT + 48*SA_STR;        // [64]
    float* dt_sh = lc_sh + 64;              // [64]
    float* w2_sh = dt_sh + 64;              // [64]

    // loads: B, C (64x64 each), X (64x48)
    for (int i = tid; i < 64*16; i += 128){
        int t = i >> 4, q = (i & 15) << 2;
        const float* row = g_xBC + (size_t)(bt0+t)*CD + DI;
        float4 vb = *(const float4*)(row + q);
        float4 vc = *(const float4*)(row + DS + q);
        *(float4*)&sBW[t*SA_STR + q] = vb;
        *(float4*)&sC [t*SA_STR + q] = vc;
        sBT[(q+0)*SA_STR + t] = vb.x;
        sBT[(q+1)*SA_STR + t] = vb.y;
        sBT[(q+2)*SA_STR + t] = vb.z;
        sBT[(q+3)*SA_STR + t] = vb.w;
    }
    for (int i = tid; i < 64*12; i += 128){
        int t = i / 12, q = (i % 12) << 2;
        float4 vx = *(const float4*)(g_xBC + (size_t)(bt0+t)*CD + h*HD + q);
        sXT[(q+0)*SA_STR + t] = vx.x;
        sXT[(q+1)*SA_STR + t] = vx.y;
        sXT[(q+2)*SA_STR + t] = vx.z;
        sXT[(q+3)*SA_STR + t] = vx.w;
    }
    if (tid < 64) dt_sh[tid] = g_dt[(size_t)(bt0+tid)*NH + h];
    if (warp == 0){
        float v0 = g_dA[(size_t)(bt0+lane)*NH + h];
        float v1 = g_dA[(size_t)(bt0+32+lane)*NH + h];
        #pragma unroll
        for (int d=1; d<32; d<<=1){
            float u0 = __shfl_up_sync(0xffffffffu, v0, d);
            float u1 = __shfl_up_sync(0xffffffffu, v1, d);
            if (lane >= d){ v0 += u0; v1 += u1; }
        }
        float tot = __shfl_sync(0xffffffffu, v0, 31);
        v1 += tot;
        lc_sh[lane]    = v0;
        lc_sh[32+lane] = v1;
        g_lc[(size_t)(bt0+lane)*NH + h]    = v0;
        g_lc[(size_t)(bt0+32+lane)*NH + h] = v1;
    }
    __syncthreads();

    // G = C @ B^T : warp handles t-rows [16w, 16w+16)
    int wt0 = warp*16;
    float gacc[8][4];
    #pragma unroll
    for (int ni=0;ni<8;ni++){ gacc[ni][0]=0.f; gacc[ni][1]=0.f; gacc[ni][2]=0.f; gacc[ni][3]=0.f; }
    #pragma unroll
    for (int kk=0; kk<64; kk+=8){
        uint32_t af[4];
        af[0] = __float_as_uint(sC[(wt0+gid  )*SA_STR + kk+tig  ]);
        af[1] = __float_as_uint(sC[(wt0+gid+8)*SA_STR + kk+tig  ]);
        af[2] = __float_as_uint(sC[(wt0+gid  )*SA_STR + kk+tig+4]);
        af[3] = __float_as_uint(sC[(wt0+gid+8)*SA_STR + kk+tig+4]);
        #pragma unroll
        for (int ni=0; ni<8; ni++){
            uint32_t bf[2];
            bf[0] = __float_as_uint(sBW[(8*ni+gid)*SA_STR + kk+tig  ]);
            bf[1] = __float_as_uint(sBW[(8*ni+gid)*SA_STR + kk+tig+4]);
            mma_tf32(gacc[ni], af, bf);
        }
    }
    if (tid < 64) w2_sh[tid] = __expf(lc_sh[63] - lc_sh[tid]) * dt_sh[tid];
    __syncthreads();   // G consumed; sBW region free; w2 ready

    // W[t][s] = mask * exp(lc_t - lc_s) * dt_s * G  (stored into sBW region)
    {
        int t0r = wt0 + gid, t1r = t0r + 8;
        float lct0 = lc_sh[t0r], lct1 = lc_sh[t1r];
        #pragma unroll
        for (int ni=0; ni<8; ni++){
            int s0 = 8*ni + 2*tig, s1 = s0 + 1;
            float lcs0 = lc_sh[s0], lcs1 = lc_sh[s1];
            float d0 = dt_sh[s0],   d1 = dt_sh[s1];
            sBW[t0r*SA_STR + s0] = (s0<=t0r) ? gacc[ni][0]*__expf(lct0-lcs0)*d0 : 0.f;
            sBW[t0r*SA_STR + s1] = (s1<=t0r) ? gacc[ni][1]*__expf(lct0-lcs1)*d1 : 0.f;
            sBW[t1r*SA_STR + s0] = (s0<=t1r) ? gacc[ni][2]*__expf(lct1-lcs0)*d0 : 0.f;
            sBW[t1r*SA_STR + s1] = (s1<=t1r) ? gacc[ni][3]*__expf(lct1-lcs1)*d1 : 0.f;
        }
    }
    for (int i = tid; i < 48*64; i += 128){
        int p = i >> 6, s = i & 63;
        sXwT[p*SA_STR + s] = sXT[p*SA_STR + s] * w2_sh[s];
    }
    __syncthreads();

    // Y = W @ X  (64x48x64)  and  S = B^T @ Xw  (64x48x64)
    float yacc[6][4], sacc[6][4];
    #pragma unroll
    for (int ni=0;ni<6;ni++){
        yacc[ni][0]=yacc[ni][1]=yacc[ni][2]=yacc[ni][3]=0.f;
        sacc[ni][0]=sacc[ni][1]=sacc[ni][2]=sacc[ni][3]=0.f;
    }
    #pragma unroll
    for (int kk=0; kk<64; kk+=8){
        uint32_t afW[4], afB[4];
        afW[0] = __float_as_uint(sBW[(wt0+gid  )*SA_STR + kk+tig  ]);
        afW[1] = __float_as_uint(sBW[(wt0+gid+8)*SA_STR + kk+tig  ]);
        afW[2] = __float_as_uint(sBW[(wt0+gid  )*SA_STR + kk+tig+4]);
        afW[3] = __float_as_uint(sBW[(wt0+gid+8)*SA_STR + kk+tig+4]);
        afB[0] = __float_as_uint(sBT[(wt0+gid  )*SA_STR + kk+tig  ]);
        afB[1] = __float_as_uint(sBT[(wt0+gid+8)*SA_STR + kk+tig  ]);
        afB[2] = __float_as_uint(sBT[(wt0+gid  )*SA_STR + kk+tig+4]);
        afB[3] = __float_as_uint(sBT[(wt0+gid+8)*SA_STR + kk+tig+4]);
        #pragma unroll
        for (int ni=0; ni<6; ni++){
            uint32_t bfX[2], bfW2[2];
            bfX[0]  = __float_as_uint(sXT [(8*ni+gid)*SA_STR + kk+tig  ]);
            bfX[1]  = __float_as_uint(sXT [(8*ni+gid)*SA_STR + kk+tig+4]);
            mma_tf32(yacc[ni], afW, bfX);
            bfW2[0] = __float_as_uint(sXwT[(8*ni+gid)*SA_STR + kk+tig  ]);
            bfW2[1] = __float_as_uint(sXwT[(8*ni+gid)*SA_STR + kk+tig+4]);
            mma_tf32(sacc[ni], afB, bfW2);
        }
    }

    // epilogues
    size_t sbase = ((size_t)bh*NCHUNK + c)*SFL;
    #pragma unroll
    for (int ni=0; ni<6; ni++){
        int p = 8*ni + 2*tig;
        int tr = wt0 + gid;
        float* y0 = &g_ys[(size_t)(bt0+tr)*DI + h*HD + p];
        *(float2*)y0            = make_float2(yacc[ni][0], yacc[ni][1]);
        *(float2*)(y0 + 8*DI)   = make_float2(yacc[ni][2], yacc[ni][3]);
        float* s0 = &g_state[sbase + tr*HD + p];
        *(float2*)s0            = make_float2(sacc[ni][0], sacc[ni][1]);
        *(float2*)(s0 + 8*HD)   = make_float2(sacc[ni][2], sacc[ni][3]);
    }
}

// ---------------- SSD pass B: sequential chunk-state combine ----------------
__global__ __launch_bounds__(128) void ssd_combine_kernel()
{
    int bh = blockIdx.x;             // BB*NH
    int b  = bh >> 4;
    int h  = bh & 15;
    int tid = threadIdx.x;
    size_t base = (size_t)bh*NCHUNK*SFL;

    float sin[SFL/128];
    #pragma unroll
    for (int j=0;j<SFL/128;j++) sin[j]=0.f;

    for (int c=0;c<NCHUNK-1;c++){
        float ef = __expf(g_lc[(size_t)(b*LL + c*CLEN + CLEN-1)*NH + h]);
        #pragma unroll
        for (int j=0;j<SFL/128;j++)
            sin[j] = sin[j]*ef + g_state[base + (size_t)c*SFL + j*128 + tid];
        #pragma unroll
        for (int j=0;j<SFL/128;j++)
            g_sin[base + (size_t)(c+1)*SFL + j*128 + tid] = sin[j];
    }
}

// ---------------- SSD pass C: y += exp(lc_t) * (C @ S_in) ----------------
__global__ __launch_bounds__(128) void ssd_fix_kernel()
{
    int blk = blockIdx.x;            // BB*NH*(NCHUNK-1)
    int bh  = blk / (NCHUNK-1);
    int c   = blk - bh*(NCHUNK-1) + 1;
    int b   = bh >> 4;
    int h   = bh & 15;
    int tid = threadIdx.x;
    int warp = tid >> 5, lane = tid & 31, gid = lane >> 2, tig = lane & 3;
    int bt0 = b*LL + c*CLEN;

    __shared__ float sC2[64*SA_STR];
    __shared__ float sST[48*SA_STR];
    __shared__ float lc2[64];

    for (int i = tid; i < 64*16; i += 128){
        int t = i >> 4, q = (i & 15) << 2;
        float4 vc = *(const float4*)(g_xBC + (size_t)(bt0+t)*CD + DI + DS + q);
        *(float4*)&sC2[t*SA_STR + q] = vc;
    }
    size_t sbase = ((size_t)bh*NCHUNK + c)*SFL;
    for (int i = tid; i < SFL; i += 128){
        int n = i / HD, p = i - n*HD;
        sST[p*SA_STR + n] = g_sin[sbase + i];
    }
    if (tid < 64) lc2[tid] = g_lc[(size_t)(bt0+tid)*NH + h];
    __syncthreads();

    int wt0 = warp*16;
    float facc[6][4];
    #pragma unroll
    for (int ni=0;ni<6;ni++){ facc[ni][0]=facc[ni][1]=facc[ni][2]=facc[ni][3]=0.f; }
    #pragma unroll
    for (int kk=0; kk<64; kk+=8){
        uint32_t af[4];
        af[0] = __float_as_uint(sC2[(wt0+gid  )*SA_STR + kk+tig  ]);
        af[1] = __float_as_uint(sC2[(wt0+gid+8)*SA_STR + kk+tig  ]);
        af[2] = __float_as_uint(sC2[(wt0+gid  )*SA_STR + kk+tig+4]);
        af[3] = __float_as_uint(sC2[(wt0+gid+8)*SA_STR + kk+tig+4]);
        #pragma unroll
        for (int ni=0; ni<6; ni++){
            uint32_t bf[2];
            bf[0] = __float_as_uint(sST[(8*ni+gid)*SA_STR + kk+tig  ]);
            bf[1] = __float_as_uint(sST[(8*ni+gid)*SA_STR + kk+tig+4]);
            mma_tf32(facc[ni], af, bf);
        }
    }

    int tr = wt0 + gid;
    float e0 = __expf(lc2[tr]);
    float e1 = __expf(lc2[tr+8]);
    #pragma unroll
    for (int ni=0; ni<6; ni++){
        int p = 8*ni + 2*tig;
        float2* y0 = (float2*)&g_ys[(size_t)(bt0+tr)*DI + h*HD + p];
        float2 v0 = *y0; v0.x += e0*facc[ni][0]; v0.y += e0*facc[ni][1]; *y0 = v0;
        float2* y1 = (float2*)&g_ys[(size_t)(bt0+tr+8)*DI + h*HD + p];
        float2 v1 = *y1; v1.x += e1*facc[ni][2]; v1.y += e1*facc[ni][3]; *y1 = v1;
    }
}

// ---------------- y = (ys + D*x) * silu(z); RMS-norm -> g_yn (tf32, k-permuted) ----------------
__global__ __launch_bounds__(256) void gate_rms_kernel(const float* __restrict__ Dp,
                                                       const float* __restrict__ gnorm)
{
    __shared__ float red[256];
    int row = blockIdx.x, tid = threadIdx.x;
    float v[3]; float ss = 0.f;
    #pragma unroll
    for (int q=0;q<3;q++){
        int i = tid + q*256;
        float ys = g_ys[(size_t)row*DI + i];
        float xv = g_xBC[(size_t)row*CD + i];
        float z  = g_zx [(size_t)row*DIP + i];
        float val = (ys + Dp[i/HD]*xv) * (z / (1.f + __expf(-z)));
        v[q] = val; ss += val*val;
    }
    red[tid] = ss; __syncthreads();
    for (int s=128;s>0;s>>=1){ if(tid<s) red[tid]+=red[tid+s]; __syncthreads(); }
    float scale = rsqrtf(red[0]*(1.0f/DI) + 1e-5f);
    #pragma unroll
    for (int q=0;q<3;q++){
        int i = tid + q*256;
        g_yn[(size_t)row*DI + kperm(i)] = __uint_as_float(f2tf(v[q]*scale*gnorm[i]));
    }
}

// ---------------- pool stage 1 ----------------
__global__ __launch_bounds__(128) void pool1_kernel()
{
    int blk = blockIdx.x;
    int b   = blk >> 4;
    int tc  = blk & 15;
    int tid = threadIdx.x;
    #pragma unroll
    for (int q=0;q<3;q++){
        int d = tid + q*128;
        const float* p = g_h + (size_t)(b*LL + tc*32)*DM + d;
        float s = 0.f;
        #pragma unroll 8
        for (int t=0;t<32;t++) s += p[(size_t)t*DM];
        g_pool[blk*DM + d] = s;
    }
}

// ---------------- pool stage 2 ----------------
__global__ __launch_bounds__(128) void pool2_kernel(const float* __restrict__ w,
                                                    const float* __restrict__ b2)
{
    __shared__ float red[128];
    int b = blockIdx.x, tid = threadIdx.x;
    float v[3];
    #pragma unroll
    for (int q=0;q<3;q++){
        int d = tid + q*128;
        float s = 0.f;
        #pragma unroll
        for (int tc=0;tc<16;tc++) s += g_pool[(b*16+tc)*DM + d];
        v[q] = s * (1.0f/LL);
    }
    red[tid] = v[0]+v[1]+v[2]; __syncthreads();
    for (int s=64;s>0;s>>=1){ if(tid<s) red[tid]+=red[tid+s]; __syncthreads(); }
    float mu = red[0]*(1.0f/DM);
    __syncthreads();
    float d0=v[0]-mu, d1=v[1]-mu, d2=v[2]-mu;
    red[tid] = d0*d0+d1*d1+d2*d2; __syncthreads();
    for (int s=64;s>0;s>>=1){ if(tid<s) red[tid]+=red[tid+s]; __syncthreads(); }
    float inv = rsqrtf(red[0]*(1.0f/DM) + 1e-5f);
    g_featT[(tid    )*BB + b] = d0*inv*w[tid]     + b2[tid];
    g_featT[(tid+128)*BB + b] = d1*inv*w[tid+128] + b2[tid+128];
    g_featT[(tid+256)*BB + b] = d2*inv*w[tid+256] + b2[tid+256];
}

// ---------------- classification heads ----------------
__global__ __launch_bounds__(256) void heads_kernel(
    const float* __restrict__ ow, const float* __restrict__ ob,
    const float* __restrict__ fw, const float* __restrict__ fb,
    const float* __restrict__ gw, const float* __restrict__ gb,
    const float* __restrict__ sw, const float* __restrict__ sb,
    float* __restrict__ out)
{
    __shared__ __align__(16) float sf[DM*BB];
    int tid = threadIdx.x;
    for (int i = tid; i < DM*BB; i += blockDim.x) sf[i] = g_featT[i];
    __syncthreads();

    int j = blockIdx.x * blockDim.x + tid;
    if (j >= NOUT) return;

    const float* W; const float* Bv; int jj, Nseg;
    if (j < N_ORDER)                      { W=ow; Bv=ob; jj=j;                     Nseg=N_ORDER; }
    else if (j < N_ORDER+N_FAMILY)        { W=fw; Bv=fb; jj=j-N_ORDER;             Nseg=N_FAMILY; }
    else if (j < N_ORDER+N_FAMILY+N_GENUS){ W=gw; Bv=gb; jj=j-N_ORDER-N_FAMILY;    Nseg=N_GENUS; }
    else                                  { W=sw; Bv=sb; jj=j-N_ORDER-N_FAMILY-N_GENUS; Nseg=N_SPECIES; }

    float acc[BB];
    #pragma unroll
    for (int b=0;b<BB;b++) acc[b]=0.f;
    for (int k=0;k<DM;k++){
        float wv = W[(size_t)k*Nseg + jj];
        const float4* row = (const float4*)&sf[k*BB];
        #pragma unroll
        for (int bq=0;bq<8;bq++){
            float4 f = row[bq];
            acc[4*bq+0] = fmaf(f.x, wv, acc[4*bq+0]);
            acc[4*bq+1] = fmaf(f.y, wv, acc[4*bq+1]);
            acc[4*bq+2] = fmaf(f.z, wv, acc[4*bq+2]);
            acc[4*bq+3] = fmaf(f.w, wv, acc[4*bq+3]);
        }
    }
    float bias = Bv[jj];
    #pragma unroll
    for (int b=0;b<BB;b++) out[(size_t)b*NOUT + j] = acc[b] + bias;
}

// ---------------- orchestration ----------------
extern "C" void kernel_launch(void* const* d_in, const int* in_sizes, int n_in,
                              void* d_out, int out_size)
{
    const int*   tokens = (const int*)  d_in[0];
    const float* emb    = (const float*)d_in[1];
    const float* ln_w   = (const float*)d_in[2];
    const float* ln_b   = (const float*)d_in[3];
    const float* Win    = (const float*)d_in[4];
    const float* cw     = (const float*)d_in[5];
    const float* cb     = (const float*)d_in[6];
    const float* dtb    = (const float*)d_in[7];
    const float* alog   = (const float*)d_in[8];
    const float* Dd     = (const float*)d_in[9];
    const float* gnw    = (const float*)d_in[10];
    const float* Wout   = (const float*)d_in[11];
    const float* nfw    = (const float*)d_in[12];
    const float* nfb    = (const float*)d_in[13];
    const float* plw    = (const float*)d_in[14];
    const float* plb    = (const float*)d_in[15];
    const float* ow     = (const float*)d_in[16];
    const float* ob     = (const float*)d_in[17];
    const float* fw     = (const float*)d_in[18];
    const float* fb     = (const float*)d_in[19];
    const float* gw     = (const float*)d_in[20];
    const float* gb     = (const float*)d_in[21];
    const float* sw     = (const float*)d_in[22];
    const float* sb     = (const float*)d_in[23];
    float* out = (float*)d_out;

    const int smem_bytes = SMEM_FLOATS * 4;
    cudaFuncSetAttribute((const void*)gemm_tc<0,1>, cudaFuncAttributeMaxDynamicSharedMemorySize, smem_bytes);
    cudaFuncSetAttribute((const void*)gemm_tc<1,2>, cudaFuncAttributeMaxDynamicSharedMemorySize, smem_bytes);
    cudaFuncSetAttribute((const void*)ssd_local_kernel, cudaFuncAttributeMaxDynamicSharedMemorySize, SSD_A_SMEM);

    wcvt_t_kernel<<<dim3((DIP+31)/32, (DI+31)/32, 4), 256>>>(Win, Wout);
    embed_ln_kernel<<<NT, 128>>>(tokens, emb, ln_w, ln_b);

    for (int l = 0; l < 2; l++) {
        if (l > 0) ln_kernel<<<NT, 128>>>(ln_w + l*DM, ln_b + l*DM, 1);
        gemm_tc<0,1><<<dim3((DIP+GBN-1)/GBN, NT/GBM, 1), 256, smem_bytes>>>(l);
        conv_dtda_kernel<<<CONV_BLKS + DTDA_BLKS, 224>>>(cw + (size_t)l*CD*4, cb + l*CD,
                                                         dtb + l*NH, alog + l*NH);
        ssd_local_kernel  <<<BB*NH*NCHUNK, 128, SSD_A_SMEM>>>();
        ssd_combine_kernel<<<BB*NH, 128>>>();
        ssd_fix_kernel    <<<BB*NH*(NCHUNK-1), 128>>>();
        gate_rms_kernel<<<NT, 256>>>(Dd + l*NH, gnw + l*DI);
        gemm_tc<1,2><<<dim3((DM+GBN-1)/GBN, NT/GBM, 2), 256, smem_bytes>>>(l);
    }

    ln_kernel<<<NT, 128>>>(nfw, nfb, 0);
    pool1_kernel<<<BB*16, 128>>>();
    pool2_kernel<<<BB, 128>>>(plw, plb);
    heads_kernel<<<(NOUT + 255)/256, 256>>>(ow, ob, fw, fb, gw, gb, sw, sb, out);
}